// round 4
// baseline (speedup 1.0000x reference)
#include <cuda_runtime.h>
#include <cstdint>
#include <math.h>

#define DD     5
#define HGRID  24
#define WGRID  48
#define CLV    1024
#define NB     4
#define DIM    128
#define LMAX   12
#define DEPTH  6
#define LTOK   16
#define BALL   (DD*HGRID*WGRID)   // 5760
#define CAP    64
#define G      3
#define RROWS  (G*LTOK)           // 48
#define NT     192
#define NWARP  (NT/32)            // 6
#define PNT    256

// ---------------- device scratch ----------------
__device__ int   g_counts[BALL];
__device__ int   g_list[BALL*CAP];
__device__ float g_bgp[NB*DIM];
__device__ float g_feat[BALL*NB*DIM];

// ---------------- packed f32x2 helpers ----------------
__device__ __forceinline__ unsigned long long pk2(float lo, float hi){
    unsigned long long r;
    asm("mov.b64 %0,{%1,%2};" : "=l"(r) : "f"(lo), "f"(hi));
    return r;
}
__device__ __forceinline__ void upk2(unsigned long long v, float &lo, float &hi){
    asm("mov.b64 {%0,%1},%2;" : "=f"(lo), "=f"(hi) : "l"(v));
}
__device__ __forceinline__ unsigned long long fma2(unsigned long long a,
                                                   unsigned long long b,
                                                   unsigned long long c){
    unsigned long long d;
    asm("fma.rn.f32x2 %0,%1,%2,%3;" : "=l"(d) : "l"(a), "l"(b), "l"(c));
    return d;
}

__device__ __forceinline__ float gelu_f(float x){
    float x3 = x*x*x;
    return 0.5f*x*(1.0f + tanhf(0.7978845608028654f*(x + 0.044715f*x3)));
}

// ---------------- tiny setup kernels ----------------
__global__ void k_zero(){
    int i = blockIdx.x*blockDim.x + threadIdx.x;
    if (i < BALL) g_counts[i] = 0;
}

__global__ void k_scatter(const int* __restrict__ li, int n){
    int i = blockIdx.x*blockDim.x + threadIdx.x;
    if (i >= n) return;
    int a = li[3*i], b = li[3*i+1], c = li[3*i+2];
    int flat = a*(HGRID*WGRID) + b*WGRID + c;
    int slot = atomicAdd(&g_counts[flat], 1);
    if (slot < CAP) g_list[flat*CAP + slot] = i;
}

__global__ void k_bg(const float* __restrict__ ob,
                     const float* __restrict__ dw,
                     const float* __restrict__ db){
    int c = blockIdx.x*blockDim.x + threadIdx.x;
    if (c >= NB*DIM) return;
    float s = 0.0f;
    for (int m = 0; m < NB; m++){
        const float* bg = ob + m*DIM;
        float t = 0.0f;
        for (int k = 0; k < DIM; k++)
            t += bg[k] * dw[k*(NB*DIM) + c];
        s += t;
    }
    s = s * (1.0f/NB) + db[c];
    g_bgp[c] = ob[c] + s;
}

// ---------------- GEMM tile: C(48 x 128) = A(48 x K) @ B(K x 128) ----------------
// A, C in smem (ld 128). B global (row-major, ldb), staged in 32-row chunks.
// MODE: 0=zero, 1=bias, 2=load C (accumulate), 3=load C + bias.
// Overlay-safe: store happens after the chunk-final __syncthreads(), so C may alias A.
template<int K, int MODE, bool DOGELU>
__device__ __forceinline__ void gemm_tile(const float* __restrict__ A,
                                          const float* __restrict__ Bg, int ldb,
                                          const float* __restrict__ bias,
                                          float* __restrict__ C,
                                          float* __restrict__ Bs){
    const int tid = threadIdx.x;
    const int rg = tid >> 4, cg = tid & 15;
    const int r0 = rg*4, c0 = cg*8;

    unsigned long long acc[4][4];
    if (MODE == 0){
        #pragma unroll
        for (int i = 0; i < 4; i++)
            #pragma unroll
            for (int j = 0; j < 4; j++) acc[i][j] = 0ull;
    } else if (MODE == 1){
        float4 b0 = *(const float4*)(bias + c0);
        float4 b1 = *(const float4*)(bias + c0 + 4);
        unsigned long long p0 = pk2(b0.x,b0.y), p1 = pk2(b0.z,b0.w);
        unsigned long long p2 = pk2(b1.x,b1.y), p3 = pk2(b1.z,b1.w);
        #pragma unroll
        for (int i = 0; i < 4; i++){ acc[i][0]=p0; acc[i][1]=p1; acc[i][2]=p2; acc[i][3]=p3; }
    } else {
        float4 bb0 = make_float4(0.f,0.f,0.f,0.f), bb1 = bb0;
        if (MODE == 3){
            bb0 = *(const float4*)(bias + c0);
            bb1 = *(const float4*)(bias + c0 + 4);
        }
        #pragma unroll
        for (int i = 0; i < 4; i++){
            float4 cv0 = *(const float4*)(C + (r0+i)*128 + c0);
            float4 cv1 = *(const float4*)(C + (r0+i)*128 + c0 + 4);
            acc[i][0] = pk2(cv0.x+bb0.x, cv0.y+bb0.y);
            acc[i][1] = pk2(cv0.z+bb0.z, cv0.w+bb0.w);
            acc[i][2] = pk2(cv1.x+bb1.x, cv1.y+bb1.y);
            acc[i][3] = pk2(cv1.z+bb1.z, cv1.w+bb1.w);
        }
    }

    for (int kc = 0; kc < K; kc += 32){
        // stage B chunk: Bs[kk][c], 32 x 128
        #pragma unroll
        for (int i4 = tid; i4 < 1024; i4 += NT){
            int kk = i4 >> 5, c4 = (i4 & 31) << 2;
            *(float4*)(Bs + kk*128 + c4) =
                *(const float4*)(Bg + (size_t)(kc+kk)*ldb + c4);
        }
        __syncthreads();

        #pragma unroll
        for (int k = 0; k < 32; k += 4){
            float4 av[4];
            #pragma unroll
            for (int i = 0; i < 4; i++)
                av[i] = *(const float4*)(A + (r0+i)*128 + kc + k);
            #pragma unroll
            for (int kk = 0; kk < 4; kk++){
                const float* brow = Bs + (k+kk)*128 + c0;
                ulonglong2 bA = *(const ulonglong2*)(brow);
                ulonglong2 bB = *(const ulonglong2*)(brow + 4);
                #pragma unroll
                for (int i = 0; i < 4; i++){
                    float a = ((const float*)&av[i])[kk];
                    unsigned long long pa = pk2(a, a);
                    acc[i][0] = fma2(pa, bA.x, acc[i][0]);
                    acc[i][1] = fma2(pa, bA.y, acc[i][1]);
                    acc[i][2] = fma2(pa, bB.x, acc[i][2]);
                    acc[i][3] = fma2(pa, bB.y, acc[i][3]);
                }
            }
        }
        __syncthreads();
    }

    #pragma unroll
    for (int i = 0; i < 4; i++){
        float f[8];
        upk2(acc[i][0], f[0], f[1]);
        upk2(acc[i][1], f[2], f[3]);
        upk2(acc[i][2], f[4], f[5]);
        upk2(acc[i][3], f[6], f[7]);
        if (DOGELU){
            #pragma unroll
            for (int j = 0; j < 8; j++) f[j] = gelu_f(f[j]);
        }
        *(float4*)(C + (r0+i)*128 + c0)     = make_float4(f[0],f[1],f[2],f[3]);
        *(float4*)(C + (r0+i)*128 + c0 + 4) = make_float4(f[4],f[5],f[6],f[7]);
    }
    __syncthreads();
}

// ---------------- LayerNorm: dst = LN(src)*w + b ----------------
__device__ __forceinline__ void layernorm(const float* __restrict__ src,
                                          float* __restrict__ dst,
                                          const float* __restrict__ w,
                                          const float* __restrict__ b){
    const int warp = threadIdx.x >> 5, lane = threadIdx.x & 31;
    for (int r = warp; r < RROWS; r += NWARP){
        float4 v = *(const float4*)(src + r*DIM + lane*4);
        float s  = v.x+v.y+v.z+v.w;
        float ss = v.x*v.x+v.y*v.y+v.z*v.z+v.w*v.w;
        #pragma unroll
        for (int o = 16; o; o >>= 1){
            s  += __shfl_xor_sync(0xffffffffu, s,  o);
            ss += __shfl_xor_sync(0xffffffffu, ss, o);
        }
        float mean = s * (1.0f/DIM);
        float var  = ss * (1.0f/DIM) - mean*mean;
        float rstd = rsqrtf(var + 1e-5f);
        float4 wv = *(const float4*)(w + lane*4);
        float4 bv = *(const float4*)(b + lane*4);
        float4 o4;
        o4.x = (v.x-mean)*rstd*wv.x + bv.x;
        o4.y = (v.y-mean)*rstd*wv.y + bv.y;
        o4.z = (v.z-mean)*rstd*wv.z + bv.z;
        o4.w = (v.w-mean)*rstd*wv.w + bv.w;
        *(float4*)(dst + r*DIM + lane*4) = o4;
    }
}

// ---------------- warp-cooperative attention (conflict-free) ----------------
// Q in sq (overwritten by O), K in sk, V in sv. One warp per row, lanes span 128 dims.
__device__ __forceinline__ void attention(float* __restrict__ sq,
                                          const float* __restrict__ sk,
                                          const float* __restrict__ sv){
    const int warp = threadIdx.x >> 5, lane = threadIdx.x & 31;
    const int qoff = ((lane >> 3) << 5) + ((lane & 7) << 2);  // head*32 + sub*4
    const float scale = 0.17677669529663687f;                 // 1/sqrt(32)

    for (int r = warp; r < RROWS; r += NWARP){
        const int base = (r >> 4) << 4;   // first token row of this cell
        float4 q4 = *(const float4*)(sq + r*DIM + qoff);
        float sc[LTOK]; float mx = -1e30f;
        #pragma unroll
        for (int j = 0; j < LTOK; j++){
            float4 k4 = *(const float4*)(sk + (base+j)*DIM + qoff);
            float s = q4.x*k4.x + q4.y*k4.y + q4.z*k4.z + q4.w*k4.w;
            s += __shfl_xor_sync(0xffffffffu, s, 1);
            s += __shfl_xor_sync(0xffffffffu, s, 2);
            s += __shfl_xor_sync(0xffffffffu, s, 4);
            s *= scale;
            sc[j] = s; mx = fmaxf(mx, s);
        }
        float den = 0.0f;
        #pragma unroll
        for (int j = 0; j < LTOK; j++){ sc[j] = __expf(sc[j]-mx); den += sc[j]; }
        float inv = __fdividef(1.0f, den);
        float4 o = make_float4(0.f,0.f,0.f,0.f);
        #pragma unroll
        for (int j = 0; j < LTOK; j++){
            float p = sc[j]*inv;
            float4 v4 = *(const float4*)(sv + (base+j)*DIM + qoff);
            o.x += p*v4.x; o.y += p*v4.y; o.z += p*v4.z; o.w += p*v4.w;
        }
        *(float4*)(sq + r*DIM + qoff) = o;
    }
}

// ---------------- fused per-3-cell transformer ----------------
__global__ __launch_bounds__(NT, 2)
void k_transformer(const float* __restrict__ x,
                   const float* __restrict__ ln1w, const float* __restrict__ ln1b,
                   const float* __restrict__ wqkv, const float* __restrict__ bqkv,
                   const float* __restrict__ wo,   const float* __restrict__ bo,
                   const float* __restrict__ ln2w, const float* __restrict__ ln2b,
                   const float* __restrict__ w1,   const float* __restrict__ b1,
                   const float* __restrict__ w2,   const float* __restrict__ b2){
    extern __shared__ float smem[];
    float* sh  = smem;                  // 48*128 residual
    float* sxn = sh  + RROWS*DIM;       // 48*128 LN out / V overlay
    float* sq  = sxn + RROWS*DIM;       // 48*128 Q / O / MLP h1
    float* sk  = sq  + RROWS*DIM;       // 48*128 K
    float* sb  = sk  + RROWS*DIM;       // 32*128 weight stage
    int*  sel   = (int*)(sb + 32*DIM);  // G*LMAX
    int*  smcnt = sel + G*LMAX;         // G

    const int tid   = threadIdx.x;
    const int cell0 = blockIdx.x * G;

    // ---- token selection ----
    if (tid < G){
        int cell  = cell0 + tid;
        int cnt   = g_counts[cell];
        int avail = min(cnt, CAP);
        int m     = min(cnt, LMAX);
        smcnt[tid] = m;
        if (cnt <= LMAX){
            for (int j = 0; j < m; j++)
                sel[tid*LMAX + j] = g_list[cell*CAP + j];
        } else {
            int tmp[CAP];
            for (int j = 0; j < avail; j++) tmp[j] = g_list[cell*CAP + j];
            for (int a = 0; a < m; a++){
                int best = a;
                for (int bq2 = a+1; bq2 < avail; bq2++)
                    if (tmp[bq2] < tmp[best]) best = bq2;
                int t2 = tmp[best]; tmp[best] = tmp[a]; tmp[a] = t2;
                sel[tid*LMAX + a] = t2;
            }
        }
    }
    __syncthreads();

    // ---- assemble h ----
    for (int i = tid; i < RROWS*DIM; i += NT){
        int r = i >> 7, d = i & 127;
        int g = r >> 4, lr = r & 15;
        float v;
        if (lr < NB) v = g_bgp[lr*DIM + d];
        else {
            int j = lr - NB;
            v = (j < smcnt[g]) ? x[(size_t)sel[g*LMAX + j]*DIM + d] : 0.0f;
        }
        sh[i] = v;
    }
    __syncthreads();

    for (int layer = 0; layer < DEPTH; layer++){
        // ---- attention ----
        layernorm(sh, sxn, ln1w + layer*DIM, ln1b + layer*DIM);
        __syncthreads();

        const float* wqL = wqkv + (size_t)layer*DIM*3*DIM;
        const float* bqL = bqkv + layer*3*DIM;
        gemm_tile<128,1,false>(sxn, wqL +   0, 3*DIM, bqL +   0, sq,  sb);
        gemm_tile<128,1,false>(sxn, wqL + 128, 3*DIM, bqL + 128, sk,  sb);
        gemm_tile<128,1,false>(sxn, wqL + 256, 3*DIM, bqL + 256, sxn, sb); // V overlays LN buf

        attention(sq, sk, sxn);
        __syncthreads();

        gemm_tile<128,3,false>(sq, wo + (size_t)layer*DIM*DIM, DIM,
                               bo + layer*DIM, sh, sb);

        // ---- MLP ----
        layernorm(sh, sxn, ln2w + layer*DIM, ln2b + layer*DIM);
        __syncthreads();

        for (int n = 0; n < 4; n++){
            gemm_tile<128,1,true>(sxn, w1 + (size_t)layer*DIM*512 + n*128, 512,
                                  b1 + layer*512 + n*128, sq, sb);
            const float* w2p = w2 + (size_t)layer*512*DIM + (size_t)n*128*DIM;
            if (n == 0)
                gemm_tile<128,3,false>(sq, w2p, DIM, b2 + layer*DIM, sh, sb);
            else
                gemm_tile<128,2,false>(sq, w2p, DIM, (const float*)0, sh, sb);
        }
    }

    // ---- export background features ----
    for (int i = tid; i < G*NB*DIM; i += NT){
        int g   = i >> 9;
        int rem = i & 511;
        int lr  = rem >> 7;
        int d   = rem & 127;
        g_feat[(size_t)(cell0+g)*(NB*DIM) + rem] = sh[(g*LTOK + lr)*DIM + d];
    }
}

// ---------------- final projection: out(5760x1024) = feat(5760x512) @ W + b ----------------
__global__ __launch_bounds__(PNT, 2)
void k_proj(const float* __restrict__ Wp, const float* __restrict__ bp,
            float* __restrict__ out){
    __shared__ float As[64*32];
    __shared__ float Bs2[32*128];
    const int tid = threadIdx.x;
    const int rowblk = blockIdx.x, colblk = blockIdx.y;
    const int rg = tid >> 4, cg = tid & 15;
    const int r0 = rg*4, c0 = cg*8;

    unsigned long long acc[4][4];
    {
        const float* bb = bp + colblk*128 + c0;
        float4 b0 = *(const float4*)(bb);
        float4 b1 = *(const float4*)(bb + 4);
        unsigned long long p0 = pk2(b0.x,b0.y), p1 = pk2(b0.z,b0.w);
        unsigned long long p2 = pk2(b1.x,b1.y), p3 = pk2(b1.z,b1.w);
        #pragma unroll
        for (int i = 0; i < 4; i++){ acc[i][0]=p0; acc[i][1]=p1; acc[i][2]=p2; acc[i][3]=p3; }
    }

    for (int kc = 0; kc < 512; kc += 32){
        #pragma unroll
        for (int i4 = tid; i4 < 512; i4 += PNT){
            int r = i4 >> 3, k4 = (i4 & 7) << 2;
            *(float4*)(As + r*32 + k4) =
                *(const float4*)(g_feat + (size_t)(rowblk*64 + r)*(NB*DIM) + kc + k4);
        }
        #pragma unroll
        for (int i4 = tid; i4 < 1024; i4 += PNT){
            int kk = i4 >> 5, c4 = (i4 & 31) << 2;
            *(float4*)(Bs2 + kk*128 + c4) =
                *(const float4*)(Wp + (size_t)(kc+kk)*CLV + colblk*128 + c4);
        }
        __syncthreads();
        #pragma unroll
        for (int k = 0; k < 32; k += 4){
            float4 av[4];
            #pragma unroll
            for (int i = 0; i < 4; i++)
                av[i] = *(const float4*)(As + (r0+i)*32 + k);
            #pragma unroll
            for (int kk = 0; kk < 4; kk++){
                const float* brow = Bs2 + (k+kk)*128 + c0;
                ulonglong2 bA = *(const ulonglong2*)(brow);
                ulonglong2 bB = *(const ulonglong2*)(brow + 4);
                #pragma unroll
                for (int i = 0; i < 4; i++){
                    float a = ((const float*)&av[i])[kk];
                    unsigned long long pa = pk2(a, a);
                    acc[i][0] = fma2(pa, bA.x, acc[i][0]);
                    acc[i][1] = fma2(pa, bA.y, acc[i][1]);
                    acc[i][2] = fma2(pa, bB.x, acc[i][2]);
                    acc[i][3] = fma2(pa, bB.y, acc[i][3]);
                }
            }
        }
        __syncthreads();
    }

    #pragma unroll
    for (int i = 0; i < 4; i++){
        int cell = rowblk*64 + r0 + i;
        bool present = (g_counts[cell] > 0);
        float f[8];
        upk2(acc[i][0], f[0], f[1]);
        upk2(acc[i][1], f[2], f[3]);
        upk2(acc[i][2], f[4], f[5]);
        upk2(acc[i][3], f[6], f[7]);
        if (!present){
            #pragma unroll
            for (int j = 0; j < 8; j++) f[j] = 0.0f;
        }
        *(float4*)(out + (size_t)cell*CLV + colblk*128 + c0)     = make_float4(f[0],f[1],f[2],f[3]);
        *(float4*)(out + (size_t)cell*CLV + colblk*128 + c0 + 4) = make_float4(f[4],f[5],f[6],f[7]);
    }
}

// ---------------- launch ----------------
extern "C" void kernel_launch(void* const* d_in, const int* in_sizes, int n_in,
                              void* d_out, int out_size){
    const float* x    = (const float*)d_in[0];
    const int*   li   = (const int*)  d_in[1];
    const float* ob   = (const float*)d_in[2];
    const float* dw   = (const float*)d_in[3];
    const float* db   = (const float*)d_in[4];
    const float* ln1w = (const float*)d_in[5];
    const float* ln1b = (const float*)d_in[6];
    const float* wqkv = (const float*)d_in[7];
    const float* bqkv = (const float*)d_in[8];
    const float* wo   = (const float*)d_in[9];
    const float* bo   = (const float*)d_in[10];
    const float* ln2w = (const float*)d_in[11];
    const float* ln2b = (const float*)d_in[12];
    const float* w1   = (const float*)d_in[13];
    const float* b1   = (const float*)d_in[14];
    const float* w2   = (const float*)d_in[15];
    const float* b2   = (const float*)d_in[16];
    const float* pw   = (const float*)d_in[17];
    const float* pb   = (const float*)d_in[18];

    int n = in_sizes[0] / DIM;

    const int SMEM_BYTES = (4*RROWS*DIM + 32*DIM) * 4 + (G*LMAX + G) * 4;
    cudaFuncSetAttribute(k_transformer, cudaFuncAttributeMaxDynamicSharedMemorySize, SMEM_BYTES);

    k_zero<<<(BALL + 255)/256, 256>>>();
    k_scatter<<<(n + 255)/256, 256>>>(li, n);
    k_bg<<<2, 256>>>(ob, dw, db);
    k_transformer<<<BALL/G, NT, SMEM_BYTES>>>(x, ln1w, ln1b, wqkv, bqkv, wo, bo,
                                              ln2w, ln2b, w1, b1, w2, b2);
    k_proj<<<dim3(BALL/64, CLV/128), PNT>>>(pw, pb, (float*)d_out);
}

// round 5
// speedup vs baseline: 1.2209x; 1.2209x over previous
#include <cuda_runtime.h>
#include <cstdint>
#include <math.h>

#define DD     5
#define HGRID  24
#define WGRID  48
#define CLV    1024
#define NB     4
#define DIM    128
#define LMAX   12
#define DEPTH  6
#define LTOK   16
#define BALL   (DD*HGRID*WGRID)   // 5760
#define CAP    64
#define G      2
#define RROWS  (G*LTOK)           // 32
#define NT     128
#define NWARP  (NT/32)            // 4
#define ATS    132                // transposed k-group block stride (words)
#define PNT    256

// ---------------- device scratch ----------------
__device__ int   g_counts[BALL];
__device__ int   g_list[BALL*CAP];
__device__ float g_bgp[NB*DIM];
__device__ float g_feat[BALL*NB*DIM];

// ---------------- packed f32x2 helpers ----------------
__device__ __forceinline__ unsigned long long pk2(float lo, float hi){
    unsigned long long r;
    asm("mov.b64 %0,{%1,%2};" : "=l"(r) : "f"(lo), "f"(hi));
    return r;
}
__device__ __forceinline__ void upk2(unsigned long long v, float &lo, float &hi){
    asm("mov.b64 {%0,%1},%2;" : "=f"(lo), "=f"(hi) : "l"(v));
}
__device__ __forceinline__ unsigned long long fma2(unsigned long long a,
                                                   unsigned long long b,
                                                   unsigned long long c){
    unsigned long long d;
    asm("fma.rn.f32x2 %0,%1,%2,%3;" : "=l"(d) : "l"(a), "l"(b), "l"(c));
    return d;
}

__device__ __forceinline__ float gelu_f(float x){
    float x3 = x*x*x;
    return 0.5f*x*(1.0f + tanhf(0.7978845608028654f*(x + 0.044715f*x3)));
}

// ---------------- tiny setup kernels ----------------
__global__ void k_zero(){
    int i = blockIdx.x*blockDim.x + threadIdx.x;
    if (i < BALL) g_counts[i] = 0;
}

__global__ void k_scatter(const int* __restrict__ li, int n){
    int i = blockIdx.x*blockDim.x + threadIdx.x;
    if (i >= n) return;
    int a = li[3*i], b = li[3*i+1], c = li[3*i+2];
    int flat = a*(HGRID*WGRID) + b*WGRID + c;
    int slot = atomicAdd(&g_counts[flat], 1);
    if (slot < CAP) g_list[flat*CAP + slot] = i;
}

__global__ void k_bg(const float* __restrict__ ob,
                     const float* __restrict__ dw,
                     const float* __restrict__ db){
    int c = blockIdx.x*blockDim.x + threadIdx.x;
    if (c >= NB*DIM) return;
    float s = 0.0f;
    for (int m = 0; m < NB; m++){
        const float* bg = ob + m*DIM;
        float t = 0.0f;
        for (int k = 0; k < DIM; k++)
            t += bg[k] * dw[k*(NB*DIM) + c];
        s += t;
    }
    s = s * (1.0f/NB) + db[c];
    g_bgp[c] = ob[c] + s;
}

// ---------------- GEMM tile: C(32 x 128) = A^T-layout (K x 32) @ B (K x 128) --------
// At layout: element (k, r) at At[(k>>2)*ATS + (k&3)*32 + r]  (row-pairs load as u64).
// Warp w owns rows r0=w*8 .. r0+7, lane owns cols c0=lane*4 .. +3.
// acc[rp][c] packs (row r0+2rp, row r0+2rp+1) for column c0+c.
// MODE: 0=zero, 1=bias, 2=load C (accumulate), 3=load C + bias.
// TOUT: store result transposed in At-layout (for h1t); else normal 32x128 row-major.
template<int K, int MODE, bool DOGELU, bool TOUT>
__device__ __forceinline__ void gemm_t(const float* __restrict__ At,
                                       const float* __restrict__ Bg, int ldb,
                                       const float* __restrict__ bias,
                                       float* __restrict__ C,
                                       float* __restrict__ Bs){
    const int tid  = threadIdx.x;
    const int lane = tid & 31;
    const int r0   = (tid >> 5) * 8;
    const int c0   = lane * 4;

    unsigned long long acc[4][4];
    if (MODE == 0){
        #pragma unroll
        for (int rp = 0; rp < 4; rp++)
            #pragma unroll
            for (int c = 0; c < 4; c++) acc[rp][c] = 0ull;
    } else if (MODE == 1){
        float4 bb = *(const float4*)(bias + c0);
        unsigned long long d0 = pk2(bb.x,bb.x), d1 = pk2(bb.y,bb.y);
        unsigned long long d2 = pk2(bb.z,bb.z), d3 = pk2(bb.w,bb.w);
        #pragma unroll
        for (int rp = 0; rp < 4; rp++){
            acc[rp][0]=d0; acc[rp][1]=d1; acc[rp][2]=d2; acc[rp][3]=d3;
        }
    } else {
        float4 bb = make_float4(0.f,0.f,0.f,0.f);
        if (MODE == 3) bb = *(const float4*)(bias + c0);
        #pragma unroll
        for (int rp = 0; rp < 4; rp++){
            float4 cv0 = *(const float4*)(C + (r0+2*rp)*128 + c0);
            float4 cv1 = *(const float4*)(C + (r0+2*rp+1)*128 + c0);
            acc[rp][0] = pk2(cv0.x+bb.x, cv1.x+bb.x);
            acc[rp][1] = pk2(cv0.y+bb.y, cv1.y+bb.y);
            acc[rp][2] = pk2(cv0.z+bb.z, cv1.z+bb.z);
            acc[rp][3] = pk2(cv0.w+bb.w, cv1.w+bb.w);
        }
    }

    for (int kc = 0; kc < K; kc += 32){
        // stage B chunk 32 x 128 (warp per row, lanes span cols: conflict-free)
        #pragma unroll
        for (int i4 = tid; i4 < 1024; i4 += NT){
            int row = i4 >> 5, c4 = (i4 & 31) << 2;
            *(float4*)(Bs + row*128 + c4) =
                *(const float4*)(Bg + (size_t)(kc+row)*ldb + c4);
        }
        __syncthreads();

        #pragma unroll 2
        for (int kg = 0; kg < 8; kg++){
            const float* abase = At + (size_t)((kc >> 2) + kg)*ATS + r0;
            #pragma unroll
            for (int kk = 0; kk < 4; kk++){
                ulonglong2 a01 = *(const ulonglong2*)(abase + 32*kk);
                ulonglong2 a23 = *(const ulonglong2*)(abase + 32*kk + 4);
                float4 b = *(const float4*)(Bs + (kg*4 + kk)*128 + c0);
                unsigned long long bd0 = pk2(b.x,b.x), bd1 = pk2(b.y,b.y);
                unsigned long long bd2 = pk2(b.z,b.z), bd3 = pk2(b.w,b.w);
                acc[0][0] = fma2(a01.x, bd0, acc[0][0]);
                acc[0][1] = fma2(a01.x, bd1, acc[0][1]);
                acc[0][2] = fma2(a01.x, bd2, acc[0][2]);
                acc[0][3] = fma2(a01.x, bd3, acc[0][3]);
                acc[1][0] = fma2(a01.y, bd0, acc[1][0]);
                acc[1][1] = fma2(a01.y, bd1, acc[1][1]);
                acc[1][2] = fma2(a01.y, bd2, acc[1][2]);
                acc[1][3] = fma2(a01.y, bd3, acc[1][3]);
                acc[2][0] = fma2(a23.x, bd0, acc[2][0]);
                acc[2][1] = fma2(a23.x, bd1, acc[2][1]);
                acc[2][2] = fma2(a23.x, bd2, acc[2][2]);
                acc[2][3] = fma2(a23.x, bd3, acc[2][3]);
                acc[3][0] = fma2(a23.y, bd0, acc[3][0]);
                acc[3][1] = fma2(a23.y, bd1, acc[3][1]);
                acc[3][2] = fma2(a23.y, bd2, acc[3][2]);
                acc[3][3] = fma2(a23.y, bd3, acc[3][3]);
            }
        }
        __syncthreads();
    }

    if (TOUT){
        // store transposed (At-layout): per column, 8 consecutive rows -> 2x STS.128
        #pragma unroll
        for (int c = 0; c < 4; c++){
            float f[8];
            upk2(acc[0][c], f[0], f[1]);
            upk2(acc[1][c], f[2], f[3]);
            upk2(acc[2][c], f[4], f[5]);
            upk2(acc[3][c], f[6], f[7]);
            if (DOGELU){
                #pragma unroll
                for (int j = 0; j < 8; j++) f[j] = gelu_f(f[j]);
            }
            float* dst = C + lane*ATS + 32*c + r0;
            *(float4*)(dst)     = make_float4(f[0],f[1],f[2],f[3]);
            *(float4*)(dst + 4) = make_float4(f[4],f[5],f[6],f[7]);
        }
    } else {
        #pragma unroll
        for (int rp = 0; rp < 4; rp++){
            float e0,o0,e1,o1,e2,o2,e3,o3;
            upk2(acc[rp][0], e0, o0);
            upk2(acc[rp][1], e1, o1);
            upk2(acc[rp][2], e2, o2);
            upk2(acc[rp][3], e3, o3);
            if (DOGELU){
                e0=gelu_f(e0); o0=gelu_f(o0); e1=gelu_f(e1); o1=gelu_f(o1);
                e2=gelu_f(e2); o2=gelu_f(o2); e3=gelu_f(e3); o3=gelu_f(o3);
            }
            *(float4*)(C + (r0+2*rp)*128 + c0)   = make_float4(e0,e1,e2,e3);
            *(float4*)(C + (r0+2*rp+1)*128 + c0) = make_float4(o0,o1,o2,o3);
        }
    }
    __syncthreads();
}

// ---------------- LayerNorm: At(transposed) = LN(src)*w + b ----------------
__device__ __forceinline__ void layernorm_t(const float* __restrict__ src,
                                            float* __restrict__ At,
                                            const float* __restrict__ w,
                                            const float* __restrict__ b){
    const int warp = threadIdx.x >> 5, lane = threadIdx.x & 31;
    float4 wv = *(const float4*)(w + lane*4);
    float4 bv = *(const float4*)(b + lane*4);
    for (int r = warp; r < RROWS; r += NWARP){
        float4 v = *(const float4*)(src + r*DIM + lane*4);
        float s  = v.x+v.y+v.z+v.w;
        float ss = v.x*v.x+v.y*v.y+v.z*v.z+v.w*v.w;
        #pragma unroll
        for (int o = 16; o; o >>= 1){
            s  += __shfl_xor_sync(0xffffffffu, s,  o);
            ss += __shfl_xor_sync(0xffffffffu, ss, o);
        }
        float mean = s * (1.0f/DIM);
        float var  = ss * (1.0f/DIM) - mean*mean;
        float rstd = rsqrtf(var + 1e-5f);
        float* dst = At + lane*ATS + r;
        dst[0]  = (v.x-mean)*rstd*wv.x + bv.x;
        dst[32] = (v.y-mean)*rstd*wv.y + bv.y;
        dst[64] = (v.z-mean)*rstd*wv.z + bv.z;
        dst[96] = (v.w-mean)*rstd*wv.w + bv.w;
    }
}

// ---------------- warp-cooperative attention -> O written transposed to At ----------
__device__ __forceinline__ void attention_t(const float* __restrict__ sq,
                                            const float* __restrict__ sk,
                                            const float* __restrict__ sv,
                                            float* __restrict__ At){
    const int warp = threadIdx.x >> 5, lane = threadIdx.x & 31;
    const int qoff = ((lane >> 3) << 5) + ((lane & 7) << 2);  // head*32 + sub*4
    const float scale = 0.17677669529663687f;                 // 1/sqrt(32)

    for (int r = warp; r < RROWS; r += NWARP){
        const int base = (r >> 4) << 4;
        float4 q4 = *(const float4*)(sq + r*DIM + qoff);
        float sc[LTOK]; float mx = -1e30f;
        #pragma unroll
        for (int j = 0; j < LTOK; j++){
            float4 k4 = *(const float4*)(sk + (base+j)*DIM + qoff);
            float s = q4.x*k4.x + q4.y*k4.y + q4.z*k4.z + q4.w*k4.w;
            s += __shfl_xor_sync(0xffffffffu, s, 1);
            s += __shfl_xor_sync(0xffffffffu, s, 2);
            s += __shfl_xor_sync(0xffffffffu, s, 4);
            s *= scale;
            sc[j] = s; mx = fmaxf(mx, s);
        }
        float den = 0.0f;
        #pragma unroll
        for (int j = 0; j < LTOK; j++){ sc[j] = __expf(sc[j]-mx); den += sc[j]; }
        float inv = __fdividef(1.0f, den);
        float4 o = make_float4(0.f,0.f,0.f,0.f);
        #pragma unroll
        for (int j = 0; j < LTOK; j++){
            float p = sc[j]*inv;
            float4 v4 = *(const float4*)(sv + (base+j)*DIM + qoff);
            o.x += p*v4.x; o.y += p*v4.y; o.z += p*v4.z; o.w += p*v4.w;
        }
        // dims qoff..qoff+3 -> kg = qoff>>2 == lane, j-planes 0..3
        float* dst = At + lane*ATS + r;
        dst[0]  = o.x;
        dst[32] = o.y;
        dst[64] = o.z;
        dst[96] = o.w;
    }
}

// ---------------- fused per-2-cell transformer ----------------
__global__ __launch_bounds__(NT, 2)
void k_transformer(const float* __restrict__ x,
                   const float* __restrict__ ln1w, const float* __restrict__ ln1b,
                   const float* __restrict__ wqkv, const float* __restrict__ bqkv,
                   const float* __restrict__ wo,   const float* __restrict__ bo,
                   const float* __restrict__ ln2w, const float* __restrict__ ln2b,
                   const float* __restrict__ w1,   const float* __restrict__ b1,
                   const float* __restrict__ w2,   const float* __restrict__ b2){
    extern __shared__ float smem[];
    float* sh = smem;              // 4096: residual (32x128)
    float* sq = sh + 4096;         // 4096: Q
    float* sk = sq + 4096;         // 4096: K / h1t (spills into sv)
    float* sv = sk + 4096;         // 4096: V
    float* At = sv + 4096;         // 4224: transposed A (LN out / attn O)
    float* Bs = At + 4224;         // 4096: B stage (32x128)
    int*  sel   = (int*)(Bs + 4096);   // G*LMAX
    int*  smcnt = sel + G*LMAX;        // G
    float* h1t = sk;               // transposed gelu(h1) panel, 4224 words

    const int tid   = threadIdx.x;
    const int cell0 = blockIdx.x * G;

    // ---- token selection ----
    if (tid < G){
        int cell  = cell0 + tid;
        int cnt   = g_counts[cell];
        int avail = min(cnt, CAP);
        int m     = min(cnt, LMAX);
        smcnt[tid] = m;
        if (cnt <= LMAX){
            for (int j = 0; j < m; j++)
                sel[tid*LMAX + j] = g_list[cell*CAP + j];
        } else {
            int tmp[CAP];
            for (int j = 0; j < avail; j++) tmp[j] = g_list[cell*CAP + j];
            for (int a = 0; a < m; a++){
                int best = a;
                for (int bq2 = a+1; bq2 < avail; bq2++)
                    if (tmp[bq2] < tmp[best]) best = bq2;
                int t2 = tmp[best]; tmp[best] = tmp[a]; tmp[a] = t2;
                sel[tid*LMAX + a] = t2;
            }
        }
    }
    __syncthreads();

    // ---- assemble h (32 rows x 128) ----
    for (int i = tid; i < RROWS*DIM; i += NT){
        int r = i >> 7, d = i & 127;
        int g = r >> 4, lr = r & 15;
        float v;
        if (lr < NB) v = g_bgp[lr*DIM + d];
        else {
            int j = lr - NB;
            v = (j < smcnt[g]) ? x[(size_t)sel[g*LMAX + j]*DIM + d] : 0.0f;
        }
        sh[i] = v;
    }
    __syncthreads();

    for (int layer = 0; layer < DEPTH; layer++){
        // ---- attention ----
        layernorm_t(sh, At, ln1w + layer*DIM, ln1b + layer*DIM);
        __syncthreads();

        const float* wqL = wqkv + (size_t)layer*DIM*3*DIM;
        const float* bqL = bqkv + layer*3*DIM;
        gemm_t<128,1,false,false>(At, wqL +   0, 3*DIM, bqL +   0, sq, Bs);
        gemm_t<128,1,false,false>(At, wqL + 128, 3*DIM, bqL + 128, sk, Bs);
        gemm_t<128,1,false,false>(At, wqL + 256, 3*DIM, bqL + 256, sv, Bs);

        attention_t(sq, sk, sv, At);
        __syncthreads();

        gemm_t<128,3,false,false>(At, wo + (size_t)layer*DIM*DIM, DIM,
                                  bo + layer*DIM, sh, Bs);

        // ---- MLP ----
        layernorm_t(sh, At, ln2w + layer*DIM, ln2b + layer*DIM);
        __syncthreads();

        for (int n = 0; n < 4; n++){
            gemm_t<128,1,true,true>(At, w1 + (size_t)layer*DIM*512 + n*128, 512,
                                    b1 + layer*512 + n*128, h1t, Bs);
            const float* w2p = w2 + (size_t)layer*512*DIM + (size_t)n*128*DIM;
            if (n == 0)
                gemm_t<128,3,false,false>(h1t, w2p, DIM, b2 + layer*DIM, sh, Bs);
            else
                gemm_t<128,2,false,false>(h1t, w2p, DIM, (const float*)0, sh, Bs);
        }
    }

    // ---- export background features ----
    for (int i = tid; i < G*NB*DIM; i += NT){
        int g   = i >> 9;
        int rem = i & 511;
        int lr  = rem >> 7;
        int d   = rem & 127;
        g_feat[(size_t)(cell0+g)*(NB*DIM) + rem] = sh[(g*LTOK + lr)*DIM + d];
    }
}

// ---------------- final projection: out(5760x1024) = feat(5760x512) @ W + b ----------
__global__ __launch_bounds__(PNT, 2)
void k_proj(const float* __restrict__ Wp, const float* __restrict__ bp,
            float* __restrict__ out){
    __shared__ float As[64*32];
    __shared__ float Bs2[32*128];
    const int tid = threadIdx.x;
    const int rowblk = blockIdx.x, colblk = blockIdx.y;
    const int rg = tid >> 4, cg = tid & 15;
    const int r0 = rg*4, c0 = cg*8;

    unsigned long long acc[4][4];
    {
        const float* bb = bp + colblk*128 + c0;
        float4 b0 = *(const float4*)(bb);
        float4 b1 = *(const float4*)(bb + 4);
        unsigned long long p0 = pk2(b0.x,b0.y), p1 = pk2(b0.z,b0.w);
        unsigned long long p2 = pk2(b1.x,b1.y), p3 = pk2(b1.z,b1.w);
        #pragma unroll
        for (int i = 0; i < 4; i++){ acc[i][0]=p0; acc[i][1]=p1; acc[i][2]=p2; acc[i][3]=p3; }
    }

    for (int kc = 0; kc < 512; kc += 32){
        #pragma unroll
        for (int i4 = tid; i4 < 512; i4 += PNT){
            int r = i4 >> 3, k4 = (i4 & 7) << 2;
            *(float4*)(As + r*32 + k4) =
                *(const float4*)(g_feat + (size_t)(rowblk*64 + r)*(NB*DIM) + kc + k4);
        }
        #pragma unroll
        for (int i4 = tid; i4 < 1024; i4 += PNT){
            int kk = i4 >> 5, c4 = (i4 & 31) << 2;
            *(float4*)(Bs2 + kk*128 + c4) =
                *(const float4*)(Wp + (size_t)(kc+kk)*CLV + colblk*128 + c4);
        }
        __syncthreads();
        #pragma unroll
        for (int k = 0; k < 32; k += 4){
            float4 av[4];
            #pragma unroll
            for (int i = 0; i < 4; i++)
                av[i] = *(const float4*)(As + (r0+i)*32 + k);
            #pragma unroll
            for (int kk = 0; kk < 4; kk++){
                const float* brow = Bs2 + (k+kk)*128 + c0;
                ulonglong2 bA = *(const ulonglong2*)(brow);
                ulonglong2 bB = *(const ulonglong2*)(brow + 4);
                #pragma unroll
                for (int i = 0; i < 4; i++){
                    float a = ((const float*)&av[i])[kk];
                    unsigned long long pa = pk2(a, a);
                    acc[i][0] = fma2(pa, bA.x, acc[i][0]);
                    acc[i][1] = fma2(pa, bA.y, acc[i][1]);
                    acc[i][2] = fma2(pa, bB.x, acc[i][2]);
                    acc[i][3] = fma2(pa, bB.y, acc[i][3]);
                }
            }
        }
        __syncthreads();
    }

    #pragma unroll
    for (int i = 0; i < 4; i++){
        int cell = rowblk*64 + r0 + i;
        bool present = (g_counts[cell] > 0);
        float f[8];
        upk2(acc[i][0], f[0], f[1]);
        upk2(acc[i][1], f[2], f[3]);
        upk2(acc[i][2], f[4], f[5]);
        upk2(acc[i][3], f[6], f[7]);
        if (!present){
            #pragma unroll
            for (int j = 0; j < 8; j++) f[j] = 0.0f;
        }
        *(float4*)(out + (size_t)cell*CLV + colblk*128 + c0)     = make_float4(f[0],f[1],f[2],f[3]);
        *(float4*)(out + (size_t)cell*CLV + colblk*128 + c0 + 4) = make_float4(f[4],f[5],f[6],f[7]);
    }
}

// ---------------- launch ----------------
extern "C" void kernel_launch(void* const* d_in, const int* in_sizes, int n_in,
                              void* d_out, int out_size){
    const float* x    = (const float*)d_in[0];
    const int*   li   = (const int*)  d_in[1];
    const float* ob   = (const float*)d_in[2];
    const float* dw   = (const float*)d_in[3];
    const float* db   = (const float*)d_in[4];
    const float* ln1w = (const float*)d_in[5];
    const float* ln1b = (const float*)d_in[6];
    const float* wqkv = (const float*)d_in[7];
    const float* bqkv = (const float*)d_in[8];
    const float* wo   = (const float*)d_in[9];
    const float* bo   = (const float*)d_in[10];
    const float* ln2w = (const float*)d_in[11];
    const float* ln2b = (const float*)d_in[12];
    const float* w1   = (const float*)d_in[13];
    const float* b1   = (const float*)d_in[14];
    const float* w2   = (const float*)d_in[15];
    const float* b2   = (const float*)d_in[16];
    const float* pw   = (const float*)d_in[17];
    const float* pb   = (const float*)d_in[18];

    int n = in_sizes[0] / DIM;

    const int SMEM_BYTES = (5*4096 + 4224) * 4 + (G*LMAX + G) * 4;
    cudaFuncSetAttribute(k_transformer, cudaFuncAttributeMaxDynamicSharedMemorySize, SMEM_BYTES);

    k_zero<<<(BALL + 255)/256, 256>>>();
    k_scatter<<<(n + 255)/256, 256>>>(li, n);
    k_bg<<<2, 256>>>(ob, dw, db);
    k_transformer<<<BALL/G, NT, SMEM_BYTES>>>(x, ln1w, ln1b, wqkv, bqkv, wo, bo,
                                              ln2w, ln2b, w1, b1, w2, b2);
    k_proj<<<dim3(BALL/64, CLV/128), PNT>>>(pw, pb, (float*)d_out);
}

// round 7
// speedup vs baseline: 2.1478x; 1.7592x over previous
#include <cuda_runtime.h>
#include <cuda_bf16.h>
#include <cstdint>
#include <math.h>

#define DD     5
#define HGRID  24
#define WGRID  48
#define CLV    1024
#define NB     4
#define DIM    128
#define LMAX   12
#define DEPTH  6
#define LTOK   16
#define BALL   (DD*HGRID*WGRID)   // 5760
#define NROW   (BALL*LTOK)        // 92160
#define CAP    64
#define HID    512
#define AS     72                 // smem row stride in bf16 (144B: conflict-free ldmatrix)

typedef __nv_bfloat16 bf16;

// ---------------- device scratch ----------------
__device__ int   g_counts[BALL];
__device__ int   g_list[BALL*CAP];
__device__ int   g_sel[BALL*LMAX];
__device__ int   g_m[BALL];
__device__ float g_bgp[NB*DIM];
__device__ float g_h[NROW*DIM];
__device__ float g_qkv[NROW*3*DIM];
__device__ bf16  g_a1[NROW*DIM],  g_a2[NROW*DIM];
__device__ bf16  g_h1a[NROW*HID], g_h1b[NROW*HID];
__device__ bf16  g_fa1[BALL*HID], g_fa2[BALL*HID];
// transposed + split weights: [n][k] k-fast
__device__ bf16  g_wqkvT1[DEPTH*3*DIM*DIM], g_wqkvT2[DEPTH*3*DIM*DIM];
__device__ bf16  g_woT1[DEPTH*DIM*DIM],     g_woT2[DEPTH*DIM*DIM];
__device__ bf16  g_w1T1[DEPTH*HID*DIM],     g_w1T2[DEPTH*HID*DIM];
__device__ bf16  g_w2T1[DEPTH*DIM*HID],     g_w2T2[DEPTH*DIM*HID];
__device__ bf16  g_pT1[CLV*HID],            g_pT2[CLV*HID];

// ---------------- helpers ----------------
__device__ __forceinline__ uint32_t s2u(const void* p){
    uint32_t a;
    asm("{ .reg .u64 t; cvta.to.shared.u64 t, %1; cvt.u32.u64 %0, t; }" : "=r"(a) : "l"(p));
    return a;
}
__device__ __forceinline__ void ldsm_x4(uint32_t* d, uint32_t addr){
    asm volatile("ldmatrix.sync.aligned.m8n8.x4.shared.b16 {%0,%1,%2,%3}, [%4];"
        : "=r"(d[0]),"=r"(d[1]),"=r"(d[2]),"=r"(d[3]) : "r"(addr));
}
__device__ __forceinline__ void ldsm_x2(uint32_t* d, uint32_t addr){
    asm volatile("ldmatrix.sync.aligned.m8n8.x2.shared.b16 {%0,%1}, [%2];"
        : "=r"(d[0]),"=r"(d[1]) : "r"(addr));
}
__device__ __forceinline__ void mma16816(float* c, const uint32_t* a, const uint32_t* b){
    asm volatile("mma.sync.aligned.m16n8k16.row.col.f32.bf16.bf16.f32 "
        "{%0,%1,%2,%3}, {%4,%5,%6,%7}, {%8,%9}, {%0,%1,%2,%3};"
        : "+f"(c[0]),"+f"(c[1]),"+f"(c[2]),"+f"(c[3])
        : "r"(a[0]),"r"(a[1]),"r"(a[2]),"r"(a[3]), "r"(b[0]),"r"(b[1]));
}
__device__ __forceinline__ float gelu_f(float x){
    float x3 = x*x*x;
    return 0.5f*x*(1.0f + tanhf(0.7978845608028654f*(x + 0.044715f*x3)));
}
__device__ __forceinline__ void split1(float v, bf16 &h, bf16 &l){
    h = __float2bfloat16(v);
    l = __float2bfloat16(v - __bfloat162float(h));
}

#define GF_ACCUM 1
#define GF_GELU  2
#define GF_SPLIT 4
#define GF_MASK  8

// ---------------- setup kernels ----------------
__global__ void k_zero(){
    int i = blockIdx.x*blockDim.x + threadIdx.x;
    if (i < BALL) g_counts[i] = 0;
}
__global__ void k_scatter(const int* __restrict__ li, int n){
    int i = blockIdx.x*blockDim.x + threadIdx.x;
    if (i >= n) return;
    int flat = li[3*i]*(HGRID*WGRID) + li[3*i+1]*WGRID + li[3*i+2];
    int slot = atomicAdd(&g_counts[flat], 1);
    if (slot < CAP) g_list[flat*CAP + slot] = i;
}
__global__ void k_bg(const float* __restrict__ ob, const float* __restrict__ dw,
                     const float* __restrict__ db){
    int c = blockIdx.x*blockDim.x + threadIdx.x;
    if (c >= NB*DIM) return;
    float s = 0.0f;
    for (int m = 0; m < NB; m++){
        const float* bg = ob + m*DIM;
        float t = 0.0f;
        for (int k = 0; k < DIM; k++) t += bg[k] * dw[k*(NB*DIM) + c];
        s += t;
    }
    g_bgp[c] = ob[c] + s*(1.0f/NB) + db[c];
}
__global__ void k_select(){
    int cell = blockIdx.x*blockDim.x + threadIdx.x;
    if (cell >= BALL) return;
    int cnt = g_counts[cell];
    int avail = min(cnt, CAP);
    int m = min(cnt, LMAX);
    g_m[cell] = m;
    if (cnt <= LMAX){
        for (int j = 0; j < m; j++) g_sel[cell*LMAX + j] = g_list[cell*CAP + j];
    } else {
        int tmp[CAP];
        for (int j = 0; j < avail; j++) tmp[j] = g_list[cell*CAP + j];
        for (int a = 0; a < m; a++){
            int best = a;
            for (int b = a+1; b < avail; b++) if (tmp[b] < tmp[best]) best = b;
            int t = tmp[best]; tmp[best] = tmp[a]; tmp[a] = t;
            g_sel[cell*LMAX + a] = t;
        }
    }
}
__global__ void k_assemble(const float* __restrict__ x){
    int idx = blockIdx.x*blockDim.x + threadIdx.x;
    if (idx >= NROW*DIM) return;
    int row = idx >> 7, d = idx & 127;
    int cell = row >> 4, lr = row & 15;
    float v;
    if (lr < NB) v = g_bgp[lr*DIM + d];
    else {
        int j = lr - NB;
        v = (j < g_m[cell]) ? x[(size_t)g_sel[cell*LMAX + j]*DIM + d] : 0.0f;
    }
    g_h[idx] = v;
}
// transpose + split: W[K][N] -> T1/T2[N][K], per-layer via blockIdx.y
__global__ void k_tsplit(const float* __restrict__ W, bf16* __restrict__ T1,
                         bf16* __restrict__ T2, int K, int N){
    size_t off = (size_t)blockIdx.y * K * N;
    W += off; T1 += off; T2 += off;
    int tot = K*N;
    for (int idx = blockIdx.x*blockDim.x + threadIdx.x; idx < tot;
         idx += gridDim.x*blockDim.x){
        int n = idx / K, k = idx - n*K;
        float v = W[(size_t)k*N + n];
        bf16 h, l; split1(v, h, l);
        T1[idx] = h; T2[idx] = l;
    }
}
// LayerNorm + bf16 split
__global__ void k_ln_split(const float* __restrict__ w, const float* __restrict__ b){
    int warp = threadIdx.x >> 5, lane = threadIdx.x & 31;
    int row = blockIdx.x*8 + warp;
    const float* src = g_h + (size_t)row*DIM;
    float4 v = *(const float4*)(src + lane*4);
    float s  = v.x+v.y+v.z+v.w;
    float ss = v.x*v.x+v.y*v.y+v.z*v.z+v.w*v.w;
    #pragma unroll
    for (int o = 16; o; o >>= 1){
        s  += __shfl_xor_sync(0xffffffffu, s,  o);
        ss += __shfl_xor_sync(0xffffffffu, ss, o);
    }
    float mean = s*(1.0f/DIM);
    float var  = ss*(1.0f/DIM) - mean*mean;
    float rstd = rsqrtf(var + 1e-5f);
    float4 wv = *(const float4*)(w + lane*4);
    float4 bv = *(const float4*)(b + lane*4);
    float n0 = (v.x-mean)*rstd*wv.x + bv.x;
    float n1 = (v.y-mean)*rstd*wv.y + bv.y;
    float n2 = (v.z-mean)*rstd*wv.z + bv.z;
    float n3 = (v.w-mean)*rstd*wv.w + bv.w;
    bf16 h0,l0,h1,l1,h2,l2,h3,l3;
    split1(n0,h0,l0); split1(n1,h1,l1); split1(n2,h2,l2); split1(n3,h3,l3);
    __nv_bfloat162* d1 = (__nv_bfloat162*)(g_a1 + (size_t)row*DIM + lane*4);
    __nv_bfloat162* d2 = (__nv_bfloat162*)(g_a2 + (size_t)row*DIM + lane*4);
    __nv_bfloat162 p;
    p.x=h0; p.y=h1; d1[0]=p;  p.x=h2; p.y=h3; d1[1]=p;
    p.x=l0; p.y=l1; d2[0]=p;  p.x=l2; p.y=l3; d2[1]=p;
}
// attention: per-cell softmax over 16 tokens, O -> split bf16 in g_a1/g_a2
__global__ void k_attn(){
    int warp = threadIdx.x >> 5, lane = threadIdx.x & 31;
    int cell = blockIdx.x*8 + warp;
    int qoff = ((lane >> 3) << 5) + ((lane & 7) << 2);
    const float scale = 0.17677669529663687f;
    size_t base = (size_t)cell*LTOK;
    for (int r = 0; r < LTOK; r++){
        float4 q4 = *(const float4*)(g_qkv + (base+r)*384 + qoff);
        float sc[LTOK]; float mx = -1e30f;
        #pragma unroll
        for (int j = 0; j < LTOK; j++){
            float4 k4 = *(const float4*)(g_qkv + (base+j)*384 + 128 + qoff);
            float sdot = q4.x*k4.x + q4.y*k4.y + q4.z*k4.z + q4.w*k4.w;
            sdot += __shfl_xor_sync(0xffffffffu, sdot, 1);
            sdot += __shfl_xor_sync(0xffffffffu, sdot, 2);
            sdot += __shfl_xor_sync(0xffffffffu, sdot, 4);
            sdot *= scale;
            sc[j] = sdot; mx = fmaxf(mx, sdot);
        }
        float den = 0.0f;
        #pragma unroll
        for (int j = 0; j < LTOK; j++){ sc[j] = __expf(sc[j]-mx); den += sc[j]; }
        float inv = __fdividef(1.0f, den);
        float4 o = make_float4(0.f,0.f,0.f,0.f);
        #pragma unroll
        for (int j = 0; j < LTOK; j++){
            float p = sc[j]*inv;
            float4 v4 = *(const float4*)(g_qkv + (base+j)*384 + 256 + qoff);
            o.x += p*v4.x; o.y += p*v4.y; o.z += p*v4.z; o.w += p*v4.w;
        }
        bf16 h0,l0,h1,l1,h2,l2,h3,l3;
        split1(o.x,h0,l0); split1(o.y,h1,l1); split1(o.z,h2,l2); split1(o.w,h3,l3);
        __nv_bfloat162* d1 = (__nv_bfloat162*)(g_a1 + (base+r)*DIM + qoff);
        __nv_bfloat162* d2 = (__nv_bfloat162*)(g_a2 + (base+r)*DIM + qoff);
        __nv_bfloat162 p;
        p.x=h0; p.y=h1; d1[0]=p;  p.x=h2; p.y=h3; d1[1]=p;
        p.x=l0; p.y=l1; d2[0]=p;  p.x=l2; p.y=l3; d2[1]=p;
    }
}
__global__ void k_split_feat(){
    int idx = blockIdx.x*blockDim.x + threadIdx.x;
    if (idx >= BALL*HID) return;
    int cell = idx >> 9, k = idx & 511;
    float v = g_h[(size_t)cell*(LTOK*DIM) + k];  // rows 0..3 of cell = bg rows
    bf16 h, l; split1(v, h, l);
    g_fa1[idx] = h; g_fa2[idx] = l;
}

// ---------------- mma.sync GEMM: C(128 x 128-block) = A @ B^T, bf16 2-split ------
// A1/A2: [M][Ktot] bf16 row-major (lda).  B1/B2: [N][Ktot] bf16 k-fast (= col-major K x N).
// D = A1B1 + A1B2 + A2B1 accumulated in fp32 registers via HMMA m16n8k16.
// CTA: 256 thr = 8 warps (4 M x 2 N). Warp tile 32x64. K staged in 64-chunks, stride AS=72.
__global__ __launch_bounds__(256, 2)
void k_gemm(const bf16* __restrict__ A1, const bf16* __restrict__ A2, int lda,
            const bf16* __restrict__ B1, const bf16* __restrict__ B2,
            const float* __restrict__ bias,
            float* __restrict__ Cout, int ldc,
            bf16* __restrict__ O1, bf16* __restrict__ O2, int ldo,
            int Ktot, int flags){
    extern __shared__ bf16 smem[];
    // word offsets (bf16 units): sA1=0, sA2=9216, sB1=18432, sB2=27648
    const int tid = threadIdx.x, lane = tid & 31, wid = tid >> 5;
    const int warpM = wid & 3, warpN = wid >> 2;
    const int row0 = blockIdx.x*128, cofs = blockIdx.y*128;
    const uint32_t sbase = s2u(smem);

    float acc[2][8][4];
    #pragma unroll
    for (int mt = 0; mt < 2; mt++)
        #pragma unroll
        for (int nt = 0; nt < 8; nt++)
            #pragma unroll
            for (int q = 0; q < 4; q++) acc[mt][nt][q] = 0.0f;

    // ldmatrix lane-address components
    const int rowA = lane & 15, kA8 = (lane >> 4) << 3;            // x4: A row, k-offset
    const int rowB = lane & 7,  kB8 = ((lane >> 3) & 1) << 3;      // x2: B row, k-offset
    const uint32_t aoff = sbase + (uint32_t)(((warpM*32 + rowA)*AS + kA8) * 2);
    const uint32_t boff = sbase + (uint32_t)(36864 + ((warpN*64 + rowB)*AS + kB8) * 2);

    for (int kc = 0; kc < Ktot; kc += 64){
        // stage 4 panels of 128 x 64 bf16 (8 x float4 per row)
        #pragma unroll
        for (int it = 0; it < 4; it++){
            int idx = it*256 + tid;            // 0..1023
            int r = idx >> 3, c8 = (idx & 7) << 3;
            int so = r*AS + c8;
            *(float4*)(smem + so)         = *(const float4*)(A1 + (size_t)(row0+r)*lda + kc + c8);
            *(float4*)(smem + 9216 + so)  = *(const float4*)(A2 + (size_t)(row0+r)*lda + kc + c8);
            *(float4*)(smem + 18432 + so) = *(const float4*)(B1 + (size_t)(cofs+r)*Ktot + kc + c8);
            *(float4*)(smem + 27648 + so) = *(const float4*)(B2 + (size_t)(cofs+r)*Ktot + kc + c8);
        }
        __syncthreads();

        #pragma unroll
        for (int k16 = 0; k16 < 64; k16 += 16){
            uint32_t a1f[2][4], a2f[2][4];
            #pragma unroll
            for (int mt = 0; mt < 2; mt++){
                uint32_t ad = aoff + (uint32_t)((mt*16*AS + k16) * 2);
                ldsm_x4(a1f[mt], ad);
                ldsm_x4(a2f[mt], ad + 18432);
            }
            #pragma unroll
            for (int nt = 0; nt < 8; nt++){
                uint32_t bd = boff + (uint32_t)((nt*8*AS + k16) * 2);
                uint32_t b1f[2], b2f[2];
                ldsm_x2(b1f, bd);
                ldsm_x2(b2f, bd + 18432);
                mma16816(acc[0][nt], a1f[0], b1f);
                mma16816(acc[1][nt], a1f[1], b1f);
                mma16816(acc[0][nt], a2f[0], b1f);
                mma16816(acc[1][nt], a2f[1], b1f);
                mma16816(acc[0][nt], a1f[0], b2f);
                mma16816(acc[1][nt], a1f[1], b2f);
            }
        }
        __syncthreads();
    }

    // ---- epilogue ----
    const int l4 = lane >> 2, l2 = (lane & 3) << 1;
    #pragma unroll
    for (int mt = 0; mt < 2; mt++){
        #pragma unroll
        for (int hh = 0; hh < 2; hh++){
            int rg = row0 + warpM*32 + mt*16 + l4 + hh*8;
            bool maskz = (flags & GF_MASK) && (g_counts[rg] == 0);
            #pragma unroll
            for (int nt = 0; nt < 8; nt++){
                int cg = cofs + warpN*64 + nt*8 + l2;
                float v0 = acc[mt][nt][hh*2+0] + bias[cg];
                float v1 = acc[mt][nt][hh*2+1] + bias[cg+1];
                if (flags & GF_GELU){ v0 = gelu_f(v0); v1 = gelu_f(v1); }
                if (flags & GF_ACCUM){
                    float2 old = *(const float2*)(Cout + (size_t)rg*ldc + cg);
                    v0 += old.x; v1 += old.y;
                }
                if (flags & GF_SPLIT){
                    bf16 ha,la,hb,lb;
                    split1(v0, ha, la); split1(v1, hb, lb);
                    __nv_bfloat162 p;
                    p.x=ha; p.y=hb; *(__nv_bfloat162*)(O1 + (size_t)rg*ldo + cg) = p;
                    p.x=la; p.y=lb; *(__nv_bfloat162*)(O2 + (size_t)rg*ldo + cg) = p;
                } else {
                    float2 ov = maskz ? make_float2(0.f, 0.f) : make_float2(v0, v1);
                    *(float2*)(Cout + (size_t)rg*ldc + cg) = ov;
                }
            }
        }
    }
}

// ---------------- launch ----------------
extern "C" void kernel_launch(void* const* d_in, const int* in_sizes, int n_in,
                              void* d_out, int out_size){
    const float* x    = (const float*)d_in[0];
    const int*   li   = (const int*)  d_in[1];
    const float* ob   = (const float*)d_in[2];
    const float* dw   = (const float*)d_in[3];
    const float* db   = (const float*)d_in[4];
    const float* ln1w = (const float*)d_in[5];
    const float* ln1b = (const float*)d_in[6];
    const float* wqkv = (const float*)d_in[7];
    const float* bqkv = (const float*)d_in[8];
    const float* wo   = (const float*)d_in[9];
    const float* bo   = (const float*)d_in[10];
    const float* ln2w = (const float*)d_in[11];
    const float* ln2b = (const float*)d_in[12];
    const float* w1   = (const float*)d_in[13];
    const float* b1   = (const float*)d_in[14];
    const float* w2   = (const float*)d_in[15];
    const float* b2   = (const float*)d_in[16];
    const float* pw   = (const float*)d_in[17];
    const float* pb   = (const float*)d_in[18];
    int n = in_sizes[0] / DIM;

    bf16 *a1, *a2, *h1a, *h1b, *fa1, *fa2;
    bf16 *wqT1, *wqT2, *woT1, *woT2, *w1T1, *w1T2, *w2T1, *w2T2, *pT1, *pT2;
    float *h, *qkv;
    cudaGetSymbolAddress((void**)&a1,  g_a1);  cudaGetSymbolAddress((void**)&a2,  g_a2);
    cudaGetSymbolAddress((void**)&h1a, g_h1a); cudaGetSymbolAddress((void**)&h1b, g_h1b);
    cudaGetSymbolAddress((void**)&fa1, g_fa1); cudaGetSymbolAddress((void**)&fa2, g_fa2);
    cudaGetSymbolAddress((void**)&wqT1, g_wqkvT1); cudaGetSymbolAddress((void**)&wqT2, g_wqkvT2);
    cudaGetSymbolAddress((void**)&woT1, g_woT1);   cudaGetSymbolAddress((void**)&woT2, g_woT2);
    cudaGetSymbolAddress((void**)&w1T1, g_w1T1);   cudaGetSymbolAddress((void**)&w1T2, g_w1T2);
    cudaGetSymbolAddress((void**)&w2T1, g_w2T1);   cudaGetSymbolAddress((void**)&w2T2, g_w2T2);
    cudaGetSymbolAddress((void**)&pT1, g_pT1);     cudaGetSymbolAddress((void**)&pT2, g_pT2);
    cudaGetSymbolAddress((void**)&h, g_h);         cudaGetSymbolAddress((void**)&qkv, g_qkv);

    const int SMEM_GB = 4 * 128 * AS * 2;   // 73728 B
    cudaFuncSetAttribute(k_gemm, cudaFuncAttributeMaxDynamicSharedMemorySize, SMEM_GB);

    // setup
    k_zero<<<(BALL+255)/256, 256>>>();
    k_scatter<<<(n+255)/256, 256>>>(li, n);
    k_bg<<<2, 256>>>(ob, dw, db);
    k_select<<<(BALL+255)/256, 256>>>();
    k_assemble<<<(NROW*DIM+255)/256, 256>>>(x);

    // weight transpose+split
    k_tsplit<<<dim3(64, DEPTH), 256>>>(wqkv, wqT1, wqT2, DIM, 3*DIM);
    k_tsplit<<<dim3(32, DEPTH), 256>>>(wo,   woT1, woT2, DIM, DIM);
    k_tsplit<<<dim3(64, DEPTH), 256>>>(w1,   w1T1, w1T2, DIM, HID);
    k_tsplit<<<dim3(64, DEPTH), 256>>>(w2,   w2T1, w2T2, HID, DIM);
    k_tsplit<<<dim3(256, 1),    256>>>(pw,   pT1,  pT2,  HID, CLV);

    const int MB = NROW/128;   // 720
    for (int L = 0; L < DEPTH; L++){
        k_ln_split<<<NROW/8, 256>>>(ln1w + L*DIM, ln1b + L*DIM);
        k_gemm<<<dim3(MB,3), 256, SMEM_GB>>>(a1, a2, DIM,
            wqT1 + (size_t)L*3*DIM*DIM, wqT2 + (size_t)L*3*DIM*DIM,
            bqkv + L*3*DIM, qkv, 3*DIM, (bf16*)0, (bf16*)0, 0, DIM, 0);
        k_attn<<<BALL/8, 256>>>();
        k_gemm<<<dim3(MB,1), 256, SMEM_GB>>>(a1, a2, DIM,
            woT1 + (size_t)L*DIM*DIM, woT2 + (size_t)L*DIM*DIM,
            bo + L*DIM, h, DIM, (bf16*)0, (bf16*)0, 0, DIM, GF_ACCUM);
        k_ln_split<<<NROW/8, 256>>>(ln2w + L*DIM, ln2b + L*DIM);
        k_gemm<<<dim3(MB,4), 256, SMEM_GB>>>(a1, a2, DIM,
            w1T1 + (size_t)L*HID*DIM, w1T2 + (size_t)L*HID*DIM,
            b1 + L*HID, (float*)0, 0, h1a, h1b, HID, DIM, GF_GELU|GF_SPLIT);
        k_gemm<<<dim3(MB,1), 256, SMEM_GB>>>(h1a, h1b, HID,
            w2T1 + (size_t)L*DIM*HID, w2T2 + (size_t)L*DIM*HID,
            b2 + L*DIM, h, DIM, (bf16*)0, (bf16*)0, 0, HID, GF_ACCUM);
    }

    k_split_feat<<<(BALL*HID+255)/256, 256>>>();
    k_gemm<<<dim3(BALL/128, CLV/128), 256, SMEM_GB>>>(fa1, fa2, HID,
        pT1, pT2, pb, (float*)d_out, CLV, (bf16*)0, (bf16*)0, 0, HID, GF_MASK);
}

// round 8
// speedup vs baseline: 2.2289x; 1.0377x over previous
#include <cuda_runtime.h>
#include <cuda_bf16.h>
#include <cstdint>
#include <math.h>

#define DD     5
#define HGRID  24
#define WGRID  48
#define CLV    1024
#define NB     4
#define DIM    128
#define LMAX   12
#define DEPTH  6
#define LTOK   16
#define BALL   (DD*HGRID*WGRID)   // 5760
#define NROW   (BALL*LTOK)        // 92160
#define CAP    64
#define HID    512
#define AS     72                 // smem row stride in bf16 (144B: conflict-free ldmatrix)
#define STGB   73728              // bytes per pipeline stage (4 panels x 18432)

typedef __nv_bfloat16 bf16;

// ---------------- device scratch ----------------
__device__ int   g_counts[BALL];
__device__ int   g_list[BALL*CAP];
__device__ int   g_sel[BALL*LMAX];
__device__ int   g_m[BALL];
__device__ float g_bgp[NB*DIM];
__device__ float g_h[NROW*DIM];
__device__ float g_qkv[NROW*3*DIM];
__device__ bf16  g_a1[NROW*DIM],  g_a2[NROW*DIM];
__device__ bf16  g_h1a[NROW*HID], g_h1b[NROW*HID];
__device__ bf16  g_fa1[BALL*HID], g_fa2[BALL*HID];
// transposed + split weights: [n][k] k-fast
__device__ bf16  g_wqkvT1[DEPTH*3*DIM*DIM], g_wqkvT2[DEPTH*3*DIM*DIM];
__device__ bf16  g_woT1[DEPTH*DIM*DIM],     g_woT2[DEPTH*DIM*DIM];
__device__ bf16  g_w1T1[DEPTH*HID*DIM],     g_w1T2[DEPTH*HID*DIM];
__device__ bf16  g_w2T1[DEPTH*DIM*HID],     g_w2T2[DEPTH*DIM*HID];
__device__ bf16  g_pT1[CLV*HID],            g_pT2[CLV*HID];

// ---------------- helpers ----------------
__device__ __forceinline__ uint32_t s2u(const void* p){
    uint32_t a;
    asm("{ .reg .u64 t; cvta.to.shared.u64 t, %1; cvt.u32.u64 %0, t; }" : "=r"(a) : "l"(p));
    return a;
}
__device__ __forceinline__ void cp16(uint32_t dst, const void* src){
    asm volatile("cp.async.cg.shared.global [%0], [%1], 16;" :: "r"(dst), "l"(src));
}
#define CPCOMMIT() asm volatile("cp.async.commit_group;" ::: "memory")
__device__ __forceinline__ void ldsm_x4(uint32_t* d, uint32_t addr){
    asm volatile("ldmatrix.sync.aligned.m8n8.x4.shared.b16 {%0,%1,%2,%3}, [%4];"
        : "=r"(d[0]),"=r"(d[1]),"=r"(d[2]),"=r"(d[3]) : "r"(addr));
}
__device__ __forceinline__ void ldsm_x2(uint32_t* d, uint32_t addr){
    asm volatile("ldmatrix.sync.aligned.m8n8.x2.shared.b16 {%0,%1}, [%2];"
        : "=r"(d[0]),"=r"(d[1]) : "r"(addr));
}
__device__ __forceinline__ void mma16816(float* c, const uint32_t* a, const uint32_t* b){
    asm volatile("mma.sync.aligned.m16n8k16.row.col.f32.bf16.bf16.f32 "
        "{%0,%1,%2,%3}, {%4,%5,%6,%7}, {%8,%9}, {%0,%1,%2,%3};"
        : "+f"(c[0]),"+f"(c[1]),"+f"(c[2]),"+f"(c[3])
        : "r"(a[0]),"r"(a[1]),"r"(a[2]),"r"(a[3]), "r"(b[0]),"r"(b[1]));
}
__device__ __forceinline__ float gelu_f(float x){
    float x3 = x*x*x;
    return 0.5f*x*(1.0f + tanhf(0.7978845608028654f*(x + 0.044715f*x3)));
}
__device__ __forceinline__ void split1(float v, bf16 &h, bf16 &l){
    h = __float2bfloat16(v);
    l = __float2bfloat16(v - __bfloat162float(h));
}

#define GF_ACCUM 1
#define GF_GELU  2
#define GF_SPLIT 4
#define GF_MASK  8
#define GF_LN    16

// ---------------- setup kernels ----------------
__global__ void k_zero(){
    int i = blockIdx.x*blockDim.x + threadIdx.x;
    if (i < BALL) g_counts[i] = 0;
}
__global__ void k_scatter(const int* __restrict__ li, int n){
    int i = blockIdx.x*blockDim.x + threadIdx.x;
    if (i >= n) return;
    int flat = li[3*i]*(HGRID*WGRID) + li[3*i+1]*WGRID + li[3*i+2];
    int slot = atomicAdd(&g_counts[flat], 1);
    if (slot < CAP) g_list[flat*CAP + slot] = i;
}
__global__ void k_bg(const float* __restrict__ ob, const float* __restrict__ dw,
                     const float* __restrict__ db){
    int c = blockIdx.x*blockDim.x + threadIdx.x;
    if (c >= NB*DIM) return;
    float s = 0.0f;
    for (int m = 0; m < NB; m++){
        const float* bg = ob + m*DIM;
        float t = 0.0f;
        for (int k = 0; k < DIM; k++) t += bg[k] * dw[k*(NB*DIM) + c];
        s += t;
    }
    g_bgp[c] = ob[c] + s*(1.0f/NB) + db[c];
}
__global__ void k_select(){
    int cell = blockIdx.x*blockDim.x + threadIdx.x;
    if (cell >= BALL) return;
    int cnt = g_counts[cell];
    int avail = min(cnt, CAP);
    int m = min(cnt, LMAX);
    g_m[cell] = m;
    if (cnt <= LMAX){
        for (int j = 0; j < m; j++) g_sel[cell*LMAX + j] = g_list[cell*CAP + j];
    } else {
        int tmp[CAP];
        for (int j = 0; j < avail; j++) tmp[j] = g_list[cell*CAP + j];
        for (int a = 0; a < m; a++){
            int best = a;
            for (int b = a+1; b < avail; b++) if (tmp[b] < tmp[best]) best = b;
            int t = tmp[best]; tmp[best] = tmp[a]; tmp[a] = t;
            g_sel[cell*LMAX + a] = t;
        }
    }
}
__global__ void k_assemble(const float* __restrict__ x){
    int idx = blockIdx.x*blockDim.x + threadIdx.x;
    if (idx >= NROW*DIM) return;
    int row = idx >> 7, d = idx & 127;
    int cell = row >> 4, lr = row & 15;
    float v;
    if (lr < NB) v = g_bgp[lr*DIM + d];
    else {
        int j = lr - NB;
        v = (j < g_m[cell]) ? x[(size_t)g_sel[cell*LMAX + j]*DIM + d] : 0.0f;
    }
    g_h[idx] = v;
}
__global__ void k_tsplit(const float* __restrict__ W, bf16* __restrict__ T1,
                         bf16* __restrict__ T2, int K, int N){
    size_t off = (size_t)blockIdx.y * K * N;
    W += off; T1 += off; T2 += off;
    int tot = K*N;
    for (int idx = blockIdx.x*blockDim.x + threadIdx.x; idx < tot;
         idx += gridDim.x*blockDim.x){
        int n = idx / K, k = idx - n*K;
        float v = W[(size_t)k*N + n];
        bf16 h, l; split1(v, h, l);
        T1[idx] = h; T2[idx] = l;
    }
}
// LayerNorm + bf16 split (used once, before layer 0)
__global__ void k_ln_split(const float* __restrict__ w, const float* __restrict__ b){
    int warp = threadIdx.x >> 5, lane = threadIdx.x & 31;
    int row = blockIdx.x*8 + warp;
    const float* src = g_h + (size_t)row*DIM;
    float4 v = *(const float4*)(src + lane*4);
    float s  = v.x+v.y+v.z+v.w;
    float ss = v.x*v.x+v.y*v.y+v.z*v.z+v.w*v.w;
    #pragma unroll
    for (int o = 16; o; o >>= 1){
        s  += __shfl_xor_sync(0xffffffffu, s,  o);
        ss += __shfl_xor_sync(0xffffffffu, ss, o);
    }
    float mean = s*(1.0f/DIM);
    float var  = ss*(1.0f/DIM) - mean*mean;
    float rstd = rsqrtf(var + 1e-5f);
    float4 wv = *(const float4*)(w + lane*4);
    float4 bv = *(const float4*)(b + lane*4);
    float n0 = (v.x-mean)*rstd*wv.x + bv.x;
    float n1 = (v.y-mean)*rstd*wv.y + bv.y;
    float n2 = (v.z-mean)*rstd*wv.z + bv.z;
    float n3 = (v.w-mean)*rstd*wv.w + bv.w;
    bf16 h0,l0,h1,l1,h2,l2,h3,l3;
    split1(n0,h0,l0); split1(n1,h1,l1); split1(n2,h2,l2); split1(n3,h3,l3);
    __nv_bfloat162* d1 = (__nv_bfloat162*)(g_a1 + (size_t)row*DIM + lane*4);
    __nv_bfloat162* d2 = (__nv_bfloat162*)(g_a2 + (size_t)row*DIM + lane*4);
    __nv_bfloat162 p;
    p.x=h0; p.y=h1; d1[0]=p;  p.x=h2; p.y=h3; d1[1]=p;
    p.x=l0; p.y=l1; d2[0]=p;  p.x=l2; p.y=l3; d2[1]=p;
}
// attention
__global__ void k_attn(){
    int warp = threadIdx.x >> 5, lane = threadIdx.x & 31;
    int cell = blockIdx.x*8 + warp;
    int qoff = ((lane >> 3) << 5) + ((lane & 7) << 2);
    const float scale = 0.17677669529663687f;
    size_t base = (size_t)cell*LTOK;
    for (int r = 0; r < LTOK; r++){
        float4 q4 = *(const float4*)(g_qkv + (base+r)*384 + qoff);
        float sc[LTOK]; float mx = -1e30f;
        #pragma unroll
        for (int j = 0; j < LTOK; j++){
            float4 k4 = *(const float4*)(g_qkv + (base+j)*384 + 128 + qoff);
            float sdot = q4.x*k4.x + q4.y*k4.y + q4.z*k4.z + q4.w*k4.w;
            sdot += __shfl_xor_sync(0xffffffffu, sdot, 1);
            sdot += __shfl_xor_sync(0xffffffffu, sdot, 2);
            sdot += __shfl_xor_sync(0xffffffffu, sdot, 4);
            sdot *= scale;
            sc[j] = sdot; mx = fmaxf(mx, sdot);
        }
        float den = 0.0f;
        #pragma unroll
        for (int j = 0; j < LTOK; j++){ sc[j] = __expf(sc[j]-mx); den += sc[j]; }
        float inv = __fdividef(1.0f, den);
        float4 o = make_float4(0.f,0.f,0.f,0.f);
        #pragma unroll
        for (int j = 0; j < LTOK; j++){
            float p = sc[j]*inv;
            float4 v4 = *(const float4*)(g_qkv + (base+j)*384 + 256 + qoff);
            o.x += p*v4.x; o.y += p*v4.y; o.z += p*v4.z; o.w += p*v4.w;
        }
        bf16 h0,l0,h1,l1,h2,l2,h3,l3;
        split1(o.x,h0,l0); split1(o.y,h1,l1); split1(o.z,h2,l2); split1(o.w,h3,l3);
        __nv_bfloat162* d1 = (__nv_bfloat162*)(g_a1 + (base+r)*DIM + qoff);
        __nv_bfloat162* d2 = (__nv_bfloat162*)(g_a2 + (base+r)*DIM + qoff);
        __nv_bfloat162 p;
        p.x=h0; p.y=h1; d1[0]=p;  p.x=h2; p.y=h3; d1[1]=p;
        p.x=l0; p.y=l1; d2[0]=p;  p.x=l2; p.y=l3; d2[1]=p;
    }
}
__global__ void k_split_feat(){
    int idx = blockIdx.x*blockDim.x + threadIdx.x;
    if (idx >= BALL*HID) return;
    int cell = idx >> 9, k = idx & 511;
    float v = g_h[(size_t)cell*(LTOK*DIM) + k];
    bf16 h, l; split1(v, h, l);
    g_fa1[idx] = h; g_fa2[idx] = l;
}

// ---------------- mma.sync GEMM, cp.async 2-stage, optional fused LN epilogue -----
// A1/A2: [M][Ktot] bf16 row-major.  B1/B2: [N][Ktot] bf16 k-fast.
// D = A1B1 + A1B2 + A2B1 (fp32 regs).  GF_LN requires ny==1 (full 128-col rows/CTA).
__global__ __launch_bounds__(256, 1)
void k_gemm(const bf16* __restrict__ A1, const bf16* __restrict__ A2, int lda,
            const bf16* __restrict__ B1, const bf16* __restrict__ B2,
            const float* __restrict__ bias,
            float* __restrict__ Cout, int ldc,
            bf16* __restrict__ O1, bf16* __restrict__ O2, int ldo,
            const float* __restrict__ lnw, const float* __restrict__ lnb,
            int Ktot, int flags){
    extern __shared__ bf16 smem[];
    float2* red = (float2*)(smem + STGB);      // element offset = 2 stages of bf16
    const int tid = threadIdx.x, lane = tid & 31, wid = tid >> 5;
    const int warpM = wid & 3, warpN = wid >> 2;
    const int row0 = blockIdx.x*128, cofs = blockIdx.y*128;
    const uint32_t sbase = s2u(smem);

    float acc[2][8][4];
    #pragma unroll
    for (int mt = 0; mt < 2; mt++)
        #pragma unroll
        for (int nt = 0; nt < 8; nt++)
            #pragma unroll
            for (int q = 0; q < 4; q++) acc[mt][nt][q] = 0.0f;

    // ldmatrix lane-address components (byte offsets within a stage)
    const int rowA = lane & 15, kA8 = (lane >> 4) << 3;
    const int rowB = lane & 7,  kB8 = ((lane >> 3) & 1) << 3;
    const uint32_t aoff0 = (uint32_t)(((warpM*32 + rowA)*AS + kA8) * 2);
    const uint32_t boff0 = (uint32_t)(36864 + ((warpN*64 + rowB)*AS + kB8) * 2);

    // cp.async chunk loader: 16 cp16 per thread per chunk
    auto load_chunk = [&](int kc, int st){
        uint32_t sb0 = sbase + (uint32_t)st*STGB;
        #pragma unroll
        for (int it = 0; it < 4; it++){
            int idx = it*256 + tid;
            int r = idx >> 3, c8 = (idx & 7) << 3;
            uint32_t so = (uint32_t)((r*AS + c8) * 2);
            cp16(sb0 + so,         A1 + (size_t)(row0+r)*lda + kc + c8);
            cp16(sb0 + 18432 + so, A2 + (size_t)(row0+r)*lda + kc + c8);
            cp16(sb0 + 36864 + so, B1 + (size_t)(cofs+r)*Ktot + kc + c8);
            cp16(sb0 + 55296 + so, B2 + (size_t)(cofs+r)*Ktot + kc + c8);
        }
    };

    load_chunk(0, 0);
    CPCOMMIT();
    int st = 0;
    for (int kc = 0; kc < Ktot; kc += 64){
        bool more = (kc + 64 < Ktot);
        if (more){ load_chunk(kc + 64, st ^ 1); CPCOMMIT(); }
        if (more) asm volatile("cp.async.wait_group 1;" ::: "memory");
        else      asm volatile("cp.async.wait_group 0;" ::: "memory");
        __syncthreads();

        const uint32_t sadd = sbase + (uint32_t)st*STGB;
        const uint32_t aoff = sadd + aoff0, boff = sadd + boff0;
        #pragma unroll
        for (int k16 = 0; k16 < 64; k16 += 16){
            uint32_t a1f[2][4], a2f[2][4];
            #pragma unroll
            for (int mt = 0; mt < 2; mt++){
                uint32_t ad = aoff + (uint32_t)((mt*16*AS + k16) * 2);
                ldsm_x4(a1f[mt], ad);
                ldsm_x4(a2f[mt], ad + 18432);
            }
            #pragma unroll
            for (int nt = 0; nt < 8; nt++){
                uint32_t bd = boff + (uint32_t)((nt*8*AS + k16) * 2);
                uint32_t b1f[2], b2f[2];
                ldsm_x2(b1f, bd);
                ldsm_x2(b2f, bd + 18432);
                mma16816(acc[0][nt], a1f[0], b1f);
                mma16816(acc[1][nt], a1f[1], b1f);
                mma16816(acc[0][nt], a2f[0], b1f);
                mma16816(acc[1][nt], a2f[1], b1f);
                mma16816(acc[0][nt], a1f[0], b2f);
                mma16816(acc[1][nt], a1f[1], b2f);
            }
        }
        __syncthreads();
        st ^= 1;
    }

    const int l4 = lane >> 2, l2 = (lane & 3) << 1;

    if (flags & GF_LN){
        // pass 1: v = acc + bias + old_h; write g_h; per-row partial sums
        #pragma unroll
        for (int mt = 0; mt < 2; mt++){
            #pragma unroll
            for (int hh = 0; hh < 2; hh++){
                int rl = warpM*32 + mt*16 + hh*8 + l4;
                int rg = row0 + rl;
                float s = 0.0f, ss = 0.0f;
                #pragma unroll
                for (int nt = 0; nt < 8; nt++){
                    int cg = warpN*64 + nt*8 + l2;
                    float2 old = *(const float2*)(Cout + (size_t)rg*ldc + cg);
                    float v0 = acc[mt][nt][hh*2+0] + bias[cg]   + old.x;
                    float v1 = acc[mt][nt][hh*2+1] + bias[cg+1] + old.y;
                    acc[mt][nt][hh*2+0] = v0;
                    acc[mt][nt][hh*2+1] = v1;
                    *(float2*)(Cout + (size_t)rg*ldc + cg) = make_float2(v0, v1);
                    s += v0 + v1; ss += v0*v0 + v1*v1;
                }
                s  += __shfl_xor_sync(0xffffffffu, s,  1);
                ss += __shfl_xor_sync(0xffffffffu, ss, 1);
                s  += __shfl_xor_sync(0xffffffffu, s,  2);
                ss += __shfl_xor_sync(0xffffffffu, ss, 2);
                if ((lane & 3) == 0) red[rl*2 + warpN] = make_float2(s, ss);
            }
        }
        __syncthreads();
        // pass 2: normalize + split
        #pragma unroll
        for (int mt = 0; mt < 2; mt++){
            #pragma unroll
            for (int hh = 0; hh < 2; hh++){
                int rl = warpM*32 + mt*16 + hh*8 + l4;
                int rg = row0 + rl;
                float2 r0 = red[rl*2 + 0], r1 = red[rl*2 + 1];
                float mean = (r0.x + r1.x) * (1.0f/DIM);
                float var  = (r0.y + r1.y) * (1.0f/DIM) - mean*mean;
                float rstd = rsqrtf(var + 1e-5f);
                #pragma unroll
                for (int nt = 0; nt < 8; nt++){
                    int cg = warpN*64 + nt*8 + l2;
                    float n0 = (acc[mt][nt][hh*2+0] - mean)*rstd*lnw[cg]   + lnb[cg];
                    float n1 = (acc[mt][nt][hh*2+1] - mean)*rstd*lnw[cg+1] + lnb[cg+1];
                    bf16 ha,la,hb,lb;
                    split1(n0, ha, la); split1(n1, hb, lb);
                    __nv_bfloat162 p;
                    p.x=ha; p.y=hb; *(__nv_bfloat162*)(O1 + (size_t)rg*ldo + cg) = p;
                    p.x=la; p.y=lb; *(__nv_bfloat162*)(O2 + (size_t)rg*ldo + cg) = p;
                }
            }
        }
        return;
    }

    // ---- standard epilogue ----
    #pragma unroll
    for (int mt = 0; mt < 2; mt++){
        #pragma unroll
        for (int hh = 0; hh < 2; hh++){
            int rg = row0 + warpM*32 + mt*16 + l4 + hh*8;
            bool maskz = (flags & GF_MASK) && (g_counts[rg] == 0);
            #pragma unroll
            for (int nt = 0; nt < 8; nt++){
                int cg = cofs + warpN*64 + nt*8 + l2;
                float v0 = acc[mt][nt][hh*2+0] + bias[cg];
                float v1 = acc[mt][nt][hh*2+1] + bias[cg+1];
                if (flags & GF_GELU){ v0 = gelu_f(v0); v1 = gelu_f(v1); }
                if (flags & GF_ACCUM){
                    float2 old = *(const float2*)(Cout + (size_t)rg*ldc + cg);
                    v0 += old.x; v1 += old.y;
                }
                if (flags & GF_SPLIT){
                    bf16 ha,la,hb,lb;
                    split1(v0, ha, la); split1(v1, hb, lb);
                    __nv_bfloat162 p;
                    p.x=ha; p.y=hb; *(__nv_bfloat162*)(O1 + (size_t)rg*ldo + cg) = p;
                    p.x=la; p.y=lb; *(__nv_bfloat162*)(O2 + (size_t)rg*ldo + cg) = p;
                } else {
                    float2 ov = maskz ? make_float2(0.f, 0.f) : make_float2(v0, v1);
                    *(float2*)(Cout + (size_t)rg*ldc + cg) = ov;
                }
            }
        }
    }
}

// ---------------- launch ----------------
extern "C" void kernel_launch(void* const* d_in, const int* in_sizes, int n_in,
                              void* d_out, int out_size){
    const float* x    = (const float*)d_in[0];
    const int*   li   = (const int*)  d_in[1];
    const float* ob   = (const float*)d_in[2];
    const float* dw   = (const float*)d_in[3];
    const float* db   = (const float*)d_in[4];
    const float* ln1w = (const float*)d_in[5];
    const float* ln1b = (const float*)d_in[6];
    const float* wqkv = (const float*)d_in[7];
    const float* bqkv = (const float*)d_in[8];
    const float* wo   = (const float*)d_in[9];
    const float* bo   = (const float*)d_in[10];
    const float* ln2w = (const float*)d_in[11];
    const float* ln2b = (const float*)d_in[12];
    const float* w1   = (const float*)d_in[13];
    const float* b1   = (const float*)d_in[14];
    const float* w2   = (const float*)d_in[15];
    const float* b2   = (const float*)d_in[16];
    const float* pw   = (const float*)d_in[17];
    const float* pb   = (const float*)d_in[18];
    int n = in_sizes[0] / DIM;

    bf16 *a1, *a2, *h1a, *h1b, *fa1, *fa2;
    bf16 *wqT1, *wqT2, *woT1, *woT2, *w1T1, *w1T2, *w2T1, *w2T2, *pT1, *pT2;
    float *h, *qkv;
    cudaGetSymbolAddress((void**)&a1,  g_a1);  cudaGetSymbolAddress((void**)&a2,  g_a2);
    cudaGetSymbolAddress((void**)&h1a, g_h1a); cudaGetSymbolAddress((void**)&h1b, g_h1b);
    cudaGetSymbolAddress((void**)&fa1, g_fa1); cudaGetSymbolAddress((void**)&fa2, g_fa2);
    cudaGetSymbolAddress((void**)&wqT1, g_wqkvT1); cudaGetSymbolAddress((void**)&wqT2, g_wqkvT2);
    cudaGetSymbolAddress((void**)&woT1, g_woT1);   cudaGetSymbolAddress((void**)&woT2, g_woT2);
    cudaGetSymbolAddress((void**)&w1T1, g_w1T1);   cudaGetSymbolAddress((void**)&w1T2, g_w1T2);
    cudaGetSymbolAddress((void**)&w2T1, g_w2T1);   cudaGetSymbolAddress((void**)&w2T2, g_w2T2);
    cudaGetSymbolAddress((void**)&pT1, g_pT1);     cudaGetSymbolAddress((void**)&pT2, g_pT2);
    cudaGetSymbolAddress((void**)&h, g_h);         cudaGetSymbolAddress((void**)&qkv, g_qkv);

    const int SMEM_GB = 2*STGB + 2048;   // 149504 B
    cudaFuncSetAttribute(k_gemm, cudaFuncAttributeMaxDynamicSharedMemorySize, SMEM_GB);

    // setup
    k_zero<<<(BALL+255)/256, 256>>>();
    k_scatter<<<(n+255)/256, 256>>>(li, n);
    k_bg<<<2, 256>>>(ob, dw, db);
    k_select<<<(BALL+255)/256, 256>>>();
    k_assemble<<<(NROW*DIM+255)/256, 256>>>(x);

    // weight transpose+split
    k_tsplit<<<dim3(64, DEPTH), 256>>>(wqkv, wqT1, wqT2, DIM, 3*DIM);
    k_tsplit<<<dim3(32, DEPTH), 256>>>(wo,   woT1, woT2, DIM, DIM);
    k_tsplit<<<dim3(64, DEPTH), 256>>>(w1,   w1T1, w1T2, DIM, HID);
    k_tsplit<<<dim3(64, DEPTH), 256>>>(w2,   w2T1, w2T2, HID, DIM);
    k_tsplit<<<dim3(256, 1),    256>>>(pw,   pT1,  pT2,  HID, CLV);

    // initial LN (layer 0); later LNs are fused into wo/w2 epilogues
    k_ln_split<<<NROW/8, 256>>>(ln1w, ln1b);

    const int MB = NROW/128;   // 720
    for (int L = 0; L < DEPTH; L++){
        k_gemm<<<dim3(MB,3), 256, SMEM_GB>>>(a1, a2, DIM,
            wqT1 + (size_t)L*3*DIM*DIM, wqT2 + (size_t)L*3*DIM*DIM,
            bqkv + L*3*DIM, qkv, 3*DIM, (bf16*)0, (bf16*)0, 0,
            (float*)0, (float*)0, DIM, 0);
        k_attn<<<BALL/8, 256>>>();
        // wo + residual + fused ln2 -> a1/a2
        k_gemm<<<dim3(MB,1), 256, SMEM_GB>>>(a1, a2, DIM,
            woT1 + (size_t)L*DIM*DIM, woT2 + (size_t)L*DIM*DIM,
            bo + L*DIM, h, DIM, a1, a2, DIM,
            ln2w + L*DIM, ln2b + L*DIM, DIM, GF_ACCUM|GF_LN);
        k_gemm<<<dim3(MB,4), 256, SMEM_GB>>>(a1, a2, DIM,
            w1T1 + (size_t)L*HID*DIM, w1T2 + (size_t)L*HID*DIM,
            b1 + L*HID, (float*)0, 0, h1a, h1b, HID,
            (float*)0, (float*)0, DIM, GF_GELU|GF_SPLIT);
        if (L < DEPTH-1){
            // w2 + residual + fused ln1(L+1) -> a1/a2
            k_gemm<<<dim3(MB,1), 256, SMEM_GB>>>(h1a, h1b, HID,
                w2T1 + (size_t)L*DIM*HID, w2T2 + (size_t)L*DIM*HID,
                b2 + L*DIM, h, DIM, a1, a2, DIM,
                ln1w + (L+1)*DIM, ln1b + (L+1)*DIM, HID, GF_ACCUM|GF_LN);
        } else {
            k_gemm<<<dim3(MB,1), 256, SMEM_GB>>>(h1a, h1b, HID,
                w2T1 + (size_t)L*DIM*HID, w2T2 + (size_t)L*DIM*HID,
                b2 + L*DIM, h, DIM, (bf16*)0, (bf16*)0, 0,
                (float*)0, (float*)0, HID, GF_ACCUM);
        }
    }

    k_split_feat<<<(BALL*HID+255)/256, 256>>>();
    k_gemm<<<dim3(BALL/128, CLV/128), 256, SMEM_GB>>>(fa1, fa2, HID,
        pT1, pT2, pb, (float*)d_out, CLV, (bf16*)0, (bf16*)0, 0,
        (float*)0, (float*)0, HID, GF_MASK);
}

// round 10
// speedup vs baseline: 2.3055x; 1.0344x over previous
#include <cuda_runtime.h>
#include <cuda_bf16.h>
#include <cstdint>
#include <math.h>

#define DD     5
#define HGRID  24
#define WGRID  48
#define CLV    1024
#define NB     4
#define DIM    128
#define LMAX   12
#define DEPTH  6
#define LTOK   16
#define BALL   (DD*HGRID*WGRID)   // 5760
#define NROW   (BALL*LTOK)        // 92160
#define CAP    64
#define HID    512
#define AS     72                 // smem row stride in bf16 (144B: conflict-free ldmatrix)
#define STGB   73728              // bytes per stage (4 panels x 18432)

typedef __nv_bfloat16 bf16;

// ---------------- device scratch ----------------
__device__ int   g_counts[BALL];
__device__ int   g_list[BALL*CAP];
__device__ int   g_sel[BALL*LMAX];
__device__ int   g_m[BALL];
__device__ float g_bgp[NB*DIM];
__device__ float g_h[NROW*DIM];
__device__ float g_qkv[NROW*3*DIM];
__device__ bf16  g_a1[NROW*DIM],  g_a2[NROW*DIM];
__device__ bf16  g_h1a[NROW*HID], g_h1b[NROW*HID];
__device__ bf16  g_fa1[BALL*HID], g_fa2[BALL*HID];
// transposed + split weights: [n][k] k-fast
__device__ bf16  g_wqkvT1[DEPTH*3*DIM*DIM], g_wqkvT2[DEPTH*3*DIM*DIM];
__device__ bf16  g_woT1[DEPTH*DIM*DIM],     g_woT2[DEPTH*DIM*DIM];
__device__ bf16  g_w1T1[DEPTH*HID*DIM],     g_w1T2[DEPTH*HID*DIM];
__device__ bf16  g_w2T1[DEPTH*DIM*HID],     g_w2T2[DEPTH*DIM*HID];
__device__ bf16  g_pT1[CLV*HID],            g_pT2[CLV*HID];

// ---------------- helpers ----------------
__device__ __forceinline__ uint32_t s2u(const void* p){
    uint32_t a;
    asm("{ .reg .u64 t; cvta.to.shared.u64 t, %1; cvt.u32.u64 %0, t; }" : "=r"(a) : "l"(p));
    return a;
}
__device__ __forceinline__ void cp16(uint32_t dst, const void* src){
    asm volatile("cp.async.cg.shared.global [%0], [%1], 16;" :: "r"(dst), "l"(src));
}
#define CPCOMMIT() asm volatile("cp.async.commit_group;" ::: "memory")
__device__ __forceinline__ void ldsm_x4(uint32_t* d, uint32_t addr){
    asm volatile("ldmatrix.sync.aligned.m8n8.x4.shared.b16 {%0,%1,%2,%3}, [%4];"
        : "=r"(d[0]),"=r"(d[1]),"=r"(d[2]),"=r"(d[3]) : "r"(addr));
}
__device__ __forceinline__ void ldsm_x2(uint32_t* d, uint32_t addr){
    asm volatile("ldmatrix.sync.aligned.m8n8.x2.shared.b16 {%0,%1}, [%2];"
        : "=r"(d[0]),"=r"(d[1]) : "r"(addr));
}
__device__ __forceinline__ void mma16816(float* c, const uint32_t* a, const uint32_t* b){
    asm volatile("mma.sync.aligned.m16n8k16.row.col.f32.bf16.bf16.f32 "
        "{%0,%1,%2,%3}, {%4,%5,%6,%7}, {%8,%9}, {%0,%1,%2,%3};"
        : "+f"(c[0]),"+f"(c[1]),"+f"(c[2]),"+f"(c[3])
        : "r"(a[0]),"r"(a[1]),"r"(a[2]),"r"(a[3]), "r"(b[0]),"r"(b[1]));
}
__device__ __forceinline__ float gelu_f(float x){
    float x3 = x*x*x;
    return 0.5f*x*(1.0f + tanhf(0.7978845608028654f*(x + 0.044715f*x3)));
}
__device__ __forceinline__ void split1(float v, bf16 &h, bf16 &l){
    h = __float2bfloat16(v);
    l = __float2bfloat16(v - __bfloat162float(h));
}

#define GF_ACCUM 1
#define GF_GELU  2
#define GF_SPLIT 4
#define GF_MASK  8
#define GF_LN    16

// ---------------- setup kernels ----------------
__global__ void k_zero(){
    int i = blockIdx.x*blockDim.x + threadIdx.x;
    if (i < BALL) g_counts[i] = 0;
}
__global__ void k_scatter(const int* __restrict__ li, int n){
    int i = blockIdx.x*blockDim.x + threadIdx.x;
    if (i >= n) return;
    int flat = li[3*i]*(HGRID*WGRID) + li[3*i+1]*WGRID + li[3*i+2];
    int slot = atomicAdd(&g_counts[flat], 1);
    if (slot < CAP) g_list[flat*CAP + slot] = i;
}
__global__ void k_bg(const float* __restrict__ ob, const float* __restrict__ dw,
                     const float* __restrict__ db){
    int c = blockIdx.x*blockDim.x + threadIdx.x;
    if (c >= NB*DIM) return;
    float s = 0.0f;
    for (int m = 0; m < NB; m++){
        const float* bg = ob + m*DIM;
        float t = 0.0f;
        for (int k = 0; k < DIM; k++) t += bg[k] * dw[k*(NB*DIM) + c];
        s += t;
    }
    g_bgp[c] = ob[c] + s*(1.0f/NB) + db[c];
}
__global__ void k_select(){
    int cell = blockIdx.x*blockDim.x + threadIdx.x;
    if (cell >= BALL) return;
    int cnt = g_counts[cell];
    int avail = min(cnt, CAP);
    int m = min(cnt, LMAX);
    g_m[cell] = m;
    if (cnt <= LMAX){
        for (int j = 0; j < m; j++) g_sel[cell*LMAX + j] = g_list[cell*CAP + j];
    } else {
        int tmp[CAP];
        for (int j = 0; j < avail; j++) tmp[j] = g_list[cell*CAP + j];
        for (int a = 0; a < m; a++){
            int best = a;
            for (int b = a+1; b < avail; b++) if (tmp[b] < tmp[best]) best = b;
            int t = tmp[best]; tmp[best] = tmp[a]; tmp[a] = t;
            g_sel[cell*LMAX + a] = t;
        }
    }
}
__global__ void k_assemble(const float* __restrict__ x){
    int idx = blockIdx.x*blockDim.x + threadIdx.x;
    if (idx >= NROW*DIM) return;
    int row = idx >> 7, d = idx & 127;
    int cell = row >> 4, lr = row & 15;
    float v;
    if (lr < NB) v = g_bgp[lr*DIM + d];
    else {
        int j = lr - NB;
        v = (j < g_m[cell]) ? x[(size_t)g_sel[cell*LMAX + j]*DIM + d] : 0.0f;
    }
    g_h[idx] = v;
}
__global__ void k_tsplit(const float* __restrict__ W, bf16* __restrict__ T1,
                         bf16* __restrict__ T2, int K, int N){
    size_t off = (size_t)blockIdx.y * K * N;
    W += off; T1 += off; T2 += off;
    int tot = K*N;
    for (int idx = blockIdx.x*blockDim.x + threadIdx.x; idx < tot;
         idx += gridDim.x*blockDim.x){
        int n = idx / K, k = idx - n*K;
        float v = W[(size_t)k*N + n];
        bf16 h, l; split1(v, h, l);
        T1[idx] = h; T2[idx] = l;
    }
}
// LayerNorm + bf16 split (used once, before layer 0)
__global__ void k_ln_split(const float* __restrict__ w, const float* __restrict__ b){
    int warp = threadIdx.x >> 5, lane = threadIdx.x & 31;
    int row = blockIdx.x*8 + warp;
    const float* src = g_h + (size_t)row*DIM;
    float4 v = *(const float4*)(src + lane*4);
    float s  = v.x+v.y+v.z+v.w;
    float ss = v.x*v.x+v.y*v.y+v.z*v.z+v.w*v.w;
    #pragma unroll
    for (int o = 16; o; o >>= 1){
        s  += __shfl_xor_sync(0xffffffffu, s,  o);
        ss += __shfl_xor_sync(0xffffffffu, ss, o);
    }
    float mean = s*(1.0f/DIM);
    float var  = ss*(1.0f/DIM) - mean*mean;
    float rstd = rsqrtf(var + 1e-5f);
    float4 wv = *(const float4*)(w + lane*4);
    float4 bv = *(const float4*)(b + lane*4);
    float n0 = (v.x-mean)*rstd*wv.x + bv.x;
    float n1 = (v.y-mean)*rstd*wv.y + bv.y;
    float n2 = (v.z-mean)*rstd*wv.z + bv.z;
    float n3 = (v.w-mean)*rstd*wv.w + bv.w;
    bf16 h0,l0,h1,l1,h2,l2,h3,l3;
    split1(n0,h0,l0); split1(n1,h1,l1); split1(n2,h2,l2); split1(n3,h3,l3);
    __nv_bfloat162* d1 = (__nv_bfloat162*)(g_a1 + (size_t)row*DIM + lane*4);
    __nv_bfloat162* d2 = (__nv_bfloat162*)(g_a2 + (size_t)row*DIM + lane*4);
    __nv_bfloat162 p;
    p.x=h0; p.y=h1; d1[0]=p;  p.x=h2; p.y=h3; d1[1]=p;
    p.x=l0; p.y=l1; d2[0]=p;  p.x=l2; p.y=l3; d2[1]=p;
}
// attention
__global__ void k_attn(){
    int warp = threadIdx.x >> 5, lane = threadIdx.x & 31;
    int cell = blockIdx.x*8 + warp;
    int qoff = ((lane >> 3) << 5) + ((lane & 7) << 2);
    const float scale = 0.17677669529663687f;
    size_t base = (size_t)cell*LTOK;
    for (int r = 0; r < LTOK; r++){
        float4 q4 = *(const float4*)(g_qkv + (base+r)*384 + qoff);
        float sc[LTOK]; float mx = -1e30f;
        #pragma unroll
        for (int j = 0; j < LTOK; j++){
            float4 k4 = *(const float4*)(g_qkv + (base+j)*384 + 128 + qoff);
            float sdot = q4.x*k4.x + q4.y*k4.y + q4.z*k4.z + q4.w*k4.w;
            sdot += __shfl_xor_sync(0xffffffffu, sdot, 1);
            sdot += __shfl_xor_sync(0xffffffffu, sdot, 2);
            sdot += __shfl_xor_sync(0xffffffffu, sdot, 4);
            sdot *= scale;
            sc[j] = sdot; mx = fmaxf(mx, sdot);
        }
        float den = 0.0f;
        #pragma unroll
        for (int j = 0; j < LTOK; j++){ sc[j] = __expf(sc[j]-mx); den += sc[j]; }
        float inv = __fdividef(1.0f, den);
        float4 o = make_float4(0.f,0.f,0.f,0.f);
        #pragma unroll
        for (int j = 0; j < LTOK; j++){
            float p = sc[j]*inv;
            float4 v4 = *(const float4*)(g_qkv + (base+j)*384 + 256 + qoff);
            o.x += p*v4.x; o.y += p*v4.y; o.z += p*v4.z; o.w += p*v4.w;
        }
        bf16 h0,l0,h1,l1,h2,l2,h3,l3;
        split1(o.x,h0,l0); split1(o.y,h1,l1); split1(o.z,h2,l2); split1(o.w,h3,l3);
        __nv_bfloat162* d1 = (__nv_bfloat162*)(g_a1 + (base+r)*DIM + qoff);
        __nv_bfloat162* d2 = (__nv_bfloat162*)(g_a2 + (base+r)*DIM + qoff);
        __nv_bfloat162 p;
        p.x=h0; p.y=h1; d1[0]=p;  p.x=h2; p.y=h3; d1[1]=p;
        p.x=l0; p.y=l1; d2[0]=p;  p.x=l2; p.y=l3; d2[1]=p;
    }
}
__global__ void k_split_feat(){
    int idx = blockIdx.x*blockDim.x + threadIdx.x;
    if (idx >= BALL*HID) return;
    int cell = idx >> 9, k = idx & 511;
    float v = g_h[(size_t)cell*(LTOK*DIM) + k];
    bf16 h, l; split1(v, h, l);
    g_fa1[idx] = h; g_fa2[idx] = l;
}

// ---------------- mma.sync GEMM, single stage, 2 CTAs/SM, fused-LN option --------
// A1/A2: [M][Ktot] bf16 row-major.  B1/B2: [N][Ktot] bf16 k-fast.
// D = A1B1 + A1B2 + A2B1 (fp32 regs).  GF_LN requires ny==1.
__global__ __launch_bounds__(256, 2)
void k_gemm(const bf16* __restrict__ A1, const bf16* __restrict__ A2, int lda,
            const bf16* __restrict__ B1, const bf16* __restrict__ B2,
            const float* __restrict__ bias,
            float* __restrict__ Cout, int ldc,
            bf16* __restrict__ O1, bf16* __restrict__ O2, int ldo,
            const float* __restrict__ lnw, const float* __restrict__ lnb,
            int Ktot, int flags){
    extern __shared__ bf16 smem[];
    float2* red = (float2*)(smem + STGB/2);   // byte offset STGB; 256 float2 = 2048 B
    const int tid = threadIdx.x, lane = tid & 31, wid = tid >> 5;
    const int warpM = wid & 3, warpN = wid >> 2;
    const int row0 = blockIdx.x*128, cofs = blockIdx.y*128;
    const uint32_t sbase = s2u(smem);

    float acc[2][8][4];
    #pragma unroll
    for (int mt = 0; mt < 2; mt++)
        #pragma unroll
        for (int nt = 0; nt < 8; nt++)
            #pragma unroll
            for (int q = 0; q < 4; q++) acc[mt][nt][q] = 0.0f;

    const int rowA = lane & 15, kA8 = (lane >> 4) << 3;
    const int rowB = lane & 7,  kB8 = ((lane >> 3) & 1) << 3;
    const uint32_t aoff = sbase + (uint32_t)(((warpM*32 + rowA)*AS + kA8) * 2);
    const uint32_t boff = sbase + (uint32_t)(36864 + ((warpN*64 + rowB)*AS + kB8) * 2);

    for (int kc = 0; kc < Ktot; kc += 64){
        #pragma unroll
        for (int it = 0; it < 4; it++){
            int idx = it*256 + tid;
            int r = idx >> 3, c8 = (idx & 7) << 3;
            uint32_t so = (uint32_t)((r*AS + c8) * 2);
            cp16(sbase + so,         A1 + (size_t)(row0+r)*lda + kc + c8);
            cp16(sbase + 18432 + so, A2 + (size_t)(row0+r)*lda + kc + c8);
            cp16(sbase + 36864 + so, B1 + (size_t)(cofs+r)*Ktot + kc + c8);
            cp16(sbase + 55296 + so, B2 + (size_t)(cofs+r)*Ktot + kc + c8);
        }
        CPCOMMIT();
        asm volatile("cp.async.wait_group 0;" ::: "memory");
        __syncthreads();

        #pragma unroll
        for (int k16 = 0; k16 < 64; k16 += 16){
            uint32_t a1f[2][4], a2f[2][4];
            #pragma unroll
            for (int mt = 0; mt < 2; mt++){
                uint32_t ad = aoff + (uint32_t)((mt*16*AS + k16) * 2);
                ldsm_x4(a1f[mt], ad);
                ldsm_x4(a2f[mt], ad + 18432);
            }
            #pragma unroll
            for (int nt = 0; nt < 8; nt++){
                uint32_t bd = boff + (uint32_t)((nt*8*AS + k16) * 2);
                uint32_t b1f[2], b2f[2];
                ldsm_x2(b1f, bd);
                ldsm_x2(b2f, bd + 18432);
                mma16816(acc[0][nt], a1f[0], b1f);
                mma16816(acc[1][nt], a1f[1], b1f);
                mma16816(acc[0][nt], a2f[0], b1f);
                mma16816(acc[1][nt], a2f[1], b1f);
                mma16816(acc[0][nt], a1f[0], b2f);
                mma16816(acc[1][nt], a1f[1], b2f);
            }
        }
        __syncthreads();
    }

    const int l4 = lane >> 2, l2 = (lane & 3) << 1;

    if (flags & GF_LN){
        #pragma unroll
        for (int mt = 0; mt < 2; mt++){
            #pragma unroll
            for (int hh = 0; hh < 2; hh++){
                int rl = warpM*32 + mt*16 + hh*8 + l4;
                int rg = row0 + rl;
                float s = 0.0f, ss = 0.0f;
                #pragma unroll
                for (int nt = 0; nt < 8; nt++){
                    int cg = warpN*64 + nt*8 + l2;
                    float2 old = *(const float2*)(Cout + (size_t)rg*ldc + cg);
                    float v0 = acc[mt][nt][hh*2+0] + bias[cg]   + old.x;
                    float v1 = acc[mt][nt][hh*2+1] + bias[cg+1] + old.y;
                    acc[mt][nt][hh*2+0] = v0;
                    acc[mt][nt][hh*2+1] = v1;
                    *(float2*)(Cout + (size_t)rg*ldc + cg) = make_float2(v0, v1);
                    s += v0 + v1; ss += v0*v0 + v1*v1;
                }
                s  += __shfl_xor_sync(0xffffffffu, s,  1);
                ss += __shfl_xor_sync(0xffffffffu, ss, 1);
                s  += __shfl_xor_sync(0xffffffffu, s,  2);
                ss += __shfl_xor_sync(0xffffffffu, ss, 2);
                if ((lane & 3) == 0) red[rl*2 + warpN] = make_float2(s, ss);
            }
        }
        __syncthreads();
        #pragma unroll
        for (int mt = 0; mt < 2; mt++){
            #pragma unroll
            for (int hh = 0; hh < 2; hh++){
                int rl = warpM*32 + mt*16 + hh*8 + l4;
                int rg = row0 + rl;
                float2 r0 = red[rl*2 + 0], r1 = red[rl*2 + 1];
                float mean = (r0.x + r1.x) * (1.0f/DIM);
                float var  = (r0.y + r1.y) * (1.0f/DIM) - mean*mean;
                float rstd = rsqrtf(var + 1e-5f);
                #pragma unroll
                for (int nt = 0; nt < 8; nt++){
                    int cg = warpN*64 + nt*8 + l2;
                    float n0 = (acc[mt][nt][hh*2+0] - mean)*rstd*lnw[cg]   + lnb[cg];
                    float n1 = (acc[mt][nt][hh*2+1] - mean)*rstd*lnw[cg+1] + lnb[cg+1];
                    bf16 ha,la,hb,lb;
                    split1(n0, ha, la); split1(n1, hb, lb);
                    __nv_bfloat162 p;
                    p.x=ha; p.y=hb; *(__nv_bfloat162*)(O1 + (size_t)rg*ldo + cg) = p;
                    p.x=la; p.y=lb; *(__nv_bfloat162*)(O2 + (size_t)rg*ldo + cg) = p;
                }
            }
        }
        return;
    }

    #pragma unroll
    for (int mt = 0; mt < 2; mt++){
        #pragma unroll
        for (int hh = 0; hh < 2; hh++){
            int rg = row0 + warpM*32 + mt*16 + l4 + hh*8;
            bool maskz = (flags & GF_MASK) && (g_counts[rg] == 0);
            #pragma unroll
            for (int nt = 0; nt < 8; nt++){
                int cg = cofs + warpN*64 + nt*8 + l2;
                float v0 = acc[mt][nt][hh*2+0] + bias[cg];
                float v1 = acc[mt][nt][hh*2+1] + bias[cg+1];
                if (flags & GF_GELU){ v0 = gelu_f(v0); v1 = gelu_f(v1); }
                if (flags & GF_ACCUM){
                    float2 old = *(const float2*)(Cout + (size_t)rg*ldc + cg);
                    v0 += old.x; v1 += old.y;
                }
                if (flags & GF_SPLIT){
                    bf16 ha,la,hb,lb;
                    split1(v0, ha, la); split1(v1, hb, lb);
                    __nv_bfloat162 p;
                    p.x=ha; p.y=hb; *(__nv_bfloat162*)(O1 + (size_t)rg*ldo + cg) = p;
                    p.x=la; p.y=lb; *(__nv_bfloat162*)(O2 + (size_t)rg*ldo + cg) = p;
                } else {
                    float2 ov = maskz ? make_float2(0.f, 0.f) : make_float2(v0, v1);
                    *(float2*)(Cout + (size_t)rg*ldc + cg) = ov;
                }
            }
        }
    }
}

// ---------------- launch ----------------
extern "C" void kernel_launch(void* const* d_in, const int* in_sizes, int n_in,
                              void* d_out, int out_size){
    const float* x    = (const float*)d_in[0];
    const int*   li   = (const int*)  d_in[1];
    const float* ob   = (const float*)d_in[2];
    const float* dw   = (const float*)d_in[3];
    const float* db   = (const float*)d_in[4];
    const float* ln1w = (const float*)d_in[5];
    const float* ln1b = (const float*)d_in[6];
    const float* wqkv = (const float*)d_in[7];
    const float* bqkv = (const float*)d_in[8];
    const float* wo   = (const float*)d_in[9];
    const float* bo   = (const float*)d_in[10];
    const float* ln2w = (const float*)d_in[11];
    const float* ln2b = (const float*)d_in[12];
    const float* w1   = (const float*)d_in[13];
    const float* b1   = (const float*)d_in[14];
    const float* w2   = (const float*)d_in[15];
    const float* b2   = (const float*)d_in[16];
    const float* pw   = (const float*)d_in[17];
    const float* pb   = (const float*)d_in[18];
    int n = in_sizes[0] / DIM;

    bf16 *a1, *a2, *h1a, *h1b, *fa1, *fa2;
    bf16 *wqT1, *wqT2, *woT1, *woT2, *w1T1, *w1T2, *w2T1, *w2T2, *pT1, *pT2;
    float *h, *qkv;
    cudaGetSymbolAddress((void**)&a1,  g_a1);  cudaGetSymbolAddress((void**)&a2,  g_a2);
    cudaGetSymbolAddress((void**)&h1a, g_h1a); cudaGetSymbolAddress((void**)&h1b, g_h1b);
    cudaGetSymbolAddress((void**)&fa1, g_fa1); cudaGetSymbolAddress((void**)&fa2, g_fa2);
    cudaGetSymbolAddress((void**)&wqT1, g_wqkvT1); cudaGetSymbolAddress((void**)&wqT2, g_wqkvT2);
    cudaGetSymbolAddress((void**)&woT1, g_woT1);   cudaGetSymbolAddress((void**)&woT2, g_woT2);
    cudaGetSymbolAddress((void**)&w1T1, g_w1T1);   cudaGetSymbolAddress((void**)&w1T2, g_w1T2);
    cudaGetSymbolAddress((void**)&w2T1, g_w2T1);   cudaGetSymbolAddress((void**)&w2T2, g_w2T2);
    cudaGetSymbolAddress((void**)&pT1, g_pT1);     cudaGetSymbolAddress((void**)&pT2, g_pT2);
    cudaGetSymbolAddress((void**)&h, g_h);         cudaGetSymbolAddress((void**)&qkv, g_qkv);

    const int SMEM_GB = STGB + 2048;   // 75776 B -> 2 CTAs/SM, full red[] in bounds
    cudaFuncSetAttribute(k_gemm, cudaFuncAttributeMaxDynamicSharedMemorySize, SMEM_GB);

    // setup
    k_zero<<<(BALL+255)/256, 256>>>();
    k_scatter<<<(n+255)/256, 256>>>(li, n);
    k_bg<<<2, 256>>>(ob, dw, db);
    k_select<<<(BALL+255)/256, 256>>>();
    k_assemble<<<(NROW*DIM+255)/256, 256>>>(x);

    // weight transpose+split
    k_tsplit<<<dim3(64, DEPTH), 256>>>(wqkv, wqT1, wqT2, DIM, 3*DIM);
    k_tsplit<<<dim3(32, DEPTH), 256>>>(wo,   woT1, woT2, DIM, DIM);
    k_tsplit<<<dim3(64, DEPTH), 256>>>(w1,   w1T1, w1T2, DIM, HID);
    k_tsplit<<<dim3(64, DEPTH), 256>>>(w2,   w2T1, w2T2, HID, DIM);
    k_tsplit<<<dim3(256, 1),    256>>>(pw,   pT1,  pT2,  HID, CLV);

    // initial LN (layer 0); later LNs fused into wo/w2 epilogues
    k_ln_split<<<NROW/8, 256>>>(ln1w, ln1b);

    const int MB = NROW/128;   // 720
    for (int L = 0; L < DEPTH; L++){
        k_gemm<<<dim3(MB,3), 256, SMEM_GB>>>(a1, a2, DIM,
            wqT1 + (size_t)L*3*DIM*DIM, wqT2 + (size_t)L*3*DIM*DIM,
            bqkv + L*3*DIM, qkv, 3*DIM, (bf16*)0, (bf16*)0, 0,
            (float*)0, (float*)0, DIM, 0);
        k_attn<<<BALL/8, 256>>>();
        k_gemm<<<dim3(MB,1), 256, SMEM_GB>>>(a1, a2, DIM,
            woT1 + (size_t)L*DIM*DIM, woT2 + (size_t)L*DIM*DIM,
            bo + L*DIM, h, DIM, a1, a2, DIM,
            ln2w + L*DIM, ln2b + L*DIM, DIM, GF_ACCUM|GF_LN);
        k_gemm<<<dim3(MB,4), 256, SMEM_GB>>>(a1, a2, DIM,
            w1T1 + (size_t)L*HID*DIM, w1T2 + (size_t)L*HID*DIM,
            b1 + L*HID, (float*)0, 0, h1a, h1b, HID,
            (float*)0, (float*)0, DIM, GF_GELU|GF_SPLIT);
        if (L < DEPTH-1){
            k_gemm<<<dim3(MB,1), 256, SMEM_GB>>>(h1a, h1b, HID,
                w2T1 + (size_t)L*DIM*HID, w2T2 + (size_t)L*DIM*HID,
                b2 + L*DIM, h, DIM, a1, a2, DIM,
                ln1w + (L+1)*DIM, ln1b + (L+1)*DIM, HID, GF_ACCUM|GF_LN);
        } else {
            k_gemm<<<dim3(MB,1), 256, SMEM_GB>>>(h1a, h1b, HID,
                w2T1 + (size_t)L*DIM*HID, w2T2 + (size_t)L*DIM*HID,
                b2 + L*DIM, h, DIM, (bf16*)0, (bf16*)0, 0,
                (float*)0, (float*)0, HID, GF_ACCUM);
        }
    }

    k_split_feat<<<(BALL*HID+255)/256, 256>>>();
    k_gemm<<<dim3(BALL/128, CLV/128), 256, SMEM_GB>>>(fa1, fa2, HID,
        pT1, pT2, pb, (float*)d_out, CLV, (bf16*)0, (bf16*)0, 0,
        (float*)0, (float*)0, HID, GF_MASK);
}

// round 11
// speedup vs baseline: 2.7437x; 1.1901x over previous
#include <cuda_runtime.h>
#include <cuda_bf16.h>
#include <cstdint>
#include <math.h>

#define DD     5
#define HGRID  24
#define WGRID  48
#define CLV    1024
#define NB     4
#define DIM    128
#define LMAX   12
#define DEPTH  6
#define LTOK   16
#define BALL   (DD*HGRID*WGRID)   // 5760
#define NROW   (BALL*LTOK)        // 92160
#define CAP    64
#define HID    512
#define AS     72                 // smem row stride in bf16 (144B: conflict-free ldmatrix)
#define PANEL  18432              // bytes per 128x64 panel
#define STGB   73728              // streaming stage bytes (4 panels)

typedef __nv_bfloat16 bf16;

// ---------------- device scratch ----------------
__device__ int   g_counts[BALL];
__device__ int   g_list[BALL*CAP];
__device__ int   g_sel[BALL*LMAX];
__device__ int   g_m[BALL];
__device__ float g_bgp[NB*DIM];
__device__ float g_h[NROW*DIM];
__device__ float g_qkv[NROW*3*DIM];
__device__ bf16  g_a1[NROW*DIM],  g_a2[NROW*DIM];
__device__ bf16  g_h1a[NROW*HID];                 // single-bf16 gelu(h1)
__device__ bf16  g_fa1[BALL*HID], g_fa2[BALL*HID];
// transposed + split weights: [n][k] k-fast
__device__ bf16  g_wqkvT1[DEPTH*3*DIM*DIM], g_wqkvT2[DEPTH*3*DIM*DIM];
__device__ bf16  g_woT1[DEPTH*DIM*DIM],     g_woT2[DEPTH*DIM*DIM];
__device__ bf16  g_w1T1[DEPTH*HID*DIM],     g_w1T2[DEPTH*HID*DIM];
__device__ bf16  g_w2T1[DEPTH*DIM*HID],     g_w2T2[DEPTH*DIM*HID];
__device__ bf16  g_pT1[CLV*HID],            g_pT2[CLV*HID];

// ---------------- helpers ----------------
__device__ __forceinline__ uint32_t s2u(const void* p){
    uint32_t a;
    asm("{ .reg .u64 t; cvta.to.shared.u64 t, %1; cvt.u32.u64 %0, t; }" : "=r"(a) : "l"(p));
    return a;
}
__device__ __forceinline__ void cp16(uint32_t dst, const void* src){
    asm volatile("cp.async.cg.shared.global [%0], [%1], 16;" :: "r"(dst), "l"(src));
}
#define CPCOMMIT() asm volatile("cp.async.commit_group;" ::: "memory")
#define CPWAIT0()  asm volatile("cp.async.wait_group 0;" ::: "memory")
__device__ __forceinline__ void ldsm_x4(uint32_t* d, uint32_t addr){
    asm volatile("ldmatrix.sync.aligned.m8n8.x4.shared.b16 {%0,%1,%2,%3}, [%4];"
        : "=r"(d[0]),"=r"(d[1]),"=r"(d[2]),"=r"(d[3]) : "r"(addr));
}
__device__ __forceinline__ void ldsm_x2(uint32_t* d, uint32_t addr){
    asm volatile("ldmatrix.sync.aligned.m8n8.x2.shared.b16 {%0,%1}, [%2];"
        : "=r"(d[0]),"=r"(d[1]) : "r"(addr));
}
__device__ __forceinline__ void mma16816(float* c, const uint32_t* a, const uint32_t* b){
    asm volatile("mma.sync.aligned.m16n8k16.row.col.f32.bf16.bf16.f32 "
        "{%0,%1,%2,%3}, {%4,%5,%6,%7}, {%8,%9}, {%0,%1,%2,%3};"
        : "+f"(c[0]),"+f"(c[1]),"+f"(c[2]),"+f"(c[3])
        : "r"(a[0]),"r"(a[1]),"r"(a[2]),"r"(a[3]), "r"(b[0]),"r"(b[1]));
}
__device__ __forceinline__ float gelu_f(float x){
    float x3 = x*x*x;
    return 0.5f*x*(1.0f + tanhf(0.7978845608028654f*(x + 0.044715f*x3)));
}
__device__ __forceinline__ void split1(float v, bf16 &h, bf16 &l){
    h = __float2bfloat16(v);
    l = __float2bfloat16(v - __bfloat162float(h));
}

#define GF_ACCUM 1
#define GF_GELU  2
#define GF_SPLIT 4
#define GF_MASK  8
#define GF_LN    16
#define GF_B16   32

// ---------------- setup kernels ----------------
__global__ void k_zero(){
    int i = blockIdx.x*blockDim.x + threadIdx.x;
    if (i < BALL) g_counts[i] = 0;
}
__global__ void k_scatter(const int* __restrict__ li, int n){
    int i = blockIdx.x*blockDim.x + threadIdx.x;
    if (i >= n) return;
    int flat = li[3*i]*(HGRID*WGRID) + li[3*i+1]*WGRID + li[3*i+2];
    int slot = atomicAdd(&g_counts[flat], 1);
    if (slot < CAP) g_list[flat*CAP + slot] = i;
}
__global__ void k_bg(const float* __restrict__ ob, const float* __restrict__ dw,
                     const float* __restrict__ db){
    int c = blockIdx.x*blockDim.x + threadIdx.x;
    if (c >= NB*DIM) return;
    float s = 0.0f;
    for (int m = 0; m < NB; m++){
        const float* bg = ob + m*DIM;
        float t = 0.0f;
        for (int k = 0; k < DIM; k++) t += bg[k] * dw[k*(NB*DIM) + c];
        s += t;
    }
    g_bgp[c] = ob[c] + s*(1.0f/NB) + db[c];
}
__global__ void k_select(){
    int cell = blockIdx.x*blockDim.x + threadIdx.x;
    if (cell >= BALL) return;
    int cnt = g_counts[cell];
    int avail = min(cnt, CAP);
    int m = min(cnt, LMAX);
    g_m[cell] = m;
    if (cnt <= LMAX){
        for (int j = 0; j < m; j++) g_sel[cell*LMAX + j] = g_list[cell*CAP + j];
    } else {
        int tmp[CAP];
        for (int j = 0; j < avail; j++) tmp[j] = g_list[cell*CAP + j];
        for (int a = 0; a < m; a++){
            int best = a;
            for (int b = a+1; b < avail; b++) if (tmp[b] < tmp[best]) best = b;
            int t = tmp[best]; tmp[best] = tmp[a]; tmp[a] = t;
            g_sel[cell*LMAX + a] = t;
        }
    }
}
__global__ void k_assemble(const float* __restrict__ x){
    int idx = blockIdx.x*blockDim.x + threadIdx.x;
    if (idx >= NROW*DIM) return;
    int row = idx >> 7, d = idx & 127;
    int cell = row >> 4, lr = row & 15;
    float v;
    if (lr < NB) v = g_bgp[lr*DIM + d];
    else {
        int j = lr - NB;
        v = (j < g_m[cell]) ? x[(size_t)g_sel[cell*LMAX + j]*DIM + d] : 0.0f;
    }
    g_h[idx] = v;
}
__global__ void k_tsplit(const float* __restrict__ W, bf16* __restrict__ T1,
                         bf16* __restrict__ T2, int K, int N){
    size_t off = (size_t)blockIdx.y * K * N;
    W += off; T1 += off; T2 += off;
    int tot = K*N;
    for (int idx = blockIdx.x*blockDim.x + threadIdx.x; idx < tot;
         idx += gridDim.x*blockDim.x){
        int n = idx / K, k = idx - n*K;
        float v = W[(size_t)k*N + n];
        bf16 h, l; split1(v, h, l);
        T1[idx] = h; T2[idx] = l;
    }
}
// LayerNorm + bf16 split (layer 0 only)
__global__ void k_ln_split(const float* __restrict__ w, const float* __restrict__ b){
    int warp = threadIdx.x >> 5, lane = threadIdx.x & 31;
    int row = blockIdx.x*8 + warp;
    const float* src = g_h + (size_t)row*DIM;
    float4 v = *(const float4*)(src + lane*4);
    float s  = v.x+v.y+v.z+v.w;
    float ss = v.x*v.x+v.y*v.y+v.z*v.z+v.w*v.w;
    #pragma unroll
    for (int o = 16; o; o >>= 1){
        s  += __shfl_xor_sync(0xffffffffu, s,  o);
        ss += __shfl_xor_sync(0xffffffffu, ss, o);
    }
    float mean = s*(1.0f/DIM);
    float var  = ss*(1.0f/DIM) - mean*mean;
    float rstd = rsqrtf(var + 1e-5f);
    float4 wv = *(const float4*)(w + lane*4);
    float4 bv = *(const float4*)(b + lane*4);
    float n0 = (v.x-mean)*rstd*wv.x + bv.x;
    float n1 = (v.y-mean)*rstd*wv.y + bv.y;
    float n2 = (v.z-mean)*rstd*wv.z + bv.z;
    float n3 = (v.w-mean)*rstd*wv.w + bv.w;
    bf16 h0,l0,h1,l1,h2,l2,h3,l3;
    split1(n0,h0,l0); split1(n1,h1,l1); split1(n2,h2,l2); split1(n3,h3,l3);
    __nv_bfloat162* d1 = (__nv_bfloat162*)(g_a1 + (size_t)row*DIM + lane*4);
    __nv_bfloat162* d2 = (__nv_bfloat162*)(g_a2 + (size_t)row*DIM + lane*4);
    __nv_bfloat162 p;
    p.x=h0; p.y=h1; d1[0]=p;  p.x=h2; p.y=h3; d1[1]=p;
    p.x=l0; p.y=l1; d2[0]=p;  p.x=l2; p.y=l3; d2[1]=p;
}
// attention
__global__ void k_attn(){
    int warp = threadIdx.x >> 5, lane = threadIdx.x & 31;
    int cell = blockIdx.x*8 + warp;
    int qoff = ((lane >> 3) << 5) + ((lane & 7) << 2);
    const float scale = 0.17677669529663687f;
    size_t base = (size_t)cell*LTOK;
    for (int r = 0; r < LTOK; r++){
        float4 q4 = *(const float4*)(g_qkv + (base+r)*384 + qoff);
        float sc[LTOK]; float mx = -1e30f;
        #pragma unroll
        for (int j = 0; j < LTOK; j++){
            float4 k4 = *(const float4*)(g_qkv + (base+j)*384 + 128 + qoff);
            float sdot = q4.x*k4.x + q4.y*k4.y + q4.z*k4.z + q4.w*k4.w;
            sdot += __shfl_xor_sync(0xffffffffu, sdot, 1);
            sdot += __shfl_xor_sync(0xffffffffu, sdot, 2);
            sdot += __shfl_xor_sync(0xffffffffu, sdot, 4);
            sdot *= scale;
            sc[j] = sdot; mx = fmaxf(mx, sdot);
        }
        float den = 0.0f;
        #pragma unroll
        for (int j = 0; j < LTOK; j++){ sc[j] = __expf(sc[j]-mx); den += sc[j]; }
        float inv = __fdividef(1.0f, den);
        float4 o = make_float4(0.f,0.f,0.f,0.f);
        #pragma unroll
        for (int j = 0; j < LTOK; j++){
            float p = sc[j]*inv;
            float4 v4 = *(const float4*)(g_qkv + (base+j)*384 + 256 + qoff);
            o.x += p*v4.x; o.y += p*v4.y; o.z += p*v4.z; o.w += p*v4.w;
        }
        bf16 h0,l0,h1,l1,h2,l2,h3,l3;
        split1(o.x,h0,l0); split1(o.y,h1,l1); split1(o.z,h2,l2); split1(o.w,h3,l3);
        __nv_bfloat162* d1 = (__nv_bfloat162*)(g_a1 + (base+r)*DIM + qoff);
        __nv_bfloat162* d2 = (__nv_bfloat162*)(g_a2 + (base+r)*DIM + qoff);
        __nv_bfloat162 p;
        p.x=h0; p.y=h1; d1[0]=p;  p.x=h2; p.y=h3; d1[1]=p;
        p.x=l0; p.y=l1; d2[0]=p;  p.x=l2; p.y=l3; d2[1]=p;
    }
}
__global__ void k_split_feat(){
    int idx = blockIdx.x*blockDim.x + threadIdx.x;
    if (idx >= BALL*HID) return;
    int cell = idx >> 9, k = idx & 511;
    float v = g_h[(size_t)cell*(LTOK*DIM) + k];
    bf16 h, l; split1(v, h, l);
    g_fa1[idx] = h; g_fa2[idx] = l;
}

// ---------------- shared epilogue ----------------
__device__ __forceinline__ void gemm_epilogue(
    float (&acc)[2][8][4], int row0, int cofs,
    const float* __restrict__ bias,
    float* __restrict__ Cout, int ldc,
    bf16* __restrict__ O1, bf16* __restrict__ O2, int ldo,
    const float* __restrict__ lnw, const float* __restrict__ lnb,
    float2* red, int flags, int lane, int warpM, int warpN)
{
    const int l4 = lane >> 2, l2 = (lane & 3) << 1;

    if (flags & GF_LN){
        #pragma unroll
        for (int mt = 0; mt < 2; mt++){
            #pragma unroll
            for (int hh = 0; hh < 2; hh++){
                int rl = warpM*32 + mt*16 + hh*8 + l4;
                int rg = row0 + rl;
                float s = 0.0f, ss = 0.0f;
                #pragma unroll
                for (int nt = 0; nt < 8; nt++){
                    int cg = warpN*64 + nt*8 + l2;
                    float2 old = *(const float2*)(Cout + (size_t)rg*ldc + cg);
                    float v0 = acc[mt][nt][hh*2+0] + bias[cg]   + old.x;
                    float v1 = acc[mt][nt][hh*2+1] + bias[cg+1] + old.y;
                    acc[mt][nt][hh*2+0] = v0;
                    acc[mt][nt][hh*2+1] = v1;
                    *(float2*)(Cout + (size_t)rg*ldc + cg) = make_float2(v0, v1);
                    s += v0 + v1; ss += v0*v0 + v1*v1;
                }
                s  += __shfl_xor_sync(0xffffffffu, s,  1);
                ss += __shfl_xor_sync(0xffffffffu, ss, 1);
                s  += __shfl_xor_sync(0xffffffffu, s,  2);
                ss += __shfl_xor_sync(0xffffffffu, ss, 2);
                if ((lane & 3) == 0) red[rl*2 + warpN] = make_float2(s, ss);
            }
        }
        __syncthreads();
        #pragma unroll
        for (int mt = 0; mt < 2; mt++){
            #pragma unroll
            for (int hh = 0; hh < 2; hh++){
                int rl = warpM*32 + mt*16 + hh*8 + l4;
                int rg = row0 + rl;
                float2 r0 = red[rl*2 + 0], r1 = red[rl*2 + 1];
                float mean = (r0.x + r1.x) * (1.0f/DIM);
                float var  = (r0.y + r1.y) * (1.0f/DIM) - mean*mean;
                float rstd = rsqrtf(var + 1e-5f);
                #pragma unroll
                for (int nt = 0; nt < 8; nt++){
                    int cg = warpN*64 + nt*8 + l2;
                    float n0 = (acc[mt][nt][hh*2+0] - mean)*rstd*lnw[cg]   + lnb[cg];
                    float n1 = (acc[mt][nt][hh*2+1] - mean)*rstd*lnw[cg+1] + lnb[cg+1];
                    bf16 ha,la,hb,lb;
                    split1(n0, ha, la); split1(n1, hb, lb);
                    __nv_bfloat162 p;
                    p.x=ha; p.y=hb; *(__nv_bfloat162*)(O1 + (size_t)rg*ldo + cg) = p;
                    p.x=la; p.y=lb; *(__nv_bfloat162*)(O2 + (size_t)rg*ldo + cg) = p;
                }
            }
        }
        return;
    }

    #pragma unroll
    for (int mt = 0; mt < 2; mt++){
        #pragma unroll
        for (int hh = 0; hh < 2; hh++){
            int rg = row0 + warpM*32 + mt*16 + l4 + hh*8;
            bool maskz = (flags & GF_MASK) && (g_counts[rg] == 0);
            #pragma unroll
            for (int nt = 0; nt < 8; nt++){
                int cg = cofs + warpN*64 + nt*8 + l2;
                float v0 = acc[mt][nt][hh*2+0] + bias[cg];
                float v1 = acc[mt][nt][hh*2+1] + bias[cg+1];
                if (flags & GF_GELU){ v0 = gelu_f(v0); v1 = gelu_f(v1); }
                if (flags & GF_ACCUM){
                    float2 old = *(const float2*)(Cout + (size_t)rg*ldc + cg);
                    v0 += old.x; v1 += old.y;
                }
                if (flags & GF_SPLIT){
                    bf16 ha,la,hb,lb;
                    split1(v0, ha, la); split1(v1, hb, lb);
                    __nv_bfloat162 p;
                    p.x=ha; p.y=hb; *(__nv_bfloat162*)(O1 + (size_t)rg*ldo + cg) = p;
                    p.x=la; p.y=lb; *(__nv_bfloat162*)(O2 + (size_t)rg*ldo + cg) = p;
                } else if (flags & GF_B16){
                    __nv_bfloat162 p;
                    p.x = __float2bfloat16(v0); p.y = __float2bfloat16(v1);
                    *(__nv_bfloat162*)(O1 + (size_t)rg*ldo + cg) = p;
                } else {
                    float2 ov = maskz ? make_float2(0.f, 0.f) : make_float2(v0, v1);
                    *(float2*)(Cout + (size_t)rg*ldc + cg) = ov;
                }
            }
        }
    }
}

// ---------------- mma.sync GEMM ----------------
// ARES: Ktot must be 128; A held resident in smem; internal loop over ny N-blocks.
// A2ON: include A2 split terms (3-term vs 2-term).
template<bool ARES, bool A2ON>
__global__ __launch_bounds__(256, 2)
void k_gemm(const bf16* __restrict__ A1, const bf16* __restrict__ A2, int lda,
            const bf16* __restrict__ B1, const bf16* __restrict__ B2,
            const float* __restrict__ bias,
            float* __restrict__ Cout, int ldc,
            bf16* __restrict__ O1, bf16* __restrict__ O2, int ldo,
            const float* __restrict__ lnw, const float* __restrict__ lnb,
            int Ktot, int ny, int flags){
    extern __shared__ bf16 smem[];
    const int tid = threadIdx.x, lane = tid & 31, wid = tid >> 5;
    const int warpM = wid & 3, warpN = wid >> 2;
    const int row0 = blockIdx.x*128;
    const uint32_t sbase = s2u(smem);
    const uint32_t BBASE = ARES ? 4*PANEL : 2*PANEL;
    float2* red = (float2*)((char*)smem + (ARES ? 6*PANEL : 4*PANEL));

    const int rowA = lane & 15, kA8 = (lane >> 4) << 3;
    const int rowB = lane & 7,  kB8 = ((lane >> 3) & 1) << 3;
    const uint32_t aoff0 = (uint32_t)(((warpM*32 + rowA)*AS + kA8) * 2);
    const uint32_t boff  = sbase + BBASE + (uint32_t)(((warpN*64 + rowB)*AS + kB8) * 2);

    float acc[2][8][4];

    if (ARES){
        // load full A: panels {chunk0:A1,A2, chunk1:A1,A2}
        #pragma unroll
        for (int p = 0; p < 4; p++){
            int chunk = p >> 1;
            const bf16* src = (p & 1) ? A2 : A1;
            #pragma unroll
            for (int it = 0; it < 4; it++){
                int idx = it*256 + tid;
                int r = idx >> 3, c8 = (idx & 7) << 3;
                cp16(sbase + p*PANEL + (uint32_t)((r*AS + c8)*2),
                     src + (size_t)(row0+r)*lda + chunk*64 + c8);
            }
        }
        CPCOMMIT();

        for (int nb = 0; nb < ny; nb++){
            int cofs = nb*128;
            #pragma unroll
            for (int mt = 0; mt < 2; mt++)
                #pragma unroll
                for (int nt = 0; nt < 8; nt++)
                    #pragma unroll
                    for (int q = 0; q < 4; q++) acc[mt][nt][q] = 0.0f;

            for (int kc2 = 0; kc2 < 2; kc2++){
                #pragma unroll
                for (int it = 0; it < 4; it++){
                    int idx = it*256 + tid;
                    int r = idx >> 3, c8 = (idx & 7) << 3;
                    uint32_t so = (uint32_t)((r*AS + c8)*2);
                    cp16(sbase + BBASE + so,         B1 + (size_t)(cofs+r)*Ktot + kc2*64 + c8);
                    cp16(sbase + BBASE + PANEL + so, B2 + (size_t)(cofs+r)*Ktot + kc2*64 + c8);
                }
                CPCOMMIT();
                CPWAIT0();
                __syncthreads();

                uint32_t abase = sbase + kc2*(2*PANEL) + aoff0;
                #pragma unroll
                for (int k16 = 0; k16 < 64; k16 += 16){
                    uint32_t a1f[2][4], a2f[2][4];
                    #pragma unroll
                    for (int mt = 0; mt < 2; mt++){
                        uint32_t ad = abase + (uint32_t)((mt*16*AS + k16) * 2);
                        ldsm_x4(a1f[mt], ad);
                        ldsm_x4(a2f[mt], ad + PANEL);
                    }
                    #pragma unroll
                    for (int nt = 0; nt < 8; nt++){
                        uint32_t bd = boff + (uint32_t)((nt*8*AS + k16) * 2);
                        uint32_t b1f[2], b2f[2];
                        ldsm_x2(b1f, bd);
                        ldsm_x2(b2f, bd + PANEL);
                        mma16816(acc[0][nt], a1f[0], b1f);
                        mma16816(acc[1][nt], a1f[1], b1f);
                        mma16816(acc[0][nt], a2f[0], b1f);
                        mma16816(acc[1][nt], a2f[1], b1f);
                        mma16816(acc[0][nt], a1f[0], b2f);
                        mma16816(acc[1][nt], a1f[1], b2f);
                    }
                }
                __syncthreads();
            }
            gemm_epilogue(acc, row0, cofs, bias, Cout, ldc, O1, O2, ldo,
                          lnw, lnb, red, flags, lane, warpM, warpN);
            __syncthreads();
        }
    } else {
        const int cofs = blockIdx.y*128;
        #pragma unroll
        for (int mt = 0; mt < 2; mt++)
            #pragma unroll
            for (int nt = 0; nt < 8; nt++)
                #pragma unroll
                for (int q = 0; q < 4; q++) acc[mt][nt][q] = 0.0f;

        for (int kc = 0; kc < Ktot; kc += 64){
            #pragma unroll
            for (int it = 0; it < 4; it++){
                int idx = it*256 + tid;
                int r = idx >> 3, c8 = (idx & 7) << 3;
                uint32_t so = (uint32_t)((r*AS + c8)*2);
                cp16(sbase + so, A1 + (size_t)(row0+r)*lda + kc + c8);
                if (A2ON) cp16(sbase + PANEL + so, A2 + (size_t)(row0+r)*lda + kc + c8);
                cp16(sbase + 2*PANEL + so, B1 + (size_t)(cofs+r)*Ktot + kc + c8);
                cp16(sbase + 3*PANEL + so, B2 + (size_t)(cofs+r)*Ktot + kc + c8);
            }
            CPCOMMIT();
            CPWAIT0();
            __syncthreads();

            #pragma unroll
            for (int k16 = 0; k16 < 64; k16 += 16){
                uint32_t a1f[2][4], a2f[2][4];
                #pragma unroll
                for (int mt = 0; mt < 2; mt++){
                    uint32_t ad = sbase + aoff0 + (uint32_t)((mt*16*AS + k16) * 2);
                    ldsm_x4(a1f[mt], ad);
                    if (A2ON) ldsm_x4(a2f[mt], ad + PANEL);
                }
                #pragma unroll
                for (int nt = 0; nt < 8; nt++){
                    uint32_t bd = boff + (uint32_t)((nt*8*AS + k16) * 2);
                    uint32_t b1f[2], b2f[2];
                    ldsm_x2(b1f, bd);
                    ldsm_x2(b2f, bd + PANEL);
                    mma16816(acc[0][nt], a1f[0], b1f);
                    mma16816(acc[1][nt], a1f[1], b1f);
                    if (A2ON){
                        mma16816(acc[0][nt], a2f[0], b1f);
                        mma16816(acc[1][nt], a2f[1], b1f);
                    }
                    mma16816(acc[0][nt], a1f[0], b2f);
                    mma16816(acc[1][nt], a1f[1], b2f);
                }
            }
            __syncthreads();
        }
        gemm_epilogue(acc, row0, cofs, bias, Cout, ldc, O1, O2, ldo,
                      lnw, lnb, red, flags, lane, warpM, warpN);
    }
}

// ---------------- launch ----------------
extern "C" void kernel_launch(void* const* d_in, const int* in_sizes, int n_in,
                              void* d_out, int out_size){
    const float* x    = (const float*)d_in[0];
    const int*   li   = (const int*)  d_in[1];
    const float* ob   = (const float*)d_in[2];
    const float* dw   = (const float*)d_in[3];
    const float* db   = (const float*)d_in[4];
    const float* ln1w = (const float*)d_in[5];
    const float* ln1b = (const float*)d_in[6];
    const float* wqkv = (const float*)d_in[7];
    const float* bqkv = (const float*)d_in[8];
    const float* wo   = (const float*)d_in[9];
    const float* bo   = (const float*)d_in[10];
    const float* ln2w = (const float*)d_in[11];
    const float* ln2b = (const float*)d_in[12];
    const float* w1   = (const float*)d_in[13];
    const float* b1   = (const float*)d_in[14];
    const float* w2   = (const float*)d_in[15];
    const float* b2   = (const float*)d_in[16];
    const float* pw   = (const float*)d_in[17];
    const float* pb   = (const float*)d_in[18];
    int n = in_sizes[0] / DIM;

    bf16 *a1, *a2, *h1a, *fa1, *fa2;
    bf16 *wqT1, *wqT2, *woT1, *woT2, *w1T1, *w1T2, *w2T1, *w2T2, *pT1, *pT2;
    float *h, *qkv;
    cudaGetSymbolAddress((void**)&a1,  g_a1);  cudaGetSymbolAddress((void**)&a2,  g_a2);
    cudaGetSymbolAddress((void**)&h1a, g_h1a);
    cudaGetSymbolAddress((void**)&fa1, g_fa1); cudaGetSymbolAddress((void**)&fa2, g_fa2);
    cudaGetSymbolAddress((void**)&wqT1, g_wqkvT1); cudaGetSymbolAddress((void**)&wqT2, g_wqkvT2);
    cudaGetSymbolAddress((void**)&woT1, g_woT1);   cudaGetSymbolAddress((void**)&woT2, g_woT2);
    cudaGetSymbolAddress((void**)&w1T1, g_w1T1);   cudaGetSymbolAddress((void**)&w1T2, g_w1T2);
    cudaGetSymbolAddress((void**)&w2T1, g_w2T1);   cudaGetSymbolAddress((void**)&w2T2, g_w2T2);
    cudaGetSymbolAddress((void**)&pT1, g_pT1);     cudaGetSymbolAddress((void**)&pT2, g_pT2);
    cudaGetSymbolAddress((void**)&h, g_h);         cudaGetSymbolAddress((void**)&qkv, g_qkv);

    const int SMEM_ARES = 6*PANEL + 2048;   // 112640
    const int SMEM_STRM = 4*PANEL + 2048;   // 75776
    cudaFuncSetAttribute(k_gemm<true,true>,   cudaFuncAttributeMaxDynamicSharedMemorySize, SMEM_ARES);
    cudaFuncSetAttribute(k_gemm<false,true>,  cudaFuncAttributeMaxDynamicSharedMemorySize, SMEM_STRM);
    cudaFuncSetAttribute(k_gemm<false,false>, cudaFuncAttributeMaxDynamicSharedMemorySize, SMEM_STRM);

    // setup
    k_zero<<<(BALL+255)/256, 256>>>();
    k_scatter<<<(n+255)/256, 256>>>(li, n);
    k_bg<<<2, 256>>>(ob, dw, db);
    k_select<<<(BALL+255)/256, 256>>>();
    k_assemble<<<(NROW*DIM+255)/256, 256>>>(x);

    // weight transpose+split
    k_tsplit<<<dim3(64, DEPTH), 256>>>(wqkv, wqT1, wqT2, DIM, 3*DIM);
    k_tsplit<<<dim3(32, DEPTH), 256>>>(wo,   woT1, woT2, DIM, DIM);
    k_tsplit<<<dim3(64, DEPTH), 256>>>(w1,   w1T1, w1T2, DIM, HID);
    k_tsplit<<<dim3(64, DEPTH), 256>>>(w2,   w2T1, w2T2, HID, DIM);
    k_tsplit<<<dim3(256, 1),    256>>>(pw,   pT1,  pT2,  HID, CLV);

    // initial LN (layer 0); later LNs fused into wo/w2 epilogues
    k_ln_split<<<NROW/8, 256>>>(ln1w, ln1b);

    const int MB = NROW/128;   // 720
    for (int L = 0; L < DEPTH; L++){
        // qkv: A-resident, internal ny=3
        k_gemm<true,true><<<MB, 256, SMEM_ARES>>>(a1, a2, DIM,
            wqT1 + (size_t)L*3*DIM*DIM, wqT2 + (size_t)L*3*DIM*DIM,
            bqkv + L*3*DIM, qkv, 3*DIM, (bf16*)0, (bf16*)0, 0,
            (float*)0, (float*)0, DIM, 3, 0);
        k_attn<<<BALL/8, 256>>>();
        // wo + residual + fused ln2 -> a1/a2
        k_gemm<false,true><<<dim3(MB,1), 256, SMEM_STRM>>>(a1, a2, DIM,
            woT1 + (size_t)L*DIM*DIM, woT2 + (size_t)L*DIM*DIM,
            bo + L*DIM, h, DIM, a1, a2, DIM,
            ln2w + L*DIM, ln2b + L*DIM, DIM, 1, GF_ACCUM|GF_LN);
        // w1: A-resident, internal ny=4, gelu, single-bf16 out
        k_gemm<true,true><<<MB, 256, SMEM_ARES>>>(a1, a2, DIM,
            w1T1 + (size_t)L*HID*DIM, w1T2 + (size_t)L*HID*DIM,
            b1 + L*HID, (float*)0, 0, h1a, (bf16*)0, HID,
            (float*)0, (float*)0, DIM, 4, GF_GELU|GF_B16);
        // w2: 2-term (A single bf16), streaming
        if (L < DEPTH-1){
            k_gemm<false,false><<<dim3(MB,1), 256, SMEM_STRM>>>(h1a, (bf16*)0, HID,
                w2T1 + (size_t)L*DIM*HID, w2T2 + (size_t)L*DIM*HID,
                b2 + L*DIM, h, DIM, a1, a2, DIM,
                ln1w + (L+1)*DIM, ln1b + (L+1)*DIM, HID, 1, GF_ACCUM|GF_LN);
        } else {
            k_gemm<false,false><<<dim3(MB,1), 256, SMEM_STRM>>>(h1a, (bf16*)0, HID,
                w2T1 + (size_t)L*DIM*HID, w2T2 + (size_t)L*DIM*HID,
                b2 + L*DIM, h, DIM, (bf16*)0, (bf16*)0, 0,
                (float*)0, (float*)0, HID, 1, GF_ACCUM);
        }
    }

    k_split_feat<<<(BALL*HID+255)/256, 256>>>();
    k_gemm<false,true><<<dim3(BALL/128, CLV/128), 256, SMEM_STRM>>>(fa1, fa2, HID,
        pT1, pT2, pb, (float*)d_out, CLV, (bf16*)0, (bf16*)0, 0,
        (float*)0, (float*)0, HID, 1, GF_MASK);
}

// round 12
// speedup vs baseline: 2.8974x; 1.0560x over previous
#include <cuda_runtime.h>
#include <cuda_bf16.h>
#include <cstdint>
#include <math.h>

#define DD     5
#define HGRID  24
#define WGRID  48
#define CLV    1024
#define NB     4
#define DIM    128
#define LMAX   12
#define DEPTH  6
#define LTOK   16
#define BALL   (DD*HGRID*WGRID)   // 5760
#define NROW   (BALL*LTOK)        // 92160
#define CAP    64
#define HID    512
#define AS     72                 // smem row stride in bf16 (144B: conflict-free ldmatrix)
#define PANEL  18432              // bytes per 128x64 panel
#define PANELW 9216               // bf16 elems per panel

typedef __nv_bfloat16 bf16;

// ---------------- device scratch ----------------
__device__ int   g_counts[BALL];
__device__ int   g_list[BALL*CAP];
__device__ int   g_sel[BALL*LMAX];
__device__ int   g_m[BALL];
__device__ float g_bgp[NB*DIM];
__device__ float g_h[NROW*DIM];
__device__ float g_qkv[NROW*3*DIM];
__device__ bf16  g_a1[NROW*DIM],  g_a2[NROW*DIM];
__device__ bf16  g_h1a[NROW*HID];                 // single-bf16 gelu(h1)
__device__ bf16  g_fa1[BALL*HID], g_fa2[BALL*HID];
// transposed + split weights: [n][k] k-fast
__device__ bf16  g_wqkvT1[DEPTH*3*DIM*DIM], g_wqkvT2[DEPTH*3*DIM*DIM];
__device__ bf16  g_woT1[DEPTH*DIM*DIM],     g_woT2[DEPTH*DIM*DIM];
__device__ bf16  g_w1T1[DEPTH*HID*DIM],     g_w1T2[DEPTH*HID*DIM];
__device__ bf16  g_w2T1[DEPTH*DIM*HID],     g_w2T2[DEPTH*DIM*HID];
__device__ bf16  g_pT1[CLV*HID],            g_pT2[CLV*HID];

// ---------------- helpers ----------------
__device__ __forceinline__ uint32_t s2u(const void* p){
    uint32_t a;
    asm("{ .reg .u64 t; cvta.to.shared.u64 t, %1; cvt.u32.u64 %0, t; }" : "=r"(a) : "l"(p));
    return a;
}
__device__ __forceinline__ void cp16(uint32_t dst, const void* src){
    asm volatile("cp.async.cg.shared.global [%0], [%1], 16;" :: "r"(dst), "l"(src));
}
#define CPCOMMIT() asm volatile("cp.async.commit_group;" ::: "memory")
#define CPWAIT0()  asm volatile("cp.async.wait_group 0;" ::: "memory")
__device__ __forceinline__ void ldsm_x4(uint32_t* d, uint32_t addr){
    asm volatile("ldmatrix.sync.aligned.m8n8.x4.shared.b16 {%0,%1,%2,%3}, [%4];"
        : "=r"(d[0]),"=r"(d[1]),"=r"(d[2]),"=r"(d[3]) : "r"(addr));
}
__device__ __forceinline__ void ldsm_x2(uint32_t* d, uint32_t addr){
    asm volatile("ldmatrix.sync.aligned.m8n8.x2.shared.b16 {%0,%1}, [%2];"
        : "=r"(d[0]),"=r"(d[1]) : "r"(addr));
}
__device__ __forceinline__ void mma16816(float* c, const uint32_t* a, const uint32_t* b){
    asm volatile("mma.sync.aligned.m16n8k16.row.col.f32.bf16.bf16.f32 "
        "{%0,%1,%2,%3}, {%4,%5,%6,%7}, {%8,%9}, {%0,%1,%2,%3};"
        : "+f"(c[0]),"+f"(c[1]),"+f"(c[2]),"+f"(c[3])
        : "r"(a[0]),"r"(a[1]),"r"(a[2]),"r"(a[3]), "r"(b[0]),"r"(b[1]));
}
__device__ __forceinline__ float gelu_f(float x){
    float x3 = x*x*x;
    return 0.5f*x*(1.0f + tanhf(0.7978845608028654f*(x + 0.044715f*x3)));
}
__device__ __forceinline__ void split1(float v, bf16 &h, bf16 &l){
    h = __float2bfloat16(v);
    l = __float2bfloat16(v - __bfloat162float(h));
}

#define GF_ACCUM   1
#define GF_GELU    2
#define GF_SPLIT   4
#define GF_MASK    8
#define GF_LN      16
#define GF_B16     32
#define GF_SMEMOUT 64

// ---------------- setup kernels ----------------
__global__ void k_zero(){
    int i = blockIdx.x*blockDim.x + threadIdx.x;
    if (i < BALL) g_counts[i] = 0;
}
__global__ void k_scatter(const int* __restrict__ li, int n){
    int i = blockIdx.x*blockDim.x + threadIdx.x;
    if (i >= n) return;
    int flat = li[3*i]*(HGRID*WGRID) + li[3*i+1]*WGRID + li[3*i+2];
    int slot = atomicAdd(&g_counts[flat], 1);
    if (slot < CAP) g_list[flat*CAP + slot] = i;
}
__global__ void k_bg(const float* __restrict__ ob, const float* __restrict__ dw,
                     const float* __restrict__ db){
    int c = blockIdx.x*blockDim.x + threadIdx.x;
    if (c >= NB*DIM) return;
    float s = 0.0f;
    for (int m = 0; m < NB; m++){
        const float* bg = ob + m*DIM;
        float t = 0.0f;
        for (int k = 0; k < DIM; k++) t += bg[k] * dw[k*(NB*DIM) + c];
        s += t;
    }
    g_bgp[c] = ob[c] + s*(1.0f/NB) + db[c];
}
__global__ void k_select(){
    int cell = blockIdx.x*blockDim.x + threadIdx.x;
    if (cell >= BALL) return;
    int cnt = g_counts[cell];
    int avail = min(cnt, CAP);
    int m = min(cnt, LMAX);
    g_m[cell] = m;
    if (cnt <= LMAX){
        for (int j = 0; j < m; j++) g_sel[cell*LMAX + j] = g_list[cell*CAP + j];
    } else {
        int tmp[CAP];
        for (int j = 0; j < avail; j++) tmp[j] = g_list[cell*CAP + j];
        for (int a = 0; a < m; a++){
            int best = a;
            for (int b = a+1; b < avail; b++) if (tmp[b] < tmp[best]) best = b;
            int t = tmp[best]; tmp[best] = tmp[a]; tmp[a] = t;
            g_sel[cell*LMAX + a] = t;
        }
    }
}
__global__ void k_assemble(const float* __restrict__ x){
    int idx = blockIdx.x*blockDim.x + threadIdx.x;
    if (idx >= NROW*DIM) return;
    int row = idx >> 7, d = idx & 127;
    int cell = row >> 4, lr = row & 15;
    float v;
    if (lr < NB) v = g_bgp[lr*DIM + d];
    else {
        int j = lr - NB;
        v = (j < g_m[cell]) ? x[(size_t)g_sel[cell*LMAX + j]*DIM + d] : 0.0f;
    }
    g_h[idx] = v;
}
__global__ void k_tsplit(const float* __restrict__ W, bf16* __restrict__ T1,
                         bf16* __restrict__ T2, int K, int N){
    size_t off = (size_t)blockIdx.y * K * N;
    W += off; T1 += off; T2 += off;
    int tot = K*N;
    for (int idx = blockIdx.x*blockDim.x + threadIdx.x; idx < tot;
         idx += gridDim.x*blockDim.x){
        int n = idx / K, k = idx - n*K;
        float v = W[(size_t)k*N + n];
        bf16 h, l; split1(v, h, l);
        T1[idx] = h; T2[idx] = l;
    }
}
// LayerNorm + bf16 split (layer 0 only)
__global__ void k_ln_split(const float* __restrict__ w, const float* __restrict__ b){
    int warp = threadIdx.x >> 5, lane = threadIdx.x & 31;
    int row = blockIdx.x*8 + warp;
    const float* src = g_h + (size_t)row*DIM;
    float4 v = *(const float4*)(src + lane*4);
    float s  = v.x+v.y+v.z+v.w;
    float ss = v.x*v.x+v.y*v.y+v.z*v.z+v.w*v.w;
    #pragma unroll
    for (int o = 16; o; o >>= 1){
        s  += __shfl_xor_sync(0xffffffffu, s,  o);
        ss += __shfl_xor_sync(0xffffffffu, ss, o);
    }
    float mean = s*(1.0f/DIM);
    float var  = ss*(1.0f/DIM) - mean*mean;
    float rstd = rsqrtf(var + 1e-5f);
    float4 wv = *(const float4*)(w + lane*4);
    float4 bv = *(const float4*)(b + lane*4);
    float n0 = (v.x-mean)*rstd*wv.x + bv.x;
    float n1 = (v.y-mean)*rstd*wv.y + bv.y;
    float n2 = (v.z-mean)*rstd*wv.z + bv.z;
    float n3 = (v.w-mean)*rstd*wv.w + bv.w;
    bf16 h0,l0,h1,l1,h2,l2,h3,l3;
    split1(n0,h0,l0); split1(n1,h1,l1); split1(n2,h2,l2); split1(n3,h3,l3);
    __nv_bfloat162* d1 = (__nv_bfloat162*)(g_a1 + (size_t)row*DIM + lane*4);
    __nv_bfloat162* d2 = (__nv_bfloat162*)(g_a2 + (size_t)row*DIM + lane*4);
    __nv_bfloat162 p;
    p.x=h0; p.y=h1; d1[0]=p;  p.x=h2; p.y=h3; d1[1]=p;
    p.x=l0; p.y=l1; d2[0]=p;  p.x=l2; p.y=l3; d2[1]=p;
}
// attention
__global__ void k_attn(){
    int warp = threadIdx.x >> 5, lane = threadIdx.x & 31;
    int cell = blockIdx.x*8 + warp;
    int qoff = ((lane >> 3) << 5) + ((lane & 7) << 2);
    const float scale = 0.17677669529663687f;
    size_t base = (size_t)cell*LTOK;
    for (int r = 0; r < LTOK; r++){
        float4 q4 = *(const float4*)(g_qkv + (base+r)*384 + qoff);
        float sc[LTOK]; float mx = -1e30f;
        #pragma unroll
        for (int j = 0; j < LTOK; j++){
            float4 k4 = *(const float4*)(g_qkv + (base+j)*384 + 128 + qoff);
            float sdot = q4.x*k4.x + q4.y*k4.y + q4.z*k4.z + q4.w*k4.w;
            sdot += __shfl_xor_sync(0xffffffffu, sdot, 1);
            sdot += __shfl_xor_sync(0xffffffffu, sdot, 2);
            sdot += __shfl_xor_sync(0xffffffffu, sdot, 4);
            sdot *= scale;
            sc[j] = sdot; mx = fmaxf(mx, sdot);
        }
        float den = 0.0f;
        #pragma unroll
        for (int j = 0; j < LTOK; j++){ sc[j] = __expf(sc[j]-mx); den += sc[j]; }
        float inv = __fdividef(1.0f, den);
        float4 o = make_float4(0.f,0.f,0.f,0.f);
        #pragma unroll
        for (int j = 0; j < LTOK; j++){
            float p = sc[j]*inv;
            float4 v4 = *(const float4*)(g_qkv + (base+j)*384 + 256 + qoff);
            o.x += p*v4.x; o.y += p*v4.y; o.z += p*v4.z; o.w += p*v4.w;
        }
        bf16 h0,l0,h1,l1,h2,l2,h3,l3;
        split1(o.x,h0,l0); split1(o.y,h1,l1); split1(o.z,h2,l2); split1(o.w,h3,l3);
        __nv_bfloat162* d1 = (__nv_bfloat162*)(g_a1 + (base+r)*DIM + qoff);
        __nv_bfloat162* d2 = (__nv_bfloat162*)(g_a2 + (base+r)*DIM + qoff);
        __nv_bfloat162 p;
        p.x=h0; p.y=h1; d1[0]=p;  p.x=h2; p.y=h3; d1[1]=p;
        p.x=l0; p.y=l1; d2[0]=p;  p.x=l2; p.y=l3; d2[1]=p;
    }
}
__global__ void k_split_feat(){
    int idx = blockIdx.x*blockDim.x + threadIdx.x;
    if (idx >= BALL*HID) return;
    int cell = idx >> 9, k = idx & 511;
    float v = g_h[(size_t)cell*(LTOK*DIM) + k];
    bf16 h, l; split1(v, h, l);
    g_fa1[idx] = h; g_fa2[idx] = l;
}

// ---------------- shared MMA chunk over one 64-k slab in smem ----------------
// abase: A1 lane addr (A2 at +PANEL). bbase: B1 lane addr (B2 at +PANEL).
template<bool A2ON>
__device__ __forceinline__ void chunk_mma(float (&acc)[2][8][4],
                                          uint32_t abase, uint32_t bbase){
    #pragma unroll
    for (int k16 = 0; k16 < 64; k16 += 16){
        uint32_t a1f[2][4], a2f[2][4];
        #pragma unroll
        for (int mt = 0; mt < 2; mt++){
            uint32_t ad = abase + (uint32_t)((mt*16*AS + k16) * 2);
            ldsm_x4(a1f[mt], ad);
            if (A2ON) ldsm_x4(a2f[mt], ad + PANEL);
        }
        #pragma unroll
        for (int nt = 0; nt < 8; nt++){
            uint32_t bd = bbase + (uint32_t)((nt*8*AS + k16) * 2);
            uint32_t b1f[2], b2f[2];
            ldsm_x2(b1f, bd);
            ldsm_x2(b2f, bd + PANEL);
            mma16816(acc[0][nt], a1f[0], b1f);
            mma16816(acc[1][nt], a1f[1], b1f);
            if (A2ON){
                mma16816(acc[0][nt], a2f[0], b1f);
                mma16816(acc[1][nt], a2f[1], b1f);
            }
            mma16816(acc[0][nt], a1f[0], b2f);
            mma16816(acc[1][nt], a1f[1], b2f);
        }
    }
}

// ---------------- shared epilogue ----------------
__device__ __forceinline__ void gemm_epilogue(
    float (&acc)[2][8][4], int row0, int cofs,
    const float* __restrict__ bias,
    float* __restrict__ Cout, int ldc,
    bf16* __restrict__ O1, bf16* __restrict__ O2, int ldo,
    const float* __restrict__ lnw, const float* __restrict__ lnb,
    float2* red, int flags, int lane, int warpM, int warpN,
    bf16* smem_bf)
{
    const int l4 = lane >> 2, l2 = (lane & 3) << 1;

    if (flags & GF_LN){
        #pragma unroll
        for (int mt = 0; mt < 2; mt++){
            #pragma unroll
            for (int hh = 0; hh < 2; hh++){
                int rl = warpM*32 + mt*16 + hh*8 + l4;
                int rg = row0 + rl;
                float s = 0.0f, ss = 0.0f;
                #pragma unroll
                for (int nt = 0; nt < 8; nt++){
                    int cg = warpN*64 + nt*8 + l2;
                    float2 old = *(const float2*)(Cout + (size_t)rg*ldc + cg);
                    float v0 = acc[mt][nt][hh*2+0] + bias[cg]   + old.x;
                    float v1 = acc[mt][nt][hh*2+1] + bias[cg+1] + old.y;
                    acc[mt][nt][hh*2+0] = v0;
                    acc[mt][nt][hh*2+1] = v1;
                    *(float2*)(Cout + (size_t)rg*ldc + cg) = make_float2(v0, v1);
                    s += v0 + v1; ss += v0*v0 + v1*v1;
                }
                s  += __shfl_xor_sync(0xffffffffu, s,  1);
                ss += __shfl_xor_sync(0xffffffffu, ss, 1);
                s  += __shfl_xor_sync(0xffffffffu, s,  2);
                ss += __shfl_xor_sync(0xffffffffu, ss, 2);
                if ((lane & 3) == 0) red[rl*2 + warpN] = make_float2(s, ss);
            }
        }
        __syncthreads();
        #pragma unroll
        for (int mt = 0; mt < 2; mt++){
            #pragma unroll
            for (int hh = 0; hh < 2; hh++){
                int rl = warpM*32 + mt*16 + hh*8 + l4;
                int rg = row0 + rl;
                float2 r0 = red[rl*2 + 0], r1 = red[rl*2 + 1];
                float mean = (r0.x + r1.x) * (1.0f/DIM);
                float var  = (r0.y + r1.y) * (1.0f/DIM) - mean*mean;
                float rstd = rsqrtf(var + 1e-5f);
                #pragma unroll
                for (int nt = 0; nt < 8; nt++){
                    int cg = warpN*64 + nt*8 + l2;
                    float n0 = (acc[mt][nt][hh*2+0] - mean)*rstd*lnw[cg]   + lnb[cg];
                    float n1 = (acc[mt][nt][hh*2+1] - mean)*rstd*lnw[cg+1] + lnb[cg+1];
                    bf16 ha,la,hb,lb;
                    split1(n0, ha, la); split1(n1, hb, lb);
                    __nv_bfloat162 p, q;
                    p.x=ha; p.y=hb; q.x=la; q.y=lb;
                    if (flags & GF_SMEMOUT){
                        int p0 = (cg >> 6) * 2;
                        int c63 = cg & 63;
                        *(__nv_bfloat162*)(smem_bf + p0*PANELW     + rl*AS + c63) = p;
                        *(__nv_bfloat162*)(smem_bf + (p0+1)*PANELW + rl*AS + c63) = q;
                    } else {
                        *(__nv_bfloat162*)(O1 + (size_t)rg*ldo + cg) = p;
                        *(__nv_bfloat162*)(O2 + (size_t)rg*ldo + cg) = q;
                    }
                }
            }
        }
        return;
    }

    #pragma unroll
    for (int mt = 0; mt < 2; mt++){
        #pragma unroll
        for (int hh = 0; hh < 2; hh++){
            int rg = row0 + warpM*32 + mt*16 + l4 + hh*8;
            bool maskz = (flags & GF_MASK) && (g_counts[rg] == 0);
            #pragma unroll
            for (int nt = 0; nt < 8; nt++){
                int cg = cofs + warpN*64 + nt*8 + l2;
                float v0 = acc[mt][nt][hh*2+0] + bias[cg];
                float v1 = acc[mt][nt][hh*2+1] + bias[cg+1];
                if (flags & GF_GELU){ v0 = gelu_f(v0); v1 = gelu_f(v1); }
                if (flags & GF_ACCUM){
                    float2 old = *(const float2*)(Cout + (size_t)rg*ldc + cg);
                    v0 += old.x; v1 += old.y;
                }
                if (flags & GF_SPLIT){
                    bf16 ha,la,hb,lb;
                    split1(v0, ha, la); split1(v1, hb, lb);
                    __nv_bfloat162 p;
                    p.x=ha; p.y=hb; *(__nv_bfloat162*)(O1 + (size_t)rg*ldo + cg) = p;
                    p.x=la; p.y=lb; *(__nv_bfloat162*)(O2 + (size_t)rg*ldo + cg) = p;
                } else if (flags & GF_B16){
                    __nv_bfloat162 p;
                    p.x = __float2bfloat16(v0); p.y = __float2bfloat16(v1);
                    *(__nv_bfloat162*)(O1 + (size_t)rg*ldo + cg) = p;
                } else {
                    float2 ov = maskz ? make_float2(0.f, 0.f) : make_float2(v0, v1);
                    *(float2*)(Cout + (size_t)rg*ldc + cg) = ov;
                }
            }
        }
    }
}

// ---------------- standalone mma.sync GEMM (L0 qkv, final w2, proj) ----------------
template<bool ARES, bool A2ON>
__global__ __launch_bounds__(256, 2)
void k_gemm(const bf16* __restrict__ A1, const bf16* __restrict__ A2, int lda,
            const bf16* __restrict__ B1, const bf16* __restrict__ B2,
            const float* __restrict__ bias,
            float* __restrict__ Cout, int ldc,
            bf16* __restrict__ O1, bf16* __restrict__ O2, int ldo,
            const float* __restrict__ lnw, const float* __restrict__ lnb,
            int Ktot, int ny, int flags){
    extern __shared__ bf16 smem[];
    const int tid = threadIdx.x, lane = tid & 31, wid = tid >> 5;
    const int warpM = wid & 3, warpN = wid >> 2;
    const int row0 = blockIdx.x*128;
    const uint32_t sbase = s2u(smem);
    const uint32_t BBASE = ARES ? 4*PANEL : 2*PANEL;
    float2* red = (float2*)((char*)smem + (ARES ? 6*PANEL : 4*PANEL));

    const int rowA = lane & 15, kA8 = (lane >> 4) << 3;
    const int rowB = lane & 7,  kB8 = ((lane >> 3) & 1) << 3;
    const uint32_t aoff0 = (uint32_t)(((warpM*32 + rowA)*AS + kA8) * 2);
    const uint32_t boff  = sbase + BBASE + (uint32_t)(((warpN*64 + rowB)*AS + kB8) * 2);

    float acc[2][8][4];

    if (ARES){
        #pragma unroll
        for (int p = 0; p < 4; p++){
            int chunk = p >> 1;
            const bf16* src = (p & 1) ? A2 : A1;
            #pragma unroll
            for (int it = 0; it < 4; it++){
                int idx = it*256 + tid;
                int r = idx >> 3, c8 = (idx & 7) << 3;
                cp16(sbase + p*PANEL + (uint32_t)((r*AS + c8)*2),
                     src + (size_t)(row0+r)*lda + chunk*64 + c8);
            }
        }
        CPCOMMIT();

        for (int nb = 0; nb < ny; nb++){
            int cofs = nb*128;
            #pragma unroll
            for (int mt = 0; mt < 2; mt++)
                #pragma unroll
                for (int nt = 0; nt < 8; nt++)
                    #pragma unroll
                    for (int q = 0; q < 4; q++) acc[mt][nt][q] = 0.0f;

            for (int kc2 = 0; kc2 < 2; kc2++){
                #pragma unroll
                for (int it = 0; it < 4; it++){
                    int idx = it*256 + tid;
                    int r = idx >> 3, c8 = (idx & 7) << 3;
                    uint32_t so = (uint32_t)((r*AS + c8)*2);
                    cp16(sbase + BBASE + so,         B1 + (size_t)(cofs+r)*Ktot + kc2*64 + c8);
                    cp16(sbase + BBASE + PANEL + so, B2 + (size_t)(cofs+r)*Ktot + kc2*64 + c8);
                }
                CPCOMMIT();
                CPWAIT0();
                __syncthreads();
                chunk_mma<true>(acc, sbase + (uint32_t)(kc2*2*PANEL) + aoff0, boff);
                __syncthreads();
            }
            gemm_epilogue(acc, row0, cofs, bias, Cout, ldc, O1, O2, ldo,
                          lnw, lnb, red, flags, lane, warpM, warpN, smem);
            __syncthreads();
        }
    } else {
        const int cofs = blockIdx.y*128;
        #pragma unroll
        for (int mt = 0; mt < 2; mt++)
            #pragma unroll
            for (int nt = 0; nt < 8; nt++)
                #pragma unroll
                for (int q = 0; q < 4; q++) acc[mt][nt][q] = 0.0f;

        for (int kc = 0; kc < Ktot; kc += 64){
            #pragma unroll
            for (int it = 0; it < 4; it++){
                int idx = it*256 + tid;
                int r = idx >> 3, c8 = (idx & 7) << 3;
                uint32_t so = (uint32_t)((r*AS + c8)*2);
                cp16(sbase + so, A1 + (size_t)(row0+r)*lda + kc + c8);
                if (A2ON) cp16(sbase + PANEL + so, A2 + (size_t)(row0+r)*lda + kc + c8);
                cp16(sbase + 2*PANEL + so, B1 + (size_t)(cofs+r)*Ktot + kc + c8);
                cp16(sbase + 3*PANEL + so, B2 + (size_t)(cofs+r)*Ktot + kc + c8);
            }
            CPCOMMIT();
            CPWAIT0();
            __syncthreads();
            chunk_mma<A2ON>(acc, sbase + aoff0, boff);
            __syncthreads();
        }
        gemm_epilogue(acc, row0, cofs, bias, Cout, ldc, O1, O2, ldo,
                      lnw, lnb, red, flags, lane, warpM, warpN, smem);
    }
}

// ---------------- fused kernel: streaming GEMM + LN -> smem + A-resident GEMM -----
// Phase 1: C128 = A(global, Ktot=KW) @ Bw^T + biasW + residual(hres); LN -> smem panels.
// Phase 2: NY2 N-blocks of (LN out) @ B2^T from smem; epilogue flags2.
template<int KW, bool A2W, int NY2>
__global__ __launch_bounds__(256, 2)
void k_fused(const bf16* __restrict__ A1, const bf16* __restrict__ A2, int lda,
             const bf16* __restrict__ Bw1, const bf16* __restrict__ Bw2,
             const float* __restrict__ biasW,
             float* __restrict__ hres,
             const float* __restrict__ lnw, const float* __restrict__ lnb,
             const bf16* __restrict__ B21, const bf16* __restrict__ B22,
             const float* __restrict__ bias2,
             float* __restrict__ C2, int ldc2,
             bf16* __restrict__ O2b, int ldo2,
             int flags2){
    extern __shared__ bf16 smem[];
    const int tid = threadIdx.x, lane = tid & 31, wid = tid >> 5;
    const int warpM = wid & 3, warpN = wid >> 2;
    const int row0 = blockIdx.x*128;
    const uint32_t sbase = s2u(smem);
    float2* red = (float2*)((char*)smem + 6*PANEL);

    const int rowA = lane & 15, kA8 = (lane >> 4) << 3;
    const int rowB = lane & 7,  kB8 = ((lane >> 3) & 1) << 3;
    const uint32_t aoff0 = (uint32_t)(((warpM*32 + rowA)*AS + kA8) * 2);
    const uint32_t boffB = sbase + 4*PANEL + (uint32_t)(((warpN*64 + rowB)*AS + kB8) * 2);

    float acc[2][8][4];

    // ---- phase 1 ----
    #pragma unroll
    for (int mt = 0; mt < 2; mt++)
        #pragma unroll
        for (int nt = 0; nt < 8; nt++)
            #pragma unroll
            for (int q = 0; q < 4; q++) acc[mt][nt][q] = 0.0f;

    for (int kc = 0; kc < KW; kc += 64){
        #pragma unroll
        for (int it = 0; it < 4; it++){
            int idx = it*256 + tid;
            int r = idx >> 3, c8 = (idx & 7) << 3;
            uint32_t so = (uint32_t)((r*AS + c8)*2);
            cp16(sbase + so, A1 + (size_t)(row0+r)*lda + kc + c8);
            if (A2W) cp16(sbase + PANEL + so, A2 + (size_t)(row0+r)*lda + kc + c8);
            cp16(sbase + 4*PANEL + so, Bw1 + (size_t)r*KW + kc + c8);
            cp16(sbase + 5*PANEL + so, Bw2 + (size_t)r*KW + kc + c8);
        }
        CPCOMMIT();
        CPWAIT0();
        __syncthreads();
        chunk_mma<A2W>(acc, sbase + aoff0, boffB);
        __syncthreads();
    }
    gemm_epilogue(acc, row0, 0, biasW, hres, DIM, (bf16*)0, (bf16*)0, 0,
                  lnw, lnb, red, GF_ACCUM|GF_LN|GF_SMEMOUT, lane, warpM, warpN, smem);
    __syncthreads();

    // ---- phase 2 ----
    for (int nb = 0; nb < NY2; nb++){
        int cofs = nb*128;
        #pragma unroll
        for (int mt = 0; mt < 2; mt++)
            #pragma unroll
            for (int nt = 0; nt < 8; nt++)
                #pragma unroll
                for (int q = 0; q < 4; q++) acc[mt][nt][q] = 0.0f;

        for (int kc2 = 0; kc2 < 2; kc2++){
            #pragma unroll
            for (int it = 0; it < 4; it++){
                int idx = it*256 + tid;
                int r = idx >> 3, c8 = (idx & 7) << 3;
                uint32_t so = (uint32_t)((r*AS + c8)*2);
                cp16(sbase + 4*PANEL + so, B21 + (size_t)(cofs+r)*DIM + kc2*64 + c8);
                cp16(sbase + 5*PANEL + so, B22 + (size_t)(cofs+r)*DIM + kc2*64 + c8);
            }
            CPCOMMIT();
            CPWAIT0();
            __syncthreads();
            chunk_mma<true>(acc, sbase + (uint32_t)(kc2*2*PANEL) + aoff0, boffB);
            __syncthreads();
        }
        gemm_epilogue(acc, row0, cofs, bias2, C2, ldc2, O2b, (bf16*)0, ldo2,
                      (float*)0, (float*)0, red, flags2, lane, warpM, warpN, smem);
        __syncthreads();
    }
}

// ---------------- launch ----------------
extern "C" void kernel_launch(void* const* d_in, const int* in_sizes, int n_in,
                              void* d_out, int out_size){
    const float* x    = (const float*)d_in[0];
    const int*   li   = (const int*)  d_in[1];
    const float* ob   = (const float*)d_in[2];
    const float* dw   = (const float*)d_in[3];
    const float* db   = (const float*)d_in[4];
    const float* ln1w = (const float*)d_in[5];
    const float* ln1b = (const float*)d_in[6];
    const float* wqkv = (const float*)d_in[7];
    const float* bqkv = (const float*)d_in[8];
    const float* wo   = (const float*)d_in[9];
    const float* bo   = (const float*)d_in[10];
    const float* ln2w = (const float*)d_in[11];
    const float* ln2b = (const float*)d_in[12];
    const float* w1   = (const float*)d_in[13];
    const float* b1   = (const float*)d_in[14];
    const float* w2   = (const float*)d_in[15];
    const float* b2   = (const float*)d_in[16];
    const float* pw   = (const float*)d_in[17];
    const float* pb   = (const float*)d_in[18];
    int n = in_sizes[0] / DIM;

    bf16 *a1, *a2, *h1a, *fa1, *fa2;
    bf16 *wqT1, *wqT2, *woT1, *woT2, *w1T1, *w1T2, *w2T1, *w2T2, *pT1, *pT2;
    float *h, *qkv;
    cudaGetSymbolAddress((void**)&a1,  g_a1);  cudaGetSymbolAddress((void**)&a2,  g_a2);
    cudaGetSymbolAddress((void**)&h1a, g_h1a);
    cudaGetSymbolAddress((void**)&fa1, g_fa1); cudaGetSymbolAddress((void**)&fa2, g_fa2);
    cudaGetSymbolAddress((void**)&wqT1, g_wqkvT1); cudaGetSymbolAddress((void**)&wqT2, g_wqkvT2);
    cudaGetSymbolAddress((void**)&woT1, g_woT1);   cudaGetSymbolAddress((void**)&woT2, g_woT2);
    cudaGetSymbolAddress((void**)&w1T1, g_w1T1);   cudaGetSymbolAddress((void**)&w1T2, g_w1T2);
    cudaGetSymbolAddress((void**)&w2T1, g_w2T1);   cudaGetSymbolAddress((void**)&w2T2, g_w2T2);
    cudaGetSymbolAddress((void**)&pT1, g_pT1);     cudaGetSymbolAddress((void**)&pT2, g_pT2);
    cudaGetSymbolAddress((void**)&h, g_h);         cudaGetSymbolAddress((void**)&qkv, g_qkv);

    const int SMEM_ARES = 6*PANEL + 2048;   // 112640
    const int SMEM_STRM = 4*PANEL + 2048;   // 75776
    cudaFuncSetAttribute(k_gemm<true,true>,   cudaFuncAttributeMaxDynamicSharedMemorySize, SMEM_ARES);
    cudaFuncSetAttribute(k_gemm<false,true>,  cudaFuncAttributeMaxDynamicSharedMemorySize, SMEM_STRM);
    cudaFuncSetAttribute(k_gemm<false,false>, cudaFuncAttributeMaxDynamicSharedMemorySize, SMEM_STRM);
    cudaFuncSetAttribute(k_fused<128,true,4>,  cudaFuncAttributeMaxDynamicSharedMemorySize, SMEM_ARES);
    cudaFuncSetAttribute(k_fused<512,false,3>, cudaFuncAttributeMaxDynamicSharedMemorySize, SMEM_ARES);

    // setup
    k_zero<<<(BALL+255)/256, 256>>>();
    k_scatter<<<(n+255)/256, 256>>>(li, n);
    k_bg<<<2, 256>>>(ob, dw, db);
    k_select<<<(BALL+255)/256, 256>>>();
    k_assemble<<<(NROW*DIM+255)/256, 256>>>(x);

    // weight transpose+split
    k_tsplit<<<dim3(64, DEPTH), 256>>>(wqkv, wqT1, wqT2, DIM, 3*DIM);
    k_tsplit<<<dim3(32, DEPTH), 256>>>(wo,   woT1, woT2, DIM, DIM);
    k_tsplit<<<dim3(64, DEPTH), 256>>>(w1,   w1T1, w1T2, DIM, HID);
    k_tsplit<<<dim3(64, DEPTH), 256>>>(w2,   w2T1, w2T2, HID, DIM);
    k_tsplit<<<dim3(256, 1),    256>>>(pw,   pT1,  pT2,  HID, CLV);

    // layer-0 LN + qkv
    k_ln_split<<<NROW/8, 256>>>(ln1w, ln1b);
    const int MB = NROW/128;   // 720
    k_gemm<true,true><<<MB, 256, SMEM_ARES>>>(a1, a2, DIM,
        wqT1, wqT2, bqkv, qkv, 3*DIM, (bf16*)0, (bf16*)0, 0,
        (float*)0, (float*)0, DIM, 3, 0);

    for (int L = 0; L < DEPTH; L++){
        k_attn<<<BALL/8, 256>>>();
        // fused: wo + residual + ln2 -> smem -> w1 (gelu, bf16 out)
        k_fused<128,true,4><<<MB, 256, SMEM_ARES>>>(a1, a2, DIM,
            woT1 + (size_t)L*DIM*DIM, woT2 + (size_t)L*DIM*DIM,
            bo + L*DIM, h, ln2w + L*DIM, ln2b + L*DIM,
            w1T1 + (size_t)L*HID*DIM, w1T2 + (size_t)L*HID*DIM,
            b1 + L*HID, (float*)0, 0, h1a, HID, GF_GELU|GF_B16);
        if (L < DEPTH-1){
            // fused: w2 + residual + ln1(L+1) -> smem -> qkv(L+1)
            k_fused<512,false,3><<<MB, 256, SMEM_ARES>>>(h1a, (bf16*)0, HID,
                w2T1 + (size_t)L*DIM*HID, w2T2 + (size_t)L*DIM*HID,
                b2 + L*DIM, h, ln1w + (L+1)*DIM, ln1b + (L+1)*DIM,
                wqT1 + (size_t)(L+1)*3*DIM*DIM, wqT2 + (size_t)(L+1)*3*DIM*DIM,
                bqkv + (L+1)*3*DIM, qkv, 3*DIM, (bf16*)0, 0, 0);
        } else {
            k_gemm<false,false><<<dim3(MB,1), 256, SMEM_STRM>>>(h1a, (bf16*)0, HID,
                w2T1 + (size_t)L*DIM*HID, w2T2 + (size_t)L*DIM*HID,
                b2 + L*DIM, h, DIM, (bf16*)0, (bf16*)0, 0,
                (float*)0, (float*)0, HID, 1, GF_ACCUM);
        }
    }

    k_split_feat<<<(BALL*HID+255)/256, 256>>>();
    k_gemm<false,true><<<dim3(BALL/128, CLV/128), 256, SMEM_STRM>>>(fa1, fa2, HID,
        pT1, pT2, pb, (float*)d_out, CLV, (bf16*)0, (bf16*)0, 0,
        (float*)0, (float*)0, HID, 1, GF_MASK);
}

// round 15
// speedup vs baseline: 3.2211x; 1.1117x over previous
#include <cuda_runtime.h>
#include <cuda_bf16.h>
#include <cstdint>
#include <math.h>

#define DD     5
#define HGRID  24
#define WGRID  48
#define CLV    1024
#define NB     4
#define DIM    128
#define LMAX   12
#define DEPTH  6
#define LTOK   16
#define BALL   (DD*HGRID*WGRID)   // 5760
#define NROW   (BALL*LTOK)        // 92160
#define CAP    64
#define HID    512
#define AS     72                 // smem row stride in bf16 (144B: conflict-free ldmatrix)
#define PANEL  18432              // bytes per 128x64 panel
#define PANELW 9216               // bf16 elems per panel

typedef __nv_bfloat16 bf16;

// ---------------- device scratch ----------------
__device__ int   g_counts[BALL];
__device__ int   g_list[BALL*CAP];
__device__ int   g_sel[BALL*LMAX];
__device__ int   g_m[BALL];
__device__ float g_bgp[NB*DIM];
__device__ float g_h[NROW*DIM];
__device__ bf16  g_qkvb[NROW*3*DIM];              // bf16 QKV
__device__ bf16  g_a1[NROW*DIM],  g_a2[NROW*DIM];
__device__ bf16  g_h1a[NROW*HID];                 // single-bf16 gelu(h1)
__device__ bf16  g_fa1[BALL*HID], g_fa2[BALL*HID];
// transposed + split weights: [n][k] k-fast
__device__ bf16  g_wqkvT1[DEPTH*3*DIM*DIM], g_wqkvT2[DEPTH*3*DIM*DIM];
__device__ bf16  g_woT1[DEPTH*DIM*DIM],     g_woT2[DEPTH*DIM*DIM];
__device__ bf16  g_w1T1[DEPTH*HID*DIM],     g_w1T2[DEPTH*HID*DIM];
__device__ bf16  g_w2T1[DEPTH*DIM*HID],     g_w2T2[DEPTH*DIM*HID];
__device__ bf16  g_pT1[CLV*HID],            g_pT2[CLV*HID];

// ---------------- helpers ----------------
__device__ __forceinline__ uint32_t s2u(const void* p){
    uint32_t a;
    asm("{ .reg .u64 t; cvta.to.shared.u64 t, %1; cvt.u32.u64 %0, t; }" : "=r"(a) : "l"(p));
    return a;
}
__device__ __forceinline__ void cp16(uint32_t dst, const void* src){
    asm volatile("cp.async.cg.shared.global [%0], [%1], 16;" :: "r"(dst), "l"(src));
}
#define CPCOMMIT() asm volatile("cp.async.commit_group;" ::: "memory")
#define CPWAIT0()  asm volatile("cp.async.wait_group 0;" ::: "memory")
__device__ __forceinline__ void ldsm_x4(uint32_t* d, uint32_t addr){
    asm volatile("ldmatrix.sync.aligned.m8n8.x4.shared.b16 {%0,%1,%2,%3}, [%4];"
        : "=r"(d[0]),"=r"(d[1]),"=r"(d[2]),"=r"(d[3]) : "r"(addr));
}
__device__ __forceinline__ void ldsm_x2(uint32_t* d, uint32_t addr){
    asm volatile("ldmatrix.sync.aligned.m8n8.x2.shared.b16 {%0,%1}, [%2];"
        : "=r"(d[0]),"=r"(d[1]) : "r"(addr));
}
__device__ __forceinline__ void mma16816(float* c, const uint32_t* a, const uint32_t* b){
    asm volatile("mma.sync.aligned.m16n8k16.row.col.f32.bf16.bf16.f32 "
        "{%0,%1,%2,%3}, {%4,%5,%6,%7}, {%8,%9}, {%0,%1,%2,%3};"
        : "+f"(c[0]),"+f"(c[1]),"+f"(c[2]),"+f"(c[3])
        : "r"(a[0]),"r"(a[1]),"r"(a[2]),"r"(a[3]), "r"(b[0]),"r"(b[1]));
}
__device__ __forceinline__ float gelu_f(float x){
    float x3 = x*x*x;
    return 0.5f*x*(1.0f + tanhf(0.7978845608028654f*(x + 0.044715f*x3)));
}
__device__ __forceinline__ void split1(float v, bf16 &h, bf16 &l){
    h = __float2bfloat16(v);
    l = __float2bfloat16(v - __bfloat162float(h));
}
__device__ __forceinline__ float4 ld4bf(const bf16* p){
    uint2 r = *(const uint2*)p;
    __nv_bfloat162 a = *(__nv_bfloat162*)&r.x;
    __nv_bfloat162 b = *(__nv_bfloat162*)&r.y;
    return make_float4(__bfloat162float(a.x), __bfloat162float(a.y),
                       __bfloat162float(b.x), __bfloat162float(b.y));
}

#define GF_ACCUM   1
#define GF_GELU    2
#define GF_SPLIT   4
#define GF_MASK    8
#define GF_LN      16
#define GF_B16     32
#define GF_SMEMOUT 64

// ---------------- setup kernels ----------------
__global__ void k_zero(){
    int i = blockIdx.x*blockDim.x + threadIdx.x;
    if (i < BALL) g_counts[i] = 0;
}
__global__ void k_scatter(const int* __restrict__ li, int n){
    int i = blockIdx.x*blockDim.x + threadIdx.x;
    if (i >= n) return;
    int flat = li[3*i]*(HGRID*WGRID) + li[3*i+1]*WGRID + li[3*i+2];
    int slot = atomicAdd(&g_counts[flat], 1);
    if (slot < CAP) g_list[flat*CAP + slot] = i;
}
__global__ void k_bg(const float* __restrict__ ob, const float* __restrict__ dw,
                     const float* __restrict__ db){
    int c = blockIdx.x*blockDim.x + threadIdx.x;
    if (c >= NB*DIM) return;
    float s = 0.0f;
    for (int m = 0; m < NB; m++){
        const float* bg = ob + m*DIM;
        float t = 0.0f;
        for (int k = 0; k < DIM; k++) t += bg[k] * dw[k*(NB*DIM) + c];
        s += t;
    }
    g_bgp[c] = ob[c] + s*(1.0f/NB) + db[c];
}
__global__ void k_select(){
    int cell = blockIdx.x*blockDim.x + threadIdx.x;
    if (cell >= BALL) return;
    int cnt = g_counts[cell];
    int avail = min(cnt, CAP);
    int m = min(cnt, LMAX);
    g_m[cell] = m;
    if (cnt <= LMAX){
        for (int j = 0; j < m; j++) g_sel[cell*LMAX + j] = g_list[cell*CAP + j];
    } else {
        int tmp[CAP];
        for (int j = 0; j < avail; j++) tmp[j] = g_list[cell*CAP + j];
        for (int a = 0; a < m; a++){
            int best = a;
            for (int b = a+1; b < avail; b++) if (tmp[b] < tmp[best]) best = b;
            int t = tmp[best]; tmp[best] = tmp[a]; tmp[a] = t;
            g_sel[cell*LMAX + a] = t;
        }
    }
}
__global__ void k_assemble(const float* __restrict__ x){
    int idx = blockIdx.x*blockDim.x + threadIdx.x;
    if (idx >= NROW*DIM) return;
    int row = idx >> 7, d = idx & 127;
    int cell = row >> 4, lr = row & 15;
    float v;
    if (lr < NB) v = g_bgp[lr*DIM + d];
    else {
        int j = lr - NB;
        v = (j < g_m[cell]) ? x[(size_t)g_sel[cell*LMAX + j]*DIM + d] : 0.0f;
    }
    g_h[idx] = v;
}
__global__ void k_tsplit(const float* __restrict__ W, bf16* __restrict__ T1,
                         bf16* __restrict__ T2, int K, int N){
    size_t off = (size_t)blockIdx.y * K * N;
    W += off; T1 += off; T2 += off;
    int tot = K*N;
    for (int idx = blockIdx.x*blockDim.x + threadIdx.x; idx < tot;
         idx += gridDim.x*blockDim.x){
        int n = idx / K, k = idx - n*K;
        float v = W[(size_t)k*N + n];
        bf16 h, l; split1(v, h, l);
        T1[idx] = h; T2[idx] = l;
    }
}
// LayerNorm + bf16 split (layer 0 only)
__global__ void k_ln_split(const float* __restrict__ w, const float* __restrict__ b){
    int warp = threadIdx.x >> 5, lane = threadIdx.x & 31;
    int row = blockIdx.x*8 + warp;
    const float* src = g_h + (size_t)row*DIM;
    float4 v = *(const float4*)(src + lane*4);
    float s  = v.x+v.y+v.z+v.w;
    float ss = v.x*v.x+v.y*v.y+v.z*v.z+v.w*v.w;
    #pragma unroll
    for (int o = 16; o; o >>= 1){
        s  += __shfl_xor_sync(0xffffffffu, s,  o);
        ss += __shfl_xor_sync(0xffffffffu, ss, o);
    }
    float mean = s*(1.0f/DIM);
    float var  = ss*(1.0f/DIM) - mean*mean;
    float rstd = rsqrtf(var + 1e-5f);
    float4 wv = *(const float4*)(w + lane*4);
    float4 bv = *(const float4*)(b + lane*4);
    float n0 = (v.x-mean)*rstd*wv.x + bv.x;
    float n1 = (v.y-mean)*rstd*wv.y + bv.y;
    float n2 = (v.z-mean)*rstd*wv.z + bv.z;
    float n3 = (v.w-mean)*rstd*wv.w + bv.w;
    bf16 h0,l0,h1,l1,h2,l2,h3,l3;
    split1(n0,h0,l0); split1(n1,h1,l1); split1(n2,h2,l2); split1(n3,h3,l3);
    __nv_bfloat162* d1 = (__nv_bfloat162*)(g_a1 + (size_t)row*DIM + lane*4);
    __nv_bfloat162* d2 = (__nv_bfloat162*)(g_a2 + (size_t)row*DIM + lane*4);
    __nv_bfloat162 p;
    p.x=h0; p.y=h1; d1[0]=p;  p.x=h2; p.y=h3; d1[1]=p;
    p.x=l0; p.y=l1; d2[0]=p;  p.x=l2; p.y=l3; d2[1]=p;
}
// attention (bf16 QKV in, fp32 math, split-bf16 out)
__global__ void k_attn(){
    int warp = threadIdx.x >> 5, lane = threadIdx.x & 31;
    int cell = blockIdx.x*8 + warp;
    int qoff = ((lane >> 3) << 5) + ((lane & 7) << 2);
    const float scale = 0.17677669529663687f;
    size_t base = (size_t)cell*LTOK;
    for (int r = 0; r < LTOK; r++){
        float4 q4 = ld4bf(g_qkvb + (base+r)*384 + qoff);
        float sc[LTOK]; float mx = -1e30f;
        #pragma unroll
        for (int j = 0; j < LTOK; j++){
            float4 k4 = ld4bf(g_qkvb + (base+j)*384 + 128 + qoff);
            float sdot = q4.x*k4.x + q4.y*k4.y + q4.z*k4.z + q4.w*k4.w;
            sdot += __shfl_xor_sync(0xffffffffu, sdot, 1);
            sdot += __shfl_xor_sync(0xffffffffu, sdot, 2);
            sdot += __shfl_xor_sync(0xffffffffu, sdot, 4);
            sdot *= scale;
            sc[j] = sdot; mx = fmaxf(mx, sdot);
        }
        float den = 0.0f;
        #pragma unroll
        for (int j = 0; j < LTOK; j++){ sc[j] = __expf(sc[j]-mx); den += sc[j]; }
        float inv = __fdividef(1.0f, den);
        float4 o = make_float4(0.f,0.f,0.f,0.f);
        #pragma unroll
        for (int j = 0; j < LTOK; j++){
            float p = sc[j]*inv;
            float4 v4 = ld4bf(g_qkvb + (base+j)*384 + 256 + qoff);
            o.x += p*v4.x; o.y += p*v4.y; o.z += p*v4.z; o.w += p*v4.w;
        }
        bf16 h0,l0,h1,l1,h2,l2,h3,l3;
        split1(o.x,h0,l0); split1(o.y,h1,l1); split1(o.z,h2,l2); split1(o.w,h3,l3);
        __nv_bfloat162* d1 = (__nv_bfloat162*)(g_a1 + (base+r)*DIM + qoff);
        __nv_bfloat162* d2 = (__nv_bfloat162*)(g_a2 + (base+r)*DIM + qoff);
        __nv_bfloat162 p;
        p.x=h0; p.y=h1; d1[0]=p;  p.x=h2; p.y=h3; d1[1]=p;
        p.x=l0; p.y=l1; d2[0]=p;  p.x=l2; p.y=l3; d2[1]=p;
    }
}
__global__ void k_split_feat(){
    int idx = blockIdx.x*blockDim.x + threadIdx.x;
    if (idx >= BALL*HID) return;
    int cell = idx >> 9, k = idx & 511;
    float v = g_h[(size_t)cell*(LTOK*DIM) + k];
    bf16 h, l; split1(v, h, l);
    g_fa1[idx] = h; g_fa2[idx] = l;
}

// ---------------- shared MMA chunk over one 64-k slab in smem ----------------
template<bool A2ON>
__device__ __forceinline__ void chunk_mma(float (&acc)[2][8][4],
                                          uint32_t abase, uint32_t bbase){
    #pragma unroll
    for (int k16 = 0; k16 < 64; k16 += 16){
        uint32_t a1f[2][4], a2f[2][4];
        #pragma unroll
        for (int mt = 0; mt < 2; mt++){
            uint32_t ad = abase + (uint32_t)((mt*16*AS + k16) * 2);
            ldsm_x4(a1f[mt], ad);
            if (A2ON) ldsm_x4(a2f[mt], ad + PANEL);
        }
        #pragma unroll
        for (int nt = 0; nt < 8; nt++){
            uint32_t bd = bbase + (uint32_t)((nt*8*AS + k16) * 2);
            uint32_t b1f[2], b2f[2];
            ldsm_x2(b1f, bd);
            ldsm_x2(b2f, bd + PANEL);
            mma16816(acc[0][nt], a1f[0], b1f);
            mma16816(acc[1][nt], a1f[1], b1f);
            if (A2ON){
                mma16816(acc[0][nt], a2f[0], b1f);
                mma16816(acc[1][nt], a2f[1], b1f);
            }
            mma16816(acc[0][nt], a1f[0], b2f);
            mma16816(acc[1][nt], a1f[1], b2f);
        }
    }
}

// ---------------- shared epilogue ----------------
__device__ __forceinline__ void gemm_epilogue(
    float (&acc)[2][8][4], int row0, int cofs,
    const float* __restrict__ bias,
    float* __restrict__ Cout, int ldc,
    bf16* __restrict__ O1, bf16* __restrict__ O2, int ldo,
    const float* __restrict__ lnw, const float* __restrict__ lnb,
    float2* red, int flags, int lane, int warpM, int warpN,
    bf16* smem_bf)
{
    const int l4 = lane >> 2, l2 = (lane & 3) << 1;

    if (flags & GF_LN){
        #pragma unroll
        for (int mt = 0; mt < 2; mt++){
            #pragma unroll
            for (int hh = 0; hh < 2; hh++){
                int rl = warpM*32 + mt*16 + hh*8 + l4;
                int rg = row0 + rl;
                float s = 0.0f, ss = 0.0f;
                #pragma unroll
                for (int nt = 0; nt < 8; nt++){
                    int cg = warpN*64 + nt*8 + l2;
                    float2 old = *(const float2*)(Cout + (size_t)rg*ldc + cg);
                    float v0 = acc[mt][nt][hh*2+0] + bias[cg]   + old.x;
                    float v1 = acc[mt][nt][hh*2+1] + bias[cg+1] + old.y;
                    acc[mt][nt][hh*2+0] = v0;
                    acc[mt][nt][hh*2+1] = v1;
                    *(float2*)(Cout + (size_t)rg*ldc + cg) = make_float2(v0, v1);
                    s += v0 + v1; ss += v0*v0 + v1*v1;
                }
                s  += __shfl_xor_sync(0xffffffffu, s,  1);
                ss += __shfl_xor_sync(0xffffffffu, ss, 1);
                s  += __shfl_xor_sync(0xffffffffu, s,  2);
                ss += __shfl_xor_sync(0xffffffffu, ss, 2);
                if ((lane & 3) == 0) red[rl*2 + warpN] = make_float2(s, ss);
            }
        }
        __syncthreads();
        #pragma unroll
        for (int mt = 0; mt < 2; mt++){
            #pragma unroll
            for (int hh = 0; hh < 2; hh++){
                int rl = warpM*32 + mt*16 + hh*8 + l4;
                int rg = row0 + rl;
                float2 r0 = red[rl*2 + 0], r1 = red[rl*2 + 1];
                float mean = (r0.x + r1.x) * (1.0f/DIM);
                float var  = (r0.y + r1.y) * (1.0f/DIM) - mean*mean;
                float rstd = rsqrtf(var + 1e-5f);
                #pragma unroll
                for (int nt = 0; nt < 8; nt++){
                    int cg = warpN*64 + nt*8 + l2;
                    float n0 = (acc[mt][nt][hh*2+0] - mean)*rstd*lnw[cg]   + lnb[cg];
                    float n1 = (acc[mt][nt][hh*2+1] - mean)*rstd*lnw[cg+1] + lnb[cg+1];
                    bf16 ha,la,hb,lb;
                    split1(n0, ha, la); split1(n1, hb, lb);
                    __nv_bfloat162 p, q;
                    p.x=ha; p.y=hb; q.x=la; q.y=lb;
                    if (flags & GF_SMEMOUT){
                        int p0 = (cg >> 6) * 2;
                        int c63 = cg & 63;
                        *(__nv_bfloat162*)(smem_bf + p0*PANELW     + rl*AS + c63) = p;
                        *(__nv_bfloat162*)(smem_bf + (p0+1)*PANELW + rl*AS + c63) = q;
                    } else {
                        *(__nv_bfloat162*)(O1 + (size_t)rg*ldo + cg) = p;
                        *(__nv_bfloat162*)(O2 + (size_t)rg*ldo + cg) = q;
                    }
                }
            }
        }
        return;
    }

    #pragma unroll
    for (int mt = 0; mt < 2; mt++){
        #pragma unroll
        for (int hh = 0; hh < 2; hh++){
            int rg = row0 + warpM*32 + mt*16 + l4 + hh*8;
            bool maskz = (flags & GF_MASK) && (g_counts[rg] == 0);
            #pragma unroll
            for (int nt = 0; nt < 8; nt++){
                int cg = cofs + warpN*64 + nt*8 + l2;
                float v0 = acc[mt][nt][hh*2+0] + bias[cg];
                float v1 = acc[mt][nt][hh*2+1] + bias[cg+1];
                if (flags & GF_GELU){ v0 = gelu_f(v0); v1 = gelu_f(v1); }
                if (flags & GF_ACCUM){
                    float2 old = *(const float2*)(Cout + (size_t)rg*ldc + cg);
                    v0 += old.x; v1 += old.y;
                }
                if (flags & GF_SPLIT){
                    bf16 ha,la,hb,lb;
                    split1(v0, ha, la); split1(v1, hb, lb);
                    __nv_bfloat162 p;
                    p.x=ha; p.y=hb; *(__nv_bfloat162*)(O1 + (size_t)rg*ldo + cg) = p;
                    p.x=la; p.y=lb; *(__nv_bfloat162*)(O2 + (size_t)rg*ldo + cg) = p;
                } else if (flags & GF_B16){
                    __nv_bfloat162 p;
                    p.x = __float2bfloat16(v0); p.y = __float2bfloat16(v1);
                    *(__nv_bfloat162*)(O1 + (size_t)rg*ldo + cg) = p;
                } else {
                    float2 ov = maskz ? make_float2(0.f, 0.f) : make_float2(v0, v1);
                    *(float2*)(Cout + (size_t)rg*ldc + cg) = ov;
                }
            }
        }
    }
}

// ---------------- standalone mma.sync GEMM (L0 qkv, final w2, proj) ----------------
template<bool ARES, bool A2ON>
__global__ __launch_bounds__(256, 2)
void k_gemm(const bf16* __restrict__ A1, const bf16* __restrict__ A2, int lda,
            const bf16* __restrict__ B1, const bf16* __restrict__ B2,
            const float* __restrict__ bias,
            float* __restrict__ Cout, int ldc,
            bf16* __restrict__ O1, bf16* __restrict__ O2, int ldo,
            const float* __restrict__ lnw, const float* __restrict__ lnb,
            int Ktot, int ny, int flags){
    extern __shared__ bf16 smem[];
    const int tid = threadIdx.x, lane = tid & 31, wid = tid >> 5;
    const int warpM = wid & 3, warpN = wid >> 2;
    const int row0 = blockIdx.x*128;
    const uint32_t sbase = s2u(smem);
    const uint32_t BBASE = ARES ? 4*PANEL : 2*PANEL;
    float2* red = (float2*)((char*)smem + (ARES ? 6*PANEL : 4*PANEL));

    const int rowA = lane & 15, kA8 = (lane >> 4) << 3;
    const int rowB = lane & 7,  kB8 = ((lane >> 3) & 1) << 3;
    const uint32_t aoff0 = (uint32_t)(((warpM*32 + rowA)*AS + kA8) * 2);
    const uint32_t boff  = sbase + BBASE + (uint32_t)(((warpN*64 + rowB)*AS + kB8) * 2);

    float acc[2][8][4];

    if (ARES){
        #pragma unroll
        for (int p = 0; p < 4; p++){
            int chunk = p >> 1;
            const bf16* src = (p & 1) ? A2 : A1;
            #pragma unroll
            for (int it = 0; it < 4; it++){
                int idx = it*256 + tid;
                int r = idx >> 3, c8 = (idx & 7) << 3;
                cp16(sbase + p*PANEL + (uint32_t)((r*AS + c8)*2),
                     src + (size_t)(row0+r)*lda + chunk*64 + c8);
            }
        }
        CPCOMMIT();

        for (int nb = 0; nb < ny; nb++){
            int cofs = nb*128;
            #pragma unroll
            for (int mt = 0; mt < 2; mt++)
                #pragma unroll
                for (int nt = 0; nt < 8; nt++)
                    #pragma unroll
                    for (int q = 0; q < 4; q++) acc[mt][nt][q] = 0.0f;

            for (int kc2 = 0; kc2 < 2; kc2++){
                #pragma unroll
                for (int it = 0; it < 4; it++){
                    int idx = it*256 + tid;
                    int r = idx >> 3, c8 = (idx & 7) << 3;
                    uint32_t so = (uint32_t)((r*AS + c8)*2);
                    cp16(sbase + BBASE + so,         B1 + (size_t)(cofs+r)*Ktot + kc2*64 + c8);
                    cp16(sbase + BBASE + PANEL + so, B2 + (size_t)(cofs+r)*Ktot + kc2*64 + c8);
                }
                CPCOMMIT();
                CPWAIT0();
                __syncthreads();
                chunk_mma<true>(acc, sbase + (uint32_t)(kc2*2*PANEL) + aoff0, boff);
                __syncthreads();
            }
            gemm_epilogue(acc, row0, cofs, bias, Cout, ldc, O1, O2, ldo,
                          lnw, lnb, red, flags, lane, warpM, warpN, smem);
            __syncthreads();
        }
    } else {
        const int cofs = blockIdx.y*128;
        #pragma unroll
        for (int mt = 0; mt < 2; mt++)
            #pragma unroll
            for (int nt = 0; nt < 8; nt++)
                #pragma unroll
                for (int q = 0; q < 4; q++) acc[mt][nt][q] = 0.0f;

        for (int kc = 0; kc < Ktot; kc += 64){
            #pragma unroll
            for (int it = 0; it < 4; it++){
                int idx = it*256 + tid;
                int r = idx >> 3, c8 = (idx & 7) << 3;
                uint32_t so = (uint32_t)((r*AS + c8)*2);
                cp16(sbase + so, A1 + (size_t)(row0+r)*lda + kc + c8);
                if (A2ON) cp16(sbase + PANEL + so, A2 + (size_t)(row0+r)*lda + kc + c8);
                cp16(sbase + 2*PANEL + so, B1 + (size_t)(cofs+r)*Ktot + kc + c8);
                cp16(sbase + 3*PANEL + so, B2 + (size_t)(cofs+r)*Ktot + kc + c8);
            }
            CPCOMMIT();
            CPWAIT0();
            __syncthreads();
            chunk_mma<A2ON>(acc, sbase + aoff0, boff);
            __syncthreads();
        }
        gemm_epilogue(acc, row0, cofs, bias, Cout, ldc, O1, O2, ldo,
                      lnw, lnb, red, flags, lane, warpM, warpN, smem);
    }
}

// ---------------- fused kernel: streaming GEMM + LN -> smem + A-resident GEMM -----
template<int KW, bool A2W, int NY2>
__global__ __launch_bounds__(256, 2)
void k_fused(const bf16* __restrict__ A1, const bf16* __restrict__ A2, int lda,
             const bf16* __restrict__ Bw1, const bf16* __restrict__ Bw2,
             const float* __restrict__ biasW,
             float* __restrict__ hres,
             const float* __restrict__ lnw, const float* __restrict__ lnb,
             const bf16* __restrict__ B21, const bf16* __restrict__ B22,
             const float* __restrict__ bias2,
             float* __restrict__ C2, int ldc2,
             bf16* __restrict__ O2b, int ldo2,
             int flags2){
    extern __shared__ bf16 smem[];
    const int tid = threadIdx.x, lane = tid & 31, wid = tid >> 5;
    const int warpM = wid & 3, warpN = wid >> 2;
    const int row0 = blockIdx.x*128;
    const uint32_t sbase = s2u(smem);
    float2* red = (float2*)((char*)smem + 6*PANEL);

    const int rowA = lane & 15, kA8 = (lane >> 4) << 3;
    const int rowB = lane & 7,  kB8 = ((lane >> 3) & 1) << 3;
    const uint32_t aoff0 = (uint32_t)(((warpM*32 + rowA)*AS + kA8) * 2);
    const uint32_t boffB = sbase + 4*PANEL + (uint32_t)(((warpN*64 + rowB)*AS + kB8) * 2);

    float acc[2][8][4];

    // ---- phase 1 ----
    #pragma unroll
    for (int mt = 0; mt < 2; mt++)
        #pragma unroll
        for (int nt = 0; nt < 8; nt++)
            #pragma unroll
            for (int q = 0; q < 4; q++) acc[mt][nt][q] = 0.0f;

    for (int kc = 0; kc < KW; kc += 64){
        #pragma unroll
        for (int it = 0; it < 4; it++){
            int idx = it*256 + tid;
            int r = idx >> 3, c8 = (idx & 7) << 3;
            uint32_t so = (uint32_t)((r*AS + c8)*2);
            cp16(sbase + so, A1 + (size_t)(row0+r)*lda + kc + c8);
            if (A2W) cp16(sbase + PANEL + so, A2 + (size_t)(row0+r)*lda + kc + c8);
            cp16(sbase + 4*PANEL + so, Bw1 + (size_t)r*KW + kc + c8);
            cp16(sbase + 5*PANEL + so, Bw2 + (size_t)r*KW + kc + c8);
        }
        CPCOMMIT();
        CPWAIT0();
        __syncthreads();
        chunk_mma<A2W>(acc, sbase + aoff0, boffB);
        __syncthreads();
    }
    gemm_epilogue(acc, row0, 0, biasW, hres, DIM, (bf16*)0, (bf16*)0, 0,
                  lnw, lnb, red, GF_ACCUM|GF_LN|GF_SMEMOUT, lane, warpM, warpN, smem);
    __syncthreads();

    // ---- phase 2 ----
    for (int nb = 0; nb < NY2; nb++){
        int cofs = nb*128;
        #pragma unroll
        for (int mt = 0; mt < 2; mt++)
            #pragma unroll
            for (int nt = 0; nt < 8; nt++)
                #pragma unroll
                for (int q = 0; q < 4; q++) acc[mt][nt][q] = 0.0f;

        for (int kc2 = 0; kc2 < 2; kc2++){
            #pragma unroll
            for (int it = 0; it < 4; it++){
                int idx = it*256 + tid;
                int r = idx >> 3, c8 = (idx & 7) << 3;
                uint32_t so = (uint32_t)((r*AS + c8)*2);
                cp16(sbase + 4*PANEL + so, B21 + (size_t)(cofs+r)*DIM + kc2*64 + c8);
                cp16(sbase + 5*PANEL + so, B22 + (size_t)(cofs+r)*DIM + kc2*64 + c8);
            }
            CPCOMMIT();
            CPWAIT0();
            __syncthreads();
            chunk_mma<true>(acc, sbase + (uint32_t)(kc2*2*PANEL) + aoff0, boffB);
            __syncthreads();
        }
        gemm_epilogue(acc, row0, cofs, bias2, C2, ldc2, O2b, (bf16*)0, ldo2,
                      (float*)0, (float*)0, red, flags2, lane, warpM, warpN, smem);
        __syncthreads();
    }
}

// ---------------- launch ----------------
extern "C" void kernel_launch(void* const* d_in, const int* in_sizes, int n_in,
                              void* d_out, int out_size){
    const float* x    = (const float*)d_in[0];
    const int*   li   = (const int*)  d_in[1];
    const float* ob   = (const float*)d_in[2];
    const float* dw   = (const float*)d_in[3];
    const float* db   = (const float*)d_in[4];
    const float* ln1w = (const float*)d_in[5];
    const float* ln1b = (const float*)d_in[6];
    const float* wqkv = (const float*)d_in[7];
    const float* bqkv = (const float*)d_in[8];
    const float* wo   = (const float*)d_in[9];
    const float* bo   = (const float*)d_in[10];
    const float* ln2w = (const float*)d_in[11];
    const float* ln2b = (const float*)d_in[12];
    const float* w1   = (const float*)d_in[13];
    const float* b1   = (const float*)d_in[14];
    const float* w2   = (const float*)d_in[15];
    const float* b2   = (const float*)d_in[16];
    const float* pw   = (const float*)d_in[17];
    const float* pb   = (const float*)d_in[18];
    int n = in_sizes[0] / DIM;

    bf16 *a1, *a2, *h1a, *fa1, *fa2, *qkvb;
    bf16 *wqT1, *wqT2, *woT1, *woT2, *w1T1, *w1T2, *w2T1, *w2T2, *pT1, *pT2;
    float *h;
    cudaGetSymbolAddress((void**)&a1,  g_a1);  cudaGetSymbolAddress((void**)&a2,  g_a2);
    cudaGetSymbolAddress((void**)&h1a, g_h1a);
    cudaGetSymbolAddress((void**)&fa1, g_fa1); cudaGetSymbolAddress((void**)&fa2, g_fa2);
    cudaGetSymbolAddress((void**)&qkvb, g_qkvb);
    cudaGetSymbolAddress((void**)&wqT1, g_wqkvT1); cudaGetSymbolAddress((void**)&wqT2, g_wqkvT2);
    cudaGetSymbolAddress((void**)&woT1, g_woT1);   cudaGetSymbolAddress((void**)&woT2, g_woT2);
    cudaGetSymbolAddress((void**)&w1T1, g_w1T1);   cudaGetSymbolAddress((void**)&w1T2, g_w1T2);
    cudaGetSymbolAddress((void**)&w2T1, g_w2T1);   cudaGetSymbolAddress((void**)&w2T2, g_w2T2);
    cudaGetSymbolAddress((void**)&pT1, g_pT1);     cudaGetSymbolAddress((void**)&pT2, g_pT2);
    cudaGetSymbolAddress((void**)&h, g_h);

    const int SMEM_ARES = 6*PANEL + 2048;   // 112640
    const int SMEM_STRM = 4*PANEL + 2048;   // 75776
    cudaFuncSetAttribute(k_gemm<true,true>,   cudaFuncAttributeMaxDynamicSharedMemorySize, SMEM_ARES);
    cudaFuncSetAttribute(k_gemm<false,true>,  cudaFuncAttributeMaxDynamicSharedMemorySize, SMEM_STRM);
    cudaFuncSetAttribute(k_gemm<false,false>, cudaFuncAttributeMaxDynamicSharedMemorySize, SMEM_STRM);
    cudaFuncSetAttribute(k_fused<128,true,4>,  cudaFuncAttributeMaxDynamicSharedMemorySize, SMEM_ARES);
    cudaFuncSetAttribute(k_fused<512,false,3>, cudaFuncAttributeMaxDynamicSharedMemorySize, SMEM_ARES);

    // setup
    k_zero<<<(BALL+255)/256, 256>>>();
    k_scatter<<<(n+255)/256, 256>>>(li, n);
    k_bg<<<2, 256>>>(ob, dw, db);
    k_select<<<(BALL+255)/256, 256>>>();
    k_assemble<<<(NROW*DIM+255)/256, 256>>>(x);

    // weight transpose+split
    k_tsplit<<<dim3(64, DEPTH), 256>>>(wqkv, wqT1, wqT2, DIM, 3*DIM);
    k_tsplit<<<dim3(32, DEPTH), 256>>>(wo,   woT1, woT2, DIM, DIM);
    k_tsplit<<<dim3(64, DEPTH), 256>>>(w1,   w1T1, w1T2, DIM, HID);
    k_tsplit<<<dim3(64, DEPTH), 256>>>(w2,   w2T1, w2T2, HID, DIM);
    k_tsplit<<<dim3(256, 1),    256>>>(pw,   pT1,  pT2,  HID, CLV);

    // layer-0 LN + qkv (bf16 QKV out)
    k_ln_split<<<NROW/8, 256>>>(ln1w, ln1b);
    const int MB = NROW/128;   // 720
    k_gemm<true,true><<<MB, 256, SMEM_ARES>>>(a1, a2, DIM,
        wqT1, wqT2, bqkv, (float*)0, 0, qkvb, (bf16*)0, 3*DIM,
        (float*)0, (float*)0, DIM, 3, GF_B16);

    for (int L = 0; L < DEPTH; L++){
        k_attn<<<BALL/8, 256>>>();
        // fused: wo + residual + ln2 -> smem -> w1 (gelu, bf16 out)
        k_fused<128,true,4><<<MB, 256, SMEM_ARES>>>(a1, a2, DIM,
            woT1 + (size_t)L*DIM*DIM, woT2 + (size_t)L*DIM*DIM,
            bo + L*DIM, h, ln2w + L*DIM, ln2b + L*DIM,
            w1T1 + (size_t)L*HID*DIM, w1T2 + (size_t)L*HID*DIM,
            b1 + L*HID, (float*)0, 0, h1a, HID, GF_GELU|GF_B16);
        if (L < DEPTH-1){
            // fused: w2 + residual + ln1(L+1) -> smem -> qkv(L+1) (bf16 out)
            k_fused<512,false,3><<<MB, 256, SMEM_ARES>>>(h1a, (bf16*)0, HID,
                w2T1 + (size_t)L*DIM*HID, w2T2 + (size_t)L*DIM*HID,
                b2 + L*DIM, h, ln1w + (L+1)*DIM, ln1b + (L+1)*DIM,
                wqT1 + (size_t)(L+1)*3*DIM*DIM, wqT2 + (size_t)(L+1)*3*DIM*DIM,
                bqkv + (L+1)*3*DIM, (float*)0, 0, qkvb, 3*DIM, GF_B16);
        } else {
            k_gemm<false,false><<<dim3(MB,1), 256, SMEM_STRM>>>(h1a, (bf16*)0, HID,
                w2T1 + (size_t)L*DIM*HID, w2T2 + (size_t)L*DIM*HID,
                b2 + L*DIM, h, DIM, (bf16*)0, (bf16*)0, 0,
                (float*)0, (float*)0, HID, 1, GF_ACCUM);
        }
    }

    k_split_feat<<<(BALL*HID+255)/256, 256>>>();
    k_gemm<false,true><<<dim3(BALL/128, CLV/128), 256, SMEM_STRM>>>(fa1, fa2, HID,
        pT1, pT2, pb, (float*)d_out, CLV, (bf16*)0, (bf16*)0, 0,
        (float*)0, (float*)0, HID, 1, GF_MASK);
}

// round 16
// speedup vs baseline: 3.2678x; 1.0145x over previous
#include <cuda_runtime.h>
#include <cuda_bf16.h>
#include <cstdint>
#include <math.h>

#define DD     5
#define HGRID  24
#define WGRID  48
#define CLV    1024
#define NB     4
#define DIM    128
#define LMAX   12
#define DEPTH  6
#define LTOK   16
#define BALL   (DD*HGRID*WGRID)   // 5760
#define NROW   (BALL*LTOK)        // 92160
#define CAP    64
#define HID    512
#define AS     72                 // smem row stride in bf16 (144B: conflict-free ldmatrix)
#define PANEL  18432              // bytes per 128x64 panel
#define PANELW 9216               // bf16 elems per panel

typedef __nv_bfloat16 bf16;

// ---------------- device scratch ----------------
__device__ int   g_counts[BALL];
__device__ int   g_list[BALL*CAP];
__device__ int   g_sel[BALL*LMAX];
__device__ int   g_m[BALL];
__device__ float g_bgp[NB*DIM];
__device__ float g_h[NROW*DIM];
__device__ bf16  g_qkvb[NROW*3*DIM];              // bf16 QKV
__device__ bf16  g_a1[NROW*DIM],  g_a2[NROW*DIM]; // layer-0 LN split only
__device__ bf16  g_h1a[NROW*HID];                 // single-bf16 gelu(h1)
__device__ bf16  g_fa1[BALL*HID], g_fa2[BALL*HID];
// transposed + split weights: [n][k] k-fast
__device__ bf16  g_wqkvT1[DEPTH*3*DIM*DIM], g_wqkvT2[DEPTH*3*DIM*DIM];
__device__ bf16  g_woT1[DEPTH*DIM*DIM],     g_woT2[DEPTH*DIM*DIM];
__device__ bf16  g_w1T1[DEPTH*HID*DIM],     g_w1T2[DEPTH*HID*DIM];
__device__ bf16  g_w2T1[DEPTH*DIM*HID],     g_w2T2[DEPTH*DIM*HID];
__device__ bf16  g_pT1[CLV*HID],            g_pT2[CLV*HID];

// ---------------- helpers ----------------
__device__ __forceinline__ uint32_t s2u(const void* p){
    uint32_t a;
    asm("{ .reg .u64 t; cvta.to.shared.u64 t, %1; cvt.u32.u64 %0, t; }" : "=r"(a) : "l"(p));
    return a;
}
__device__ __forceinline__ void cp16(uint32_t dst, const void* src){
    asm volatile("cp.async.cg.shared.global [%0], [%1], 16;" :: "r"(dst), "l"(src));
}
#define CPCOMMIT() asm volatile("cp.async.commit_group;" ::: "memory")
#define CPWAIT0()  asm volatile("cp.async.wait_group 0;" ::: "memory")
__device__ __forceinline__ void ldsm_x4(uint32_t* d, uint32_t addr){
    asm volatile("ldmatrix.sync.aligned.m8n8.x4.shared.b16 {%0,%1,%2,%3}, [%4];"
        : "=r"(d[0]),"=r"(d[1]),"=r"(d[2]),"=r"(d[3]) : "r"(addr));
}
__device__ __forceinline__ void ldsm_x2(uint32_t* d, uint32_t addr){
    asm volatile("ldmatrix.sync.aligned.m8n8.x2.shared.b16 {%0,%1}, [%2];"
        : "=r"(d[0]),"=r"(d[1]) : "r"(addr));
}
__device__ __forceinline__ void mma16816(float* c, const uint32_t* a, const uint32_t* b){
    asm volatile("mma.sync.aligned.m16n8k16.row.col.f32.bf16.bf16.f32 "
        "{%0,%1,%2,%3}, {%4,%5,%6,%7}, {%8,%9}, {%0,%1,%2,%3};"
        : "+f"(c[0]),"+f"(c[1]),"+f"(c[2]),"+f"(c[3])
        : "r"(a[0]),"r"(a[1]),"r"(a[2]),"r"(a[3]), "r"(b[0]),"r"(b[1]));
}
__device__ __forceinline__ float gelu_f(float x){
    float x3 = x*x*x;
    return 0.5f*x*(1.0f + tanhf(0.7978845608028654f*(x + 0.044715f*x3)));
}
__device__ __forceinline__ void split1(float v, bf16 &h, bf16 &l){
    h = __float2bfloat16(v);
    l = __float2bfloat16(v - __bfloat162float(h));
}
__device__ __forceinline__ float4 ld4bf(const bf16* p){
    uint2 r = *(const uint2*)p;
    __nv_bfloat162 a = *(__nv_bfloat162*)&r.x;
    __nv_bfloat162 b = *(__nv_bfloat162*)&r.y;
    return make_float4(__bfloat162float(a.x), __bfloat162float(a.y),
                       __bfloat162float(b.x), __bfloat162float(b.y));
}

#define GF_ACCUM   1
#define GF_GELU    2
#define GF_SPLIT   4
#define GF_MASK    8
#define GF_LN      16
#define GF_B16     32
#define GF_SMEMOUT 64

// ---------------- setup kernels ----------------
__global__ void k_zero(){
    int i = blockIdx.x*blockDim.x + threadIdx.x;
    if (i < BALL) g_counts[i] = 0;
}
__global__ void k_scatter(const int* __restrict__ li, int n){
    int i = blockIdx.x*blockDim.x + threadIdx.x;
    if (i >= n) return;
    int flat = li[3*i]*(HGRID*WGRID) + li[3*i+1]*WGRID + li[3*i+2];
    int slot = atomicAdd(&g_counts[flat], 1);
    if (slot < CAP) g_list[flat*CAP + slot] = i;
}
__global__ void k_bg(const float* __restrict__ ob, const float* __restrict__ dw,
                     const float* __restrict__ db){
    int c = blockIdx.x*blockDim.x + threadIdx.x;
    if (c >= NB*DIM) return;
    float s = 0.0f;
    for (int m = 0; m < NB; m++){
        const float* bg = ob + m*DIM;
        float t = 0.0f;
        for (int k = 0; k < DIM; k++) t += bg[k] * dw[k*(NB*DIM) + c];
        s += t;
    }
    g_bgp[c] = ob[c] + s*(1.0f/NB) + db[c];
}
__global__ void k_select(){
    int cell = blockIdx.x*blockDim.x + threadIdx.x;
    if (cell >= BALL) return;
    int cnt = g_counts[cell];
    int avail = min(cnt, CAP);
    int m = min(cnt, LMAX);
    g_m[cell] = m;
    if (cnt <= LMAX){
        for (int j = 0; j < m; j++) g_sel[cell*LMAX + j] = g_list[cell*CAP + j];
    } else {
        int tmp[CAP];
        for (int j = 0; j < avail; j++) tmp[j] = g_list[cell*CAP + j];
        for (int a = 0; a < m; a++){
            int best = a;
            for (int b = a+1; b < avail; b++) if (tmp[b] < tmp[best]) best = b;
            int t = tmp[best]; tmp[best] = tmp[a]; tmp[a] = t;
            g_sel[cell*LMAX + a] = t;
        }
    }
}
__global__ void k_assemble(const float* __restrict__ x){
    int idx = blockIdx.x*blockDim.x + threadIdx.x;
    if (idx >= NROW*DIM) return;
    int row = idx >> 7, d = idx & 127;
    int cell = row >> 4, lr = row & 15;
    float v;
    if (lr < NB) v = g_bgp[lr*DIM + d];
    else {
        int j = lr - NB;
        v = (j < g_m[cell]) ? x[(size_t)g_sel[cell*LMAX + j]*DIM + d] : 0.0f;
    }
    g_h[idx] = v;
}
__global__ void k_tsplit(const float* __restrict__ W, bf16* __restrict__ T1,
                         bf16* __restrict__ T2, int K, int N){
    size_t off = (size_t)blockIdx.y * K * N;
    W += off; T1 += off; T2 += off;
    int tot = K*N;
    for (int idx = blockIdx.x*blockDim.x + threadIdx.x; idx < tot;
         idx += gridDim.x*blockDim.x){
        int n = idx / K, k = idx - n*K;
        float v = W[(size_t)k*N + n];
        bf16 h, l; split1(v, h, l);
        T1[idx] = h; T2[idx] = l;
    }
}
// LayerNorm + bf16 split (layer 0 only)
__global__ void k_ln_split(const float* __restrict__ w, const float* __restrict__ b){
    int warp = threadIdx.x >> 5, lane = threadIdx.x & 31;
    int row = blockIdx.x*8 + warp;
    const float* src = g_h + (size_t)row*DIM;
    float4 v = *(const float4*)(src + lane*4);
    float s  = v.x+v.y+v.z+v.w;
    float ss = v.x*v.x+v.y*v.y+v.z*v.z+v.w*v.w;
    #pragma unroll
    for (int o = 16; o; o >>= 1){
        s  += __shfl_xor_sync(0xffffffffu, s,  o);
        ss += __shfl_xor_sync(0xffffffffu, ss, o);
    }
    float mean = s*(1.0f/DIM);
    float var  = ss*(1.0f/DIM) - mean*mean;
    float rstd = rsqrtf(var + 1e-5f);
    float4 wv = *(const float4*)(w + lane*4);
    float4 bv = *(const float4*)(b + lane*4);
    float n0 = (v.x-mean)*rstd*wv.x + bv.x;
    float n1 = (v.y-mean)*rstd*wv.y + bv.y;
    float n2 = (v.z-mean)*rstd*wv.z + bv.z;
    float n3 = (v.w-mean)*rstd*wv.w + bv.w;
    bf16 h0,l0,h1,l1,h2,l2,h3,l3;
    split1(n0,h0,l0); split1(n1,h1,l1); split1(n2,h2,l2); split1(n3,h3,l3);
    __nv_bfloat162* d1 = (__nv_bfloat162*)(g_a1 + (size_t)row*DIM + lane*4);
    __nv_bfloat162* d2 = (__nv_bfloat162*)(g_a2 + (size_t)row*DIM + lane*4);
    __nv_bfloat162 p;
    p.x=h0; p.y=h1; d1[0]=p;  p.x=h2; p.y=h3; d1[1]=p;
    p.x=l0; p.y=l1; d2[0]=p;  p.x=l2; p.y=l3; d2[1]=p;
}
__global__ void k_split_feat(){
    int idx = blockIdx.x*blockDim.x + threadIdx.x;
    if (idx >= BALL*HID) return;
    int cell = idx >> 9, k = idx & 511;
    float v = g_h[(size_t)cell*(LTOK*DIM) + k];
    bf16 h, l; split1(v, h, l);
    g_fa1[idx] = h; g_fa2[idx] = l;
}

// ---------------- shared MMA chunk over one 64-k slab in smem ----------------
template<bool A2ON>
__device__ __forceinline__ void chunk_mma(float (&acc)[2][8][4],
                                          uint32_t abase, uint32_t bbase){
    #pragma unroll
    for (int k16 = 0; k16 < 64; k16 += 16){
        uint32_t a1f[2][4], a2f[2][4];
        #pragma unroll
        for (int mt = 0; mt < 2; mt++){
            uint32_t ad = abase + (uint32_t)((mt*16*AS + k16) * 2);
            ldsm_x4(a1f[mt], ad);
            if (A2ON) ldsm_x4(a2f[mt], ad + PANEL);
        }
        #pragma unroll
        for (int nt = 0; nt < 8; nt++){
            uint32_t bd = bbase + (uint32_t)((nt*8*AS + k16) * 2);
            uint32_t b1f[2], b2f[2];
            ldsm_x2(b1f, bd);
            ldsm_x2(b2f, bd + PANEL);
            mma16816(acc[0][nt], a1f[0], b1f);
            mma16816(acc[1][nt], a1f[1], b1f);
            if (A2ON){
                mma16816(acc[0][nt], a2f[0], b1f);
                mma16816(acc[1][nt], a2f[1], b1f);
            }
            mma16816(acc[0][nt], a1f[0], b2f);
            mma16816(acc[1][nt], a1f[1], b2f);
        }
    }
}

// ---------------- shared epilogue ----------------
__device__ __forceinline__ void gemm_epilogue(
    float (&acc)[2][8][4], int row0, int cofs,
    const float* __restrict__ bias,
    float* __restrict__ Cout, int ldc,
    bf16* __restrict__ O1, bf16* __restrict__ O2, int ldo,
    const float* __restrict__ lnw, const float* __restrict__ lnb,
    float2* red, int flags, int lane, int warpM, int warpN,
    bf16* smem_bf)
{
    const int l4 = lane >> 2, l2 = (lane & 3) << 1;

    if (flags & GF_LN){
        #pragma unroll
        for (int mt = 0; mt < 2; mt++){
            #pragma unroll
            for (int hh = 0; hh < 2; hh++){
                int rl = warpM*32 + mt*16 + hh*8 + l4;
                int rg = row0 + rl;
                float s = 0.0f, ss = 0.0f;
                #pragma unroll
                for (int nt = 0; nt < 8; nt++){
                    int cg = warpN*64 + nt*8 + l2;
                    float2 old = *(const float2*)(Cout + (size_t)rg*ldc + cg);
                    float v0 = acc[mt][nt][hh*2+0] + bias[cg]   + old.x;
                    float v1 = acc[mt][nt][hh*2+1] + bias[cg+1] + old.y;
                    acc[mt][nt][hh*2+0] = v0;
                    acc[mt][nt][hh*2+1] = v1;
                    *(float2*)(Cout + (size_t)rg*ldc + cg) = make_float2(v0, v1);
                    s += v0 + v1; ss += v0*v0 + v1*v1;
                }
                s  += __shfl_xor_sync(0xffffffffu, s,  1);
                ss += __shfl_xor_sync(0xffffffffu, ss, 1);
                s  += __shfl_xor_sync(0xffffffffu, s,  2);
                ss += __shfl_xor_sync(0xffffffffu, ss, 2);
                if ((lane & 3) == 0) red[rl*2 + warpN] = make_float2(s, ss);
            }
        }
        __syncthreads();
        #pragma unroll
        for (int mt = 0; mt < 2; mt++){
            #pragma unroll
            for (int hh = 0; hh < 2; hh++){
                int rl = warpM*32 + mt*16 + hh*8 + l4;
                int rg = row0 + rl;
                float2 r0 = red[rl*2 + 0], r1 = red[rl*2 + 1];
                float mean = (r0.x + r1.x) * (1.0f/DIM);
                float var  = (r0.y + r1.y) * (1.0f/DIM) - mean*mean;
                float rstd = rsqrtf(var + 1e-5f);
                #pragma unroll
                for (int nt = 0; nt < 8; nt++){
                    int cg = warpN*64 + nt*8 + l2;
                    float n0 = (acc[mt][nt][hh*2+0] - mean)*rstd*lnw[cg]   + lnb[cg];
                    float n1 = (acc[mt][nt][hh*2+1] - mean)*rstd*lnw[cg+1] + lnb[cg+1];
                    bf16 ha,la,hb,lb;
                    split1(n0, ha, la); split1(n1, hb, lb);
                    __nv_bfloat162 p, q;
                    p.x=ha; p.y=hb; q.x=la; q.y=lb;
                    if (flags & GF_SMEMOUT){
                        int p0 = (cg >> 6) * 2;
                        int c63 = cg & 63;
                        *(__nv_bfloat162*)(smem_bf + p0*PANELW     + rl*AS + c63) = p;
                        *(__nv_bfloat162*)(smem_bf + (p0+1)*PANELW + rl*AS + c63) = q;
                    } else {
                        *(__nv_bfloat162*)(O1 + (size_t)rg*ldo + cg) = p;
                        *(__nv_bfloat162*)(O2 + (size_t)rg*ldo + cg) = q;
                    }
                }
            }
        }
        return;
    }

    #pragma unroll
    for (int mt = 0; mt < 2; mt++){
        #pragma unroll
        for (int hh = 0; hh < 2; hh++){
            int rg = row0 + warpM*32 + mt*16 + l4 + hh*8;
            bool maskz = (flags & GF_MASK) && (g_counts[rg] == 0);
            #pragma unroll
            for (int nt = 0; nt < 8; nt++){
                int cg = cofs + warpN*64 + nt*8 + l2;
                float v0 = acc[mt][nt][hh*2+0] + bias[cg];
                float v1 = acc[mt][nt][hh*2+1] + bias[cg+1];
                if (flags & GF_GELU){ v0 = gelu_f(v0); v1 = gelu_f(v1); }
                if (flags & GF_ACCUM){
                    float2 old = *(const float2*)(Cout + (size_t)rg*ldc + cg);
                    v0 += old.x; v1 += old.y;
                }
                if (flags & GF_SPLIT){
                    bf16 ha,la,hb,lb;
                    split1(v0, ha, la); split1(v1, hb, lb);
                    __nv_bfloat162 p;
                    p.x=ha; p.y=hb; *(__nv_bfloat162*)(O1 + (size_t)rg*ldo + cg) = p;
                    p.x=la; p.y=lb; *(__nv_bfloat162*)(O2 + (size_t)rg*ldo + cg) = p;
                } else if (flags & GF_B16){
                    __nv_bfloat162 p;
                    p.x = __float2bfloat16(v0); p.y = __float2bfloat16(v1);
                    *(__nv_bfloat162*)(O1 + (size_t)rg*ldo + cg) = p;
                } else {
                    float2 ov = maskz ? make_float2(0.f, 0.f) : make_float2(v0, v1);
                    *(float2*)(Cout + (size_t)rg*ldc + cg) = ov;
                }
            }
        }
    }
}

// ---------------- standalone mma.sync GEMM (L0 qkv, final w2, proj) ----------------
template<bool ARES, bool A2ON>
__global__ __launch_bounds__(256, 2)
void k_gemm(const bf16* __restrict__ A1, const bf16* __restrict__ A2, int lda,
            const bf16* __restrict__ B1, const bf16* __restrict__ B2,
            const float* __restrict__ bias,
            float* __restrict__ Cout, int ldc,
            bf16* __restrict__ O1, bf16* __restrict__ O2, int ldo,
            const float* __restrict__ lnw, const float* __restrict__ lnb,
            int Ktot, int ny, int flags){
    extern __shared__ bf16 smem[];
    const int tid = threadIdx.x, lane = tid & 31, wid = tid >> 5;
    const int warpM = wid & 3, warpN = wid >> 2;
    const int row0 = blockIdx.x*128;
    const uint32_t sbase = s2u(smem);
    const uint32_t BBASE = ARES ? 4*PANEL : 2*PANEL;
    float2* red = (float2*)((char*)smem + (ARES ? 6*PANEL : 4*PANEL));

    const int rowA = lane & 15, kA8 = (lane >> 4) << 3;
    const int rowB = lane & 7,  kB8 = ((lane >> 3) & 1) << 3;
    const uint32_t aoff0 = (uint32_t)(((warpM*32 + rowA)*AS + kA8) * 2);
    const uint32_t boff  = sbase + BBASE + (uint32_t)(((warpN*64 + rowB)*AS + kB8) * 2);

    float acc[2][8][4];

    if (ARES){
        #pragma unroll
        for (int p = 0; p < 4; p++){
            int chunk = p >> 1;
            const bf16* src = (p & 1) ? A2 : A1;
            #pragma unroll
            for (int it = 0; it < 4; it++){
                int idx = it*256 + tid;
                int r = idx >> 3, c8 = (idx & 7) << 3;
                cp16(sbase + p*PANEL + (uint32_t)((r*AS + c8)*2),
                     src + (size_t)(row0+r)*lda + chunk*64 + c8);
            }
        }
        CPCOMMIT();

        for (int nb = 0; nb < ny; nb++){
            int cofs = nb*128;
            #pragma unroll
            for (int mt = 0; mt < 2; mt++)
                #pragma unroll
                for (int nt = 0; nt < 8; nt++)
                    #pragma unroll
                    for (int q = 0; q < 4; q++) acc[mt][nt][q] = 0.0f;

            for (int kc2 = 0; kc2 < 2; kc2++){
                #pragma unroll
                for (int it = 0; it < 4; it++){
                    int idx = it*256 + tid;
                    int r = idx >> 3, c8 = (idx & 7) << 3;
                    uint32_t so = (uint32_t)((r*AS + c8)*2);
                    cp16(sbase + BBASE + so,         B1 + (size_t)(cofs+r)*Ktot + kc2*64 + c8);
                    cp16(sbase + BBASE + PANEL + so, B2 + (size_t)(cofs+r)*Ktot + kc2*64 + c8);
                }
                CPCOMMIT();
                CPWAIT0();
                __syncthreads();
                chunk_mma<true>(acc, sbase + (uint32_t)(kc2*2*PANEL) + aoff0, boff);
                __syncthreads();
            }
            gemm_epilogue(acc, row0, cofs, bias, Cout, ldc, O1, O2, ldo,
                          lnw, lnb, red, flags, lane, warpM, warpN, smem);
            __syncthreads();
        }
    } else {
        const int cofs = blockIdx.y*128;
        #pragma unroll
        for (int mt = 0; mt < 2; mt++)
            #pragma unroll
            for (int nt = 0; nt < 8; nt++)
                #pragma unroll
                for (int q = 0; q < 4; q++) acc[mt][nt][q] = 0.0f;

        for (int kc = 0; kc < Ktot; kc += 64){
            #pragma unroll
            for (int it = 0; it < 4; it++){
                int idx = it*256 + tid;
                int r = idx >> 3, c8 = (idx & 7) << 3;
                uint32_t so = (uint32_t)((r*AS + c8)*2);
                cp16(sbase + so, A1 + (size_t)(row0+r)*lda + kc + c8);
                if (A2ON) cp16(sbase + PANEL + so, A2 + (size_t)(row0+r)*lda + kc + c8);
                cp16(sbase + 2*PANEL + so, B1 + (size_t)(cofs+r)*Ktot + kc + c8);
                cp16(sbase + 3*PANEL + so, B2 + (size_t)(cofs+r)*Ktot + kc + c8);
            }
            CPCOMMIT();
            CPWAIT0();
            __syncthreads();
            chunk_mma<A2ON>(acc, sbase + aoff0, boff);
            __syncthreads();
        }
        gemm_epilogue(acc, row0, cofs, bias, Cout, ldc, O1, O2, ldo,
                      lnw, lnb, red, flags, lane, warpM, warpN, smem);
    }
}

// ---------------- fused kernel: streaming GEMM + LN -> smem + A-resident GEMM -----
template<int KW, bool A2W, int NY2>
__global__ __launch_bounds__(256, 2)
void k_fused(const bf16* __restrict__ A1, const bf16* __restrict__ A2, int lda,
             const bf16* __restrict__ Bw1, const bf16* __restrict__ Bw2,
             const float* __restrict__ biasW,
             float* __restrict__ hres,
             const float* __restrict__ lnw, const float* __restrict__ lnb,
             const bf16* __restrict__ B21, const bf16* __restrict__ B22,
             const float* __restrict__ bias2,
             float* __restrict__ C2, int ldc2,
             bf16* __restrict__ O2b, int ldo2,
             int flags2){
    extern __shared__ bf16 smem[];
    const int tid = threadIdx.x, lane = tid & 31, wid = tid >> 5;
    const int warpM = wid & 3, warpN = wid >> 2;
    const int row0 = blockIdx.x*128;
    const uint32_t sbase = s2u(smem);
    float2* red = (float2*)((char*)smem + 6*PANEL);

    const int rowA = lane & 15, kA8 = (lane >> 4) << 3;
    const int rowB = lane & 7,  kB8 = ((lane >> 3) & 1) << 3;
    const uint32_t aoff0 = (uint32_t)(((warpM*32 + rowA)*AS + kA8) * 2);
    const uint32_t boffB = sbase + 4*PANEL + (uint32_t)(((warpN*64 + rowB)*AS + kB8) * 2);

    float acc[2][8][4];

    // ---- phase 1 ----
    #pragma unroll
    for (int mt = 0; mt < 2; mt++)
        #pragma unroll
        for (int nt = 0; nt < 8; nt++)
            #pragma unroll
            for (int q = 0; q < 4; q++) acc[mt][nt][q] = 0.0f;

    for (int kc = 0; kc < KW; kc += 64){
        #pragma unroll
        for (int it = 0; it < 4; it++){
            int idx = it*256 + tid;
            int r = idx >> 3, c8 = (idx & 7) << 3;
            uint32_t so = (uint32_t)((r*AS + c8)*2);
            cp16(sbase + so, A1 + (size_t)(row0+r)*lda + kc + c8);
            if (A2W) cp16(sbase + PANEL + so, A2 + (size_t)(row0+r)*lda + kc + c8);
            cp16(sbase + 4*PANEL + so, Bw1 + (size_t)r*KW + kc + c8);
            cp16(sbase + 5*PANEL + so, Bw2 + (size_t)r*KW + kc + c8);
        }
        CPCOMMIT();
        CPWAIT0();
        __syncthreads();
        chunk_mma<A2W>(acc, sbase + aoff0, boffB);
        __syncthreads();
    }
    gemm_epilogue(acc, row0, 0, biasW, hres, DIM, (bf16*)0, (bf16*)0, 0,
                  lnw, lnb, red, GF_ACCUM|GF_LN|GF_SMEMOUT, lane, warpM, warpN, smem);
    __syncthreads();

    // ---- phase 2 ----
    for (int nb = 0; nb < NY2; nb++){
        int cofs = nb*128;
        #pragma unroll
        for (int mt = 0; mt < 2; mt++)
            #pragma unroll
            for (int nt = 0; nt < 8; nt++)
                #pragma unroll
                for (int q = 0; q < 4; q++) acc[mt][nt][q] = 0.0f;

        for (int kc2 = 0; kc2 < 2; kc2++){
            #pragma unroll
            for (int it = 0; it < 4; it++){
                int idx = it*256 + tid;
                int r = idx >> 3, c8 = (idx & 7) << 3;
                uint32_t so = (uint32_t)((r*AS + c8)*2);
                cp16(sbase + 4*PANEL + so, B21 + (size_t)(cofs+r)*DIM + kc2*64 + c8);
                cp16(sbase + 5*PANEL + so, B22 + (size_t)(cofs+r)*DIM + kc2*64 + c8);
            }
            CPCOMMIT();
            CPWAIT0();
            __syncthreads();
            chunk_mma<true>(acc, sbase + (uint32_t)(kc2*2*PANEL) + aoff0, boffB);
            __syncthreads();
        }
        gemm_epilogue(acc, row0, cofs, bias2, C2, ldc2, O2b, (bf16*)0, ldo2,
                      (float*)0, (float*)0, red, flags2, lane, warpM, warpN, smem);
        __syncthreads();
    }
}

// ---------------- attention-fused kernel: attn -> smem A + wo+LN -> smem + w1 ----
// Each CTA owns 128 rows = 8 cells; warp w handles cell row0/16 + w.
__global__ __launch_bounds__(256, 2)
void k_afused(const bf16* __restrict__ qkvb,
              const bf16* __restrict__ Bw1, const bf16* __restrict__ Bw2,
              const float* __restrict__ biasW,
              float* __restrict__ hres,
              const float* __restrict__ lnw, const float* __restrict__ lnb,
              const bf16* __restrict__ B21, const bf16* __restrict__ B22,
              const float* __restrict__ bias2,
              bf16* __restrict__ O2b, int ldo2, int flags2){
    extern __shared__ bf16 smem[];
    const int tid = threadIdx.x, lane = tid & 31, wid = tid >> 5;
    const int warpM = wid & 3, warpN = wid >> 2;
    const int row0 = blockIdx.x*128;
    const uint32_t sbase = s2u(smem);
    float2* red = (float2*)((char*)smem + 6*PANEL);

    const int rowA = lane & 15, kA8 = (lane >> 4) << 3;
    const int rowB = lane & 7,  kB8 = ((lane >> 3) & 1) << 3;
    const uint32_t aoff0 = (uint32_t)(((warpM*32 + rowA)*AS + kA8) * 2);
    const uint32_t boffB = sbase + 4*PANEL + (uint32_t)(((warpN*64 + rowB)*AS + kB8) * 2);

    // ---- attention prologue: warp wid handles cell 8*blk + wid ----
    {
        const int qoff = ((lane >> 3) << 5) + ((lane & 7) << 2);
        const float scale = 0.17677669529663687f;
        const size_t base = (size_t)(row0 + wid*LTOK);   // first global row of cell
        const int p0 = (qoff >> 6) * 2;                  // A-panel pair for these dims
        const int c63 = qoff & 63;
        for (int r = 0; r < LTOK; r++){
            float4 q4 = ld4bf(qkvb + (base+r)*384 + qoff);
            float sc[LTOK]; float mx = -1e30f;
            #pragma unroll
            for (int j = 0; j < LTOK; j++){
                float4 k4 = ld4bf(qkvb + (base+j)*384 + 128 + qoff);
                float sd = q4.x*k4.x + q4.y*k4.y + q4.z*k4.z + q4.w*k4.w;
                sd += __shfl_xor_sync(0xffffffffu, sd, 1);
                sd += __shfl_xor_sync(0xffffffffu, sd, 2);
                sd += __shfl_xor_sync(0xffffffffu, sd, 4);
                sd *= scale;
                sc[j] = sd; mx = fmaxf(mx, sd);
            }
            float den = 0.0f;
            #pragma unroll
            for (int j = 0; j < LTOK; j++){ sc[j] = __expf(sc[j]-mx); den += sc[j]; }
            float inv = __fdividef(1.0f, den);
            float4 o = make_float4(0.f,0.f,0.f,0.f);
            #pragma unroll
            for (int j = 0; j < LTOK; j++){
                float p = sc[j]*inv;
                float4 v4 = ld4bf(qkvb + (base+j)*384 + 256 + qoff);
                o.x += p*v4.x; o.y += p*v4.y; o.z += p*v4.z; o.w += p*v4.w;
            }
            bf16 h0,l0,h1,l1,h2,l2,h3,l3;
            split1(o.x,h0,l0); split1(o.y,h1,l1); split1(o.z,h2,l2); split1(o.w,h3,l3);
            const int rl = wid*LTOK + r;
            __nv_bfloat162 p, q;
            p.x=h0; p.y=h1; q.x=l0; q.y=l1;
            *(__nv_bfloat162*)(smem + p0*PANELW     + rl*AS + c63)     = p;
            *(__nv_bfloat162*)(smem + (p0+1)*PANELW + rl*AS + c63)     = q;
            p.x=h2; p.y=h3; q.x=l2; q.y=l3;
            *(__nv_bfloat162*)(smem + p0*PANELW     + rl*AS + c63 + 2) = p;
            *(__nv_bfloat162*)(smem + (p0+1)*PANELW + rl*AS + c63 + 2) = q;
        }
    }
    __syncthreads();

    float acc[2][8][4];

    // ---- phase 1: wo GEMM, A resident (panels 0-3), B streamed ----
    #pragma unroll
    for (int mt = 0; mt < 2; mt++)
        #pragma unroll
        for (int nt = 0; nt < 8; nt++)
            #pragma unroll
            for (int q = 0; q < 4; q++) acc[mt][nt][q] = 0.0f;

    for (int kc2 = 0; kc2 < 2; kc2++){
        #pragma unroll
        for (int it = 0; it < 4; it++){
            int idx = it*256 + tid;
            int r = idx >> 3, c8 = (idx & 7) << 3;
            uint32_t so = (uint32_t)((r*AS + c8)*2);
            cp16(sbase + 4*PANEL + so, Bw1 + (size_t)r*DIM + kc2*64 + c8);
            cp16(sbase + 5*PANEL + so, Bw2 + (size_t)r*DIM + kc2*64 + c8);
        }
        CPCOMMIT();
        CPWAIT0();
        __syncthreads();
        chunk_mma<true>(acc, sbase + (uint32_t)(kc2*2*PANEL) + aoff0, boffB);
        __syncthreads();
    }
    gemm_epilogue(acc, row0, 0, biasW, hres, DIM, (bf16*)0, (bf16*)0, 0,
                  lnw, lnb, red, GF_ACCUM|GF_LN|GF_SMEMOUT, lane, warpM, warpN, smem);
    __syncthreads();

    // ---- phase 2: w1 from smem, 4 N-blocks ----
    for (int nb = 0; nb < 4; nb++){
        int cofs = nb*128;
        #pragma unroll
        for (int mt = 0; mt < 2; mt++)
            #pragma unroll
            for (int nt = 0; nt < 8; nt++)
                #pragma unroll
                for (int q = 0; q < 4; q++) acc[mt][nt][q] = 0.0f;

        for (int kc2 = 0; kc2 < 2; kc2++){
            #pragma unroll
            for (int it = 0; it < 4; it++){
                int idx = it*256 + tid;
                int r = idx >> 3, c8 = (idx & 7) << 3;
                uint32_t so = (uint32_t)((r*AS + c8)*2);
                cp16(sbase + 4*PANEL + so, B21 + (size_t)(cofs+r)*DIM + kc2*64 + c8);
                cp16(sbase + 5*PANEL + so, B22 + (size_t)(cofs+r)*DIM + kc2*64 + c8);
            }
            CPCOMMIT();
            CPWAIT0();
            __syncthreads();
            chunk_mma<true>(acc, sbase + (uint32_t)(kc2*2*PANEL) + aoff0, boffB);
            __syncthreads();
        }
        gemm_epilogue(acc, row0, cofs, bias2, (float*)0, 0, O2b, (bf16*)0, ldo2,
                      (float*)0, (float*)0, red, flags2, lane, warpM, warpN, smem);
        __syncthreads();
    }
}

// ---------------- launch ----------------
extern "C" void kernel_launch(void* const* d_in, const int* in_sizes, int n_in,
                              void* d_out, int out_size){
    const float* x    = (const float*)d_in[0];
    const int*   li   = (const int*)  d_in[1];
    const float* ob   = (const float*)d_in[2];
    const float* dw   = (const float*)d_in[3];
    const float* db   = (const float*)d_in[4];
    const float* ln1w = (const float*)d_in[5];
    const float* ln1b = (const float*)d_in[6];
    const float* wqkv = (const float*)d_in[7];
    const float* bqkv = (const float*)d_in[8];
    const float* wo   = (const float*)d_in[9];
    const float* bo   = (const float*)d_in[10];
    const float* ln2w = (const float*)d_in[11];
    const float* ln2b = (const float*)d_in[12];
    const float* w1   = (const float*)d_in[13];
    const float* b1   = (const float*)d_in[14];
    const float* w2   = (const float*)d_in[15];
    const float* b2   = (const float*)d_in[16];
    const float* pw   = (const float*)d_in[17];
    const float* pb   = (const float*)d_in[18];
    int n = in_sizes[0] / DIM;

    bf16 *a1, *a2, *h1a, *fa1, *fa2, *qkvb;
    bf16 *wqT1, *wqT2, *woT1, *woT2, *w1T1, *w1T2, *w2T1, *w2T2, *pT1, *pT2;
    float *h;
    cudaGetSymbolAddress((void**)&a1,  g_a1);  cudaGetSymbolAddress((void**)&a2,  g_a2);
    cudaGetSymbolAddress((void**)&h1a, g_h1a);
    cudaGetSymbolAddress((void**)&fa1, g_fa1); cudaGetSymbolAddress((void**)&fa2, g_fa2);
    cudaGetSymbolAddress((void**)&qkvb, g_qkvb);
    cudaGetSymbolAddress((void**)&wqT1, g_wqkvT1); cudaGetSymbolAddress((void**)&wqT2, g_wqkvT2);
    cudaGetSymbolAddress((void**)&woT1, g_woT1);   cudaGetSymbolAddress((void**)&woT2, g_woT2);
    cudaGetSymbolAddress((void**)&w1T1, g_w1T1);   cudaGetSymbolAddress((void**)&w1T2, g_w1T2);
    cudaGetSymbolAddress((void**)&w2T1, g_w2T1);   cudaGetSymbolAddress((void**)&w2T2, g_w2T2);
    cudaGetSymbolAddress((void**)&pT1, g_pT1);     cudaGetSymbolAddress((void**)&pT2, g_pT2);
    cudaGetSymbolAddress((void**)&h, g_h);

    const int SMEM_ARES = 6*PANEL + 2048;   // 112640
    const int SMEM_STRM = 4*PANEL + 2048;   // 75776
    cudaFuncSetAttribute(k_gemm<true,true>,   cudaFuncAttributeMaxDynamicSharedMemorySize, SMEM_ARES);
    cudaFuncSetAttribute(k_gemm<false,true>,  cudaFuncAttributeMaxDynamicSharedMemorySize, SMEM_STRM);
    cudaFuncSetAttribute(k_gemm<false,false>, cudaFuncAttributeMaxDynamicSharedMemorySize, SMEM_STRM);
    cudaFuncSetAttribute(k_fused<512,false,3>, cudaFuncAttributeMaxDynamicSharedMemorySize, SMEM_ARES);
    cudaFuncSetAttribute(k_afused, cudaFuncAttributeMaxDynamicSharedMemorySize, SMEM_ARES);

    // setup
    k_zero<<<(BALL+255)/256, 256>>>();
    k_scatter<<<(n+255)/256, 256>>>(li, n);
    k_bg<<<2, 256>>>(ob, dw, db);
    k_select<<<(BALL+255)/256, 256>>>();
    k_assemble<<<(NROW*DIM+255)/256, 256>>>(x);

    // weight transpose+split
    k_tsplit<<<dim3(64, DEPTH), 256>>>(wqkv, wqT1, wqT2, DIM, 3*DIM);
    k_tsplit<<<dim3(32, DEPTH), 256>>>(wo,   woT1, woT2, DIM, DIM);
    k_tsplit<<<dim3(64, DEPTH), 256>>>(w1,   w1T1, w1T2, DIM, HID);
    k_tsplit<<<dim3(64, DEPTH), 256>>>(w2,   w2T1, w2T2, HID, DIM);
    k_tsplit<<<dim3(256, 1),    256>>>(pw,   pT1,  pT2,  HID, CLV);

    // layer-0 LN + qkv (bf16 QKV out)
    k_ln_split<<<NROW/8, 256>>>(ln1w, ln1b);
    const int MB = NROW/128;   // 720
    k_gemm<true,true><<<MB, 256, SMEM_ARES>>>(a1, a2, DIM,
        wqT1, wqT2, bqkv, (float*)0, 0, qkvb, (bf16*)0, 3*DIM,
        (float*)0, (float*)0, DIM, 3, GF_B16);

    for (int L = 0; L < DEPTH; L++){
        // fused: attention + wo + residual + ln2 -> smem -> w1 (gelu, bf16 out)
        k_afused<<<MB, 256, SMEM_ARES>>>(qkvb,
            woT1 + (size_t)L*DIM*DIM, woT2 + (size_t)L*DIM*DIM,
            bo + L*DIM, h, ln2w + L*DIM, ln2b + L*DIM,
            w1T1 + (size_t)L*HID*DIM, w1T2 + (size_t)L*HID*DIM,
            b1 + L*HID, h1a, HID, GF_GELU|GF_B16);
        if (L < DEPTH-1){
            // fused: w2 + residual + ln1(L+1) -> smem -> qkv(L+1) (bf16 out)
            k_fused<512,false,3><<<MB, 256, SMEM_ARES>>>(h1a, (bf16*)0, HID,
                w2T1 + (size_t)L*DIM*HID, w2T2 + (size_t)L*DIM*HID,
                b2 + L*DIM, h, ln1w + (L+1)*DIM, ln1b + (L+1)*DIM,
                wqT1 + (size_t)(L+1)*3*DIM*DIM, wqT2 + (size_t)(L+1)*3*DIM*DIM,
                bqkv + (L+1)*3*DIM, (float*)0, 0, qkvb, 3*DIM, GF_B16);
        } else {
            k_gemm<false,false><<<dim3(MB,1), 256, SMEM_STRM>>>(h1a, (bf16*)0, HID,
                w2T1 + (size_t)L*DIM*HID, w2T2 + (size_t)L*DIM*HID,
                b2 + L*DIM, h, DIM, (bf16*)0, (bf16*)0, 0,
                (float*)0, (float*)0, HID, 1, GF_ACCUM);
        }
    }

    k_split_feat<<<(BALL*HID+255)/256, 256>>>();
    k_gemm<false,true><<<dim3(BALL/128, CLV/128), 256, SMEM_STRM>>>(fa1, fa2, HID,
        pT1, pT2, pb, (float*)d_out, CLV, (bf16*)0, (bf16*)0, 0,
        (float*)0, (float*)0, HID, 1, GF_MASK);
}